// round 1
// baseline (speedup 1.0000x reference)
#include <cuda_runtime.h>
#include <cuda_bf16.h>
#include <math.h>

// Problem constants
#define N_NODES 1024
#define N_EDGES 32768
#define DIM     1024
#define HEADS   8
#define DH      128
#define KPROJ   256

// ---------------------------------------------------------------------------
// Scratch (device globals -- no allocation allowed)
// ---------------------------------------------------------------------------
__device__ float g_xq[N_NODES * DIM];      // node @ w_query + b
__device__ float g_q[N_NODES * DIM];       // xq @ w_to_q
__device__ float g_kv[N_NODES * DH];       // xq @ w_to_k
__device__ float g_kproj[KPROJ * DH];      // proj_k^T @ kv
__device__ float g_attnout[N_NODES * DIM]; // attention output [n, h*DH+d]
__device__ float g_xattn[N_NODES * DIM];   // attnout @ w_out + b

// ---------------------------------------------------------------------------
// SGEMM: C[M,N] = A[M,K] @ B[K,N] (+ bias[N] broadcast per row, optional)
// BM=BN=128, BK=8, 256 threads, 8x8 per thread, double-buffered smem.
// Requires M%128==0, N%128==0, K%8==0 (true for all call sites).
// ---------------------------------------------------------------------------
#define BM 128
#define BN 128
#define BK 8

__global__ __launch_bounds__(256) void sgemm_kernel(
    const float* __restrict__ A, const float* __restrict__ B,
    const float* __restrict__ bias, float* __restrict__ C,
    int M, int N, int K)
{
    __shared__ float As[2][BK][BM];
    __shared__ float Bs[2][BK][BN];

    const int tid = threadIdx.x;
    const int bm = blockIdx.y * BM;
    const int bn = blockIdx.x * BN;
    const int tx = tid & 15;   // 0..15 -> columns
    const int ty = tid >> 4;   // 0..15 -> rows

    // A tile load mapping: 128 rows x 8 cols, one float4 per thread
    const int a_r = tid >> 1;          // 0..127
    const int a_c = (tid & 1) << 2;    // 0 or 4
    // B tile load mapping: 8 rows x 128 cols, one float4 per thread
    const int b_r = tid >> 5;          // 0..7
    const int b_c = (tid & 31) << 2;   // 0..124

    const float* Ag = A + (size_t)(bm + a_r) * K + a_c;
    const float* Bg = B + (size_t)b_r * N + bn + b_c;

    float acc[8][8];
#pragma unroll
    for (int i = 0; i < 8; i++)
#pragma unroll
        for (int j = 0; j < 8; j++) acc[i][j] = 0.f;

    // prologue: load tile 0
    {
        float4 av = *(const float4*)Ag;
        float4 bv = *(const float4*)Bg;
        As[0][a_c + 0][a_r] = av.x;
        As[0][a_c + 1][a_r] = av.y;
        As[0][a_c + 2][a_r] = av.z;
        As[0][a_c + 3][a_r] = av.w;
        *(float4*)&Bs[0][b_r][b_c] = bv;
    }
    __syncthreads();

    const int ktiles = K / BK;
    for (int kt = 0; kt < ktiles; kt++) {
        const int cur = kt & 1;
        float4 av, bv;
        const bool more = (kt + 1 < ktiles);
        if (more) {
            av = *(const float4*)(Ag + (kt + 1) * BK);
            bv = *(const float4*)(Bg + (size_t)(kt + 1) * BK * N);
        }
#pragma unroll
        for (int k = 0; k < BK; k++) {
            float af[8], bf[8];
            *(float4*)&af[0] = *(const float4*)&As[cur][k][ty * 4];
            *(float4*)&af[4] = *(const float4*)&As[cur][k][64 + ty * 4];
            *(float4*)&bf[0] = *(const float4*)&Bs[cur][k][tx * 4];
            *(float4*)&bf[4] = *(const float4*)&Bs[cur][k][64 + tx * 4];
#pragma unroll
            for (int i = 0; i < 8; i++)
#pragma unroll
                for (int j = 0; j < 8; j++)
                    acc[i][j] += af[i] * bf[j];
        }
        if (more) {
            const int nxt = cur ^ 1;
            As[nxt][a_c + 0][a_r] = av.x;
            As[nxt][a_c + 1][a_r] = av.y;
            As[nxt][a_c + 2][a_r] = av.z;
            As[nxt][a_c + 3][a_r] = av.w;
            *(float4*)&Bs[nxt][b_r][b_c] = bv;
        }
        __syncthreads();
    }

    // epilogue
    float bcol[8];
    if (bias) {
        *(float4*)&bcol[0] = *(const float4*)&bias[bn + tx * 4];
        *(float4*)&bcol[4] = *(const float4*)&bias[bn + 64 + tx * 4];
    } else {
#pragma unroll
        for (int j = 0; j < 8; j++) bcol[j] = 0.f;
    }
#pragma unroll
    for (int i = 0; i < 8; i++) {
        const int r = bm + ((i < 4) ? (ty * 4 + i) : (64 + ty * 4 + (i - 4)));
        float4 v0, v1;
        v0.x = acc[i][0] + bcol[0];
        v0.y = acc[i][1] + bcol[1];
        v0.z = acc[i][2] + bcol[2];
        v0.w = acc[i][3] + bcol[3];
        v1.x = acc[i][4] + bcol[4];
        v1.y = acc[i][5] + bcol[5];
        v1.z = acc[i][6] + bcol[6];
        v1.w = acc[i][7] + bcol[7];
        *(float4*)&C[(size_t)r * N + bn + tx * 4] = v0;
        *(float4*)&C[(size_t)r * N + bn + 64 + tx * 4] = v1;
    }
}

// ---------------------------------------------------------------------------
// kproj[k,d] = sum_n proj_k[n,k] * kv[n,d]    (k<256, d<128, n<1024)
// one block per k, 128 threads (d). proj_k read is uniform per block.
// ---------------------------------------------------------------------------
__global__ __launch_bounds__(128) void kproj_kernel(
    const float* __restrict__ kv, const float* __restrict__ pk,
    float* __restrict__ kp)
{
    const int k = blockIdx.x;
    const int d = threadIdx.x;
    float s0 = 0.f, s1 = 0.f, s2 = 0.f, s3 = 0.f;
#pragma unroll 4
    for (int n = 0; n < N_NODES; n += 4) {
        s0 += pk[(size_t)(n + 0) * KPROJ + k] * kv[(size_t)(n + 0) * DH + d];
        s1 += pk[(size_t)(n + 1) * KPROJ + k] * kv[(size_t)(n + 1) * DH + d];
        s2 += pk[(size_t)(n + 2) * KPROJ + k] * kv[(size_t)(n + 2) * DH + d];
        s3 += pk[(size_t)(n + 3) * KPROJ + k] * kv[(size_t)(n + 3) * DH + d];
    }
    kp[(size_t)k * DH + d] = (s0 + s1) + (s2 + s3);
}

// ---------------------------------------------------------------------------
// Fused attention: per node n (one block, 8 warps = 8 heads):
//   dots[h,k] = (q[n,h,:] . kproj[k,:]) / sqrt(DH)
//   attn = softmax_k(dots)
//   out[n, h*DH+d] = sum_k attn[h,k] * kproj[k,d]
// kproj (128 KB) stays hot in L1/L2.
// ---------------------------------------------------------------------------
__global__ __launch_bounds__(256) void attn_kernel(
    const float* __restrict__ q, const float* __restrict__ kproj,
    float* __restrict__ out)
{
    __shared__ float q_s[DIM];
    __shared__ float prob[HEADS][KPROJ];

    const int n = blockIdx.x;
    for (int i = threadIdx.x; i < DIM; i += 256)
        q_s[i] = q[(size_t)n * DIM + i];
    __syncthreads();

    const int w = threadIdx.x >> 5;  // head
    const int l = threadIdx.x & 31;  // lane
    const float4* qh4 = (const float4*)(q_s + w * DH);

    // each lane computes 8 dots: k = j*32 + l
    float d8[8];
#pragma unroll
    for (int j = 0; j < 8; j++) {
        const int k = j * 32 + l;
        const float4* kr4 = (const float4*)(kproj + (size_t)k * DH);
        float s = 0.f;
#pragma unroll
        for (int d4 = 0; d4 < DH / 4; d4++) {
            float4 qq = qh4[d4];
            float4 kk = kr4[d4];
            s += qq.x * kk.x + qq.y * kk.y + qq.z * kk.z + qq.w * kk.w;
        }
        d8[j] = s * 0.088388347648318447f;  // DH^-0.5
    }

    // softmax over 256 values distributed across the warp
    float mx = d8[0];
#pragma unroll
    for (int j = 1; j < 8; j++) mx = fmaxf(mx, d8[j]);
#pragma unroll
    for (int o = 16; o; o >>= 1) mx = fmaxf(mx, __shfl_xor_sync(0xFFFFFFFFu, mx, o));
    float sum = 0.f;
#pragma unroll
    for (int j = 0; j < 8; j++) { d8[j] = expf(d8[j] - mx); sum += d8[j]; }
#pragma unroll
    for (int o = 16; o; o >>= 1) sum += __shfl_xor_sync(0xFFFFFFFFu, sum, o);
    const float inv = 1.f / sum;
#pragma unroll
    for (int j = 0; j < 8; j++) prob[w][j * 32 + l] = d8[j] * inv;
    __syncwarp();

    // out: each lane produces 4 d-values: d = j*32 + l
    float o0 = 0.f, o1 = 0.f, o2 = 0.f, o3 = 0.f;
    for (int k = 0; k < KPROJ; k++) {
        const float p = prob[w][k];
        const float* kr = kproj + (size_t)k * DH + l;
        o0 += p * kr[0];
        o1 += p * kr[32];
        o2 += p * kr[64];
        o3 += p * kr[96];
    }
    float* op = out + (size_t)n * DIM + w * DH + l;
    op[0]  = o0;
    op[32] = o1;
    op[64] = o2;
    op[96] = o3;
}

// ---------------------------------------------------------------------------
// LayerNorm(row of 1024) + residual. Safe in-place (src may alias dst).
// dst[row,c] = (src[row,c]-mu)*rsqrt(var+eps)*gamma[c] + beta[c] + resid[row,c]
// ---------------------------------------------------------------------------
__global__ __launch_bounds__(256) void ln_res_kernel(
    const float* __restrict__ src, const float* __restrict__ resid,
    const float* __restrict__ gamma, const float* __restrict__ beta,
    float* __restrict__ dst)
{
    const int row = blockIdx.x;
    const int t = threadIdx.x;
    const float4 v = *(const float4*)&src[(size_t)row * DIM + t * 4];

    float sum = v.x + v.y + v.z + v.w;
    float sq = v.x * v.x + v.y * v.y + v.z * v.z + v.w * v.w;
#pragma unroll
    for (int o = 16; o; o >>= 1) {
        sum += __shfl_xor_sync(0xFFFFFFFFu, sum, o);
        sq  += __shfl_xor_sync(0xFFFFFFFFu, sq, o);
    }
    __shared__ float ssum[8], ssq[8];
    const int w = t >> 5, l = t & 31;
    if (l == 0) { ssum[w] = sum; ssq[w] = sq; }
    __syncthreads();
    sum = 0.f; sq = 0.f;
#pragma unroll
    for (int i = 0; i < 8; i++) { sum += ssum[i]; sq += ssq[i]; }

    const float mu = sum * (1.f / DIM);
    const float var = sq * (1.f / DIM) - mu * mu;
    const float rstd = rsqrtf(var + 1e-5f);

    const float4 g = *(const float4*)&gamma[t * 4];
    const float4 b = *(const float4*)&beta[t * 4];
    const float4 rr = *(const float4*)&resid[(size_t)row * DIM + t * 4];
    float4 o;
    o.x = (v.x - mu) * rstd * g.x + b.x + rr.x;
    o.y = (v.y - mu) * rstd * g.y + b.y + rr.y;
    o.z = (v.z - mu) * rstd * g.z + b.z + rr.z;
    o.w = (v.w - mu) * rstd * g.w + b.w + rr.w;
    *(float4*)&dst[(size_t)row * DIM + t * 4] = o;
}

// ---------------------------------------------------------------------------
// kernel_launch
// ---------------------------------------------------------------------------
extern "C" void kernel_launch(void* const* d_in, const int* in_sizes, int n_in,
                              void* d_out, int out_size)
{
    const float* node       = (const float*)d_in[0];
    const float* edge       = (const float*)d_in[1];
    const float* w_query    = (const float*)d_in[2];
    const float* b_query    = (const float*)d_in[3];
    const float* w_edge     = (const float*)d_in[4];
    const float* b_edge     = (const float*)d_in[5];
    const float* w_to_q     = (const float*)d_in[6];
    const float* w_to_k     = (const float*)d_in[7];
    const float* proj_k     = (const float*)d_in[8];
    const float* w_out      = (const float*)d_in[9];
    const float* b_out      = (const float*)d_in[10];
    const float* gamma_node = (const float*)d_in[11];
    const float* beta_node  = (const float*)d_in[12];
    const float* gamma_edge = (const float*)d_in[13];
    const float* beta_edge  = (const float*)d_in[14];

    float* x_out = (float*)d_out;                           // [1024,1024]
    float* y_out = (float*)d_out + (size_t)N_NODES * DIM;   // [32768,1024]

    float *p_xq, *p_q, *p_kv, *p_kproj, *p_attnout, *p_xattn;
    cudaGetSymbolAddress((void**)&p_xq, g_xq);
    cudaGetSymbolAddress((void**)&p_q, g_q);
    cudaGetSymbolAddress((void**)&p_kv, g_kv);
    cudaGetSymbolAddress((void**)&p_kproj, g_kproj);
    cudaGetSymbolAddress((void**)&p_attnout, g_attnout);
    cudaGetSymbolAddress((void**)&p_xattn, g_xattn);

    // ---- edge path (dominant GEMM): m -> y region of d_out, then LN in place
    {
        dim3 grid(DIM / BN, N_EDGES / BM);
        sgemm_kernel<<<grid, 256>>>(edge, w_edge, b_edge, y_out,
                                    N_EDGES, DIM, DIM);
    }

    // ---- node path
    {
        dim3 grid(DIM / BN, N_NODES / BM);
        sgemm_kernel<<<grid, 256>>>(node, w_query, b_query, p_xq,
                                    N_NODES, DIM, DIM);
        sgemm_kernel<<<grid, 256>>>(p_xq, w_to_q, nullptr, p_q,
                                    N_NODES, DIM, DIM);
    }
    {
        dim3 grid(DH / BN, N_NODES / BM);  // N=128 -> grid.x=1
        sgemm_kernel<<<grid, 256>>>(p_xq, w_to_k, nullptr, p_kv,
                                    N_NODES, DH, DIM);
    }
    kproj_kernel<<<KPROJ, 128>>>(p_kv, proj_k, p_kproj);
    attn_kernel<<<N_NODES, 256>>>(p_q, p_kproj, p_attnout);
    {
        dim3 grid(DIM / BN, N_NODES / BM);
        sgemm_kernel<<<grid, 256>>>(p_attnout, w_out, b_out, p_xattn,
                                    N_NODES, DIM, DIM);
    }
    ln_res_kernel<<<N_NODES, 256>>>(p_xattn, node, gamma_node, beta_node, x_out);

    // ---- edge LN (in place over y region)
    ln_res_kernel<<<N_EDGES, 256>>>(y_out, edge, gamma_edge, beta_edge, y_out);
}

// round 3
// speedup vs baseline: 2.5880x; 2.5880x over previous
#include <cuda_runtime.h>
#include <cuda_bf16.h>
#include <math.h>
#include <stdint.h>

#define N_NODES 1024
#define N_EDGES 32768
#define DIM     1024
#define HEADS   8
#define DH      128
#define KPROJ   256
#define QKV_N   1152   // w_to_q (1024) ++ w_to_k (128), fused GEMM

// ---------------------------------------------------------------------------
// Scratch (device globals -- no allocation allowed)
// ---------------------------------------------------------------------------
__device__ __nv_bfloat16 g_eh[N_EDGES * DIM],  g_el[N_EDGES * DIM];    // edge hi/lo
__device__ __nv_bfloat16 g_weT_h[DIM * DIM],   g_weT_l[DIM * DIM];     // w_edge^T
__device__ __nv_bfloat16 g_nh[N_NODES * DIM],  g_nl[N_NODES * DIM];    // node hi/lo
__device__ __nv_bfloat16 g_wqT_h[DIM * DIM],   g_wqT_l[DIM * DIM];     // w_query^T
__device__ __nv_bfloat16 g_wqkT_h[QKV_N * DIM], g_wqkT_l[QKV_N * DIM]; // [w_to_q|w_to_k]^T
__device__ __nv_bfloat16 g_woT_h[DIM * DIM],   g_woT_l[DIM * DIM];     // w_out^T
__device__ __nv_bfloat16 g_xqh[N_NODES * DIM], g_xql[N_NODES * DIM];   // xq hi/lo
__device__ float         g_qkv[N_NODES * QKV_N];                       // [q | kv] fp32
__device__ float         g_kproj[KPROJ * DH];
__device__ __nv_bfloat16 g_ah[N_NODES * DIM],  g_al[N_NODES * DIM];    // attn out hi/lo
__device__ float         g_xattn[N_NODES * DIM];

// ---------------------------------------------------------------------------
// Generic-ISA PTX helpers (NO arch-specific 'a' instructions)
// ---------------------------------------------------------------------------
__device__ __forceinline__ uint32_t smem_u32(const void* p) {
    uint32_t a;
    asm("{ .reg .u64 t; cvta.to.shared.u64 t, %1; cvt.u32.u64 %0, t; }"
        : "=r"(a) : "l"(p));
    return a;
}

#define CP_ASYNC16(dst, src) \
    asm volatile("cp.async.cg.shared.global [%0], [%1], 16;" :: "r"(dst), "l"(src))
#define CP_COMMIT() asm volatile("cp.async.commit_group;" ::: "memory")
#define CP_WAIT1()  asm volatile("cp.async.wait_group 1;" ::: "memory")

#define LDSM4(r, addr) \
    asm volatile("ldmatrix.sync.aligned.m8n8.x4.shared.b16 {%0,%1,%2,%3}, [%4];" \
        : "=r"((r)[0]), "=r"((r)[1]), "=r"((r)[2]), "=r"((r)[3]) : "r"(addr))
#define LDSM2(r, addr) \
    asm volatile("ldmatrix.sync.aligned.m8n8.x2.shared.b16 {%0,%1}, [%2];" \
        : "=r"((r)[0]), "=r"((r)[1]) : "r"(addr))

__device__ __forceinline__ void mma16816(float* c, const uint32_t* a, const uint32_t* b) {
    asm volatile(
        "mma.sync.aligned.m16n8k16.row.col.f32.bf16.bf16.f32 "
        "{%0,%1,%2,%3}, {%4,%5,%6,%7}, {%8,%9}, {%0,%1,%2,%3};"
        : "+f"(c[0]), "+f"(c[1]), "+f"(c[2]), "+f"(c[3])
        : "r"(a[0]), "r"(a[1]), "r"(a[2]), "r"(a[3]), "r"(b[0]), "r"(b[1]));
}

// ---------------------------------------------------------------------------
// GEMM: C[M, :] = A[M,1024] @ B[1024, N] with 2-term bf16 split:
//   C ~= Ah*Bh + Ah*Bl + Al*Bh           (error ~2^-18)
// A as (Ah, Al) [M,1024] row-major bf16; B transposed (BhT, BlT) [N,1024].
// BM=BN=128, BK=32, 256 threads (8 warps, 2x4; warp tile 64x32).
// 3-stage cp.async pipeline. Smem rows padded to 80B -> conflict-free ldmatrix.
// Epilogue adds bias; writes fp32 (Cf) and/or bf16 hi/lo split (Ch/Cl).
// ---------------------------------------------------------------------------
#define GK 1024
#define NT_K 32                    // 1024 / BK
#define ROWB 80                    // padded smem row stride (bytes) for 32 bf16
#define TILE_BYTES (128 * ROWB)    // 10240
#define STAGE_BYTES (4 * TILE_BYTES)
#define SM_HDR 512
#define SM_TOTAL (SM_HDR + 3 * STAGE_BYTES)   // 123392

__global__ void __launch_bounds__(256, 1) gemm_bf16s(
    const __nv_bfloat16* __restrict__ Ah, const __nv_bfloat16* __restrict__ Al,
    const __nv_bfloat16* __restrict__ BhT, const __nv_bfloat16* __restrict__ BlT,
    const float* __restrict__ bias,
    float* __restrict__ Cf, __nv_bfloat16* __restrict__ Ch, __nv_bfloat16* __restrict__ Cl,
    int Nt)
{
    extern __shared__ char smem[];
    const uint32_t sb = smem_u32(smem);
    const int tid = threadIdx.x;
    const int wid = tid >> 5;
    const int lane = tid & 31;
    const int bm = blockIdx.y * 128;
    const int bn = blockIdx.x * 128;

    if (tid < 128) ((float*)smem)[tid] = bias ? bias[bn + tid] : 0.f;

    const __nv_bfloat16* srcs[4] = {
        Ah + (size_t)bm * GK, Al + (size_t)bm * GK,
        BhT + (size_t)bn * GK, BlT + (size_t)bn * GK };

    auto load_stage = [&](int kt, int s) {
        const uint32_t base = sb + SM_HDR + s * STAGE_BYTES;
#pragma unroll
        for (int t = 0; t < 4; t++) {
#pragma unroll
            for (int i = 0; i < 2; i++) {
                const int idx = i * 256 + tid;      // 0..511
                const int row = idx >> 2, seg = idx & 3;
                const void* g = srcs[t] + (size_t)row * GK + kt * 32 + seg * 8;
                CP_ASYNC16(base + t * TILE_BYTES + row * ROWB + seg * 16, g);
            }
        }
    };

    // prologue: stages 0, 1
    load_stage(0, 0); CP_COMMIT();
    load_stage(1, 1); CP_COMMIT();

    // warp tile origin
    const int wm = (wid >> 2) * 64;       // 0 or 64
    const int wn = (wid & 3) * 32;        // 0,32,64,96
    // ldmatrix per-lane offsets (bytes)
    const uint32_t aoff = (uint32_t)(lane & 15) * ROWB + (uint32_t)(lane >> 4) * 16;
    const int l15 = lane & 15;
    const uint32_t boff = (uint32_t)(l15 & 7) * ROWB + (uint32_t)(l15 >> 3) * 16;

    float acc[4][4][4];
#pragma unroll
    for (int mt = 0; mt < 4; mt++)
#pragma unroll
        for (int nt = 0; nt < 4; nt++)
#pragma unroll
            for (int j = 0; j < 4; j++) acc[mt][nt][j] = 0.f;

    for (int kt = 0; kt < NT_K; kt++) {
        CP_WAIT1();          // tile kt resident
        __syncthreads();     // visible to all; also: everyone done reading stage (kt-1)%3

        if (kt + 2 < NT_K) { load_stage(kt + 2, (kt + 2) % 3); CP_COMMIT(); }

        const uint32_t st = sb + SM_HDR + (kt % 3) * STAGE_BYTES;
        const uint32_t tAh = st;
        const uint32_t tAl = st + TILE_BYTES;
        const uint32_t tBh = st + 2 * TILE_BYTES;
        const uint32_t tBl = st + 3 * TILE_BYTES;

#pragma unroll
        for (int kh = 0; kh < 2; kh++) {
            const uint32_t kb = kh * 32;
            uint32_t aF[4][4], bH[4][2], bL[4][2];
#pragma unroll
            for (int nt = 0; nt < 4; nt++) {
                const uint32_t bo = (uint32_t)(wn + nt * 8) * ROWB + kb + boff;
                LDSM2(bH[nt], tBh + bo);
                LDSM2(bL[nt], tBl + bo);
            }
#pragma unroll
            for (int mt = 0; mt < 4; mt++)
                LDSM4(aF[mt], tAh + (uint32_t)(wm + mt * 16) * ROWB + kb + aoff);
#pragma unroll
            for (int mt = 0; mt < 4; mt++)
#pragma unroll
                for (int nt = 0; nt < 4; nt++) {
                    mma16816(acc[mt][nt], aF[mt], bH[nt]);
                    mma16816(acc[mt][nt], aF[mt], bL[nt]);
                }
#pragma unroll
            for (int mt = 0; mt < 4; mt++)
                LDSM4(aF[mt], tAl + (uint32_t)(wm + mt * 16) * ROWB + kb + aoff);
#pragma unroll
            for (int mt = 0; mt < 4; mt++)
#pragma unroll
                for (int nt = 0; nt < 4; nt++)
                    mma16816(acc[mt][nt], aF[mt], bH[nt]);
        }
    }

    // epilogue
    const float* bs = (const float*)smem;
#pragma unroll
    for (int mt = 0; mt < 4; mt++) {
#pragma unroll
        for (int nt = 0; nt < 4; nt++) {
            const int c = wn + nt * 8 + (lane & 3) * 2;
            const size_t r0 = (size_t)bm + wm + mt * 16 + (lane >> 2);
            const float v0 = acc[mt][nt][0] + bs[c];
            const float v1 = acc[mt][nt][1] + bs[c + 1];
            const float v2 = acc[mt][nt][2] + bs[c];
            const float v3 = acc[mt][nt][3] + bs[c + 1];
            if (Cf) {
                *(float2*)&Cf[r0 * Nt + bn + c]       = make_float2(v0, v1);
                *(float2*)&Cf[(r0 + 8) * Nt + bn + c] = make_float2(v2, v3);
            }
            if (Ch) {
                __nv_bfloat16 h0 = __float2bfloat16(v0), h1 = __float2bfloat16(v1);
                __nv_bfloat16 h2 = __float2bfloat16(v2), h3 = __float2bfloat16(v3);
                *(__nv_bfloat162*)&Ch[r0 * Nt + bn + c] = __halves2bfloat162(h0, h1);
                *(__nv_bfloat162*)&Ch[(r0 + 8) * Nt + bn + c] = __halves2bfloat162(h2, h3);
                *(__nv_bfloat162*)&Cl[r0 * Nt + bn + c] = __halves2bfloat162(
                    __float2bfloat16(v0 - __bfloat162float(h0)),
                    __float2bfloat16(v1 - __bfloat162float(h1)));
                *(__nv_bfloat162*)&Cl[(r0 + 8) * Nt + bn + c] = __halves2bfloat162(
                    __float2bfloat16(v2 - __bfloat162float(h2)),
                    __float2bfloat16(v3 - __bfloat162float(h3)));
            }
        }
    }
}

// ---------------------------------------------------------------------------
// fp32 -> bf16 hi/lo split (elementwise)
// ---------------------------------------------------------------------------
__global__ void __launch_bounds__(256) split_kernel(
    const float4* __restrict__ in, __nv_bfloat162* __restrict__ oh,
    __nv_bfloat162* __restrict__ ol, int n4)
{
    int i = blockIdx.x * 256 + threadIdx.x;
    if (i >= n4) return;
    float4 v = in[i];
    __nv_bfloat16 h0 = __float2bfloat16(v.x), h1 = __float2bfloat16(v.y);
    __nv_bfloat16 h2 = __float2bfloat16(v.z), h3 = __float2bfloat16(v.w);
    oh[2 * i + 0] = __halves2bfloat162(h0, h1);
    oh[2 * i + 1] = __halves2bfloat162(h2, h3);
    ol[2 * i + 0] = __halves2bfloat162(
        __float2bfloat16(v.x - __bfloat162float(h0)),
        __float2bfloat16(v.y - __bfloat162float(h1)));
    ol[2 * i + 1] = __halves2bfloat162(
        __float2bfloat16(v.z - __bfloat162float(h2)),
        __float2bfloat16(v.w - __bfloat162float(h3)));
}

// ---------------------------------------------------------------------------
// w[K,N] fp32 -> out[N,1024] bf16 hi/lo (transpose + split); K == 1024.
// ---------------------------------------------------------------------------
__global__ void __launch_bounds__(256) tsplit_kernel(
    const float* __restrict__ w, __nv_bfloat16* __restrict__ oh,
    __nv_bfloat16* __restrict__ ol, int N)
{
    __shared__ float t[32][33];
    const int n0 = blockIdx.x * 32, k0 = blockIdx.y * 32;
    const int tx = threadIdx.x, ty = threadIdx.y;   // block (32, 8)
#pragma unroll
    for (int i = 0; i < 4; i++)
        t[ty + i * 8][tx] = w[(size_t)(k0 + ty + i * 8) * N + n0 + tx];
    __syncthreads();
#pragma unroll
    for (int i = 0; i < 4; i++) {
        const int n = n0 + ty + i * 8, k = k0 + tx;
        const float v = t[tx][ty + i * 8];
        __nv_bfloat16 h = __float2bfloat16(v);
        oh[(size_t)n * 1024 + k] = h;
        ol[(size_t)n * 1024 + k] = __float2bfloat16(v - __bfloat162float(h));
    }
}

// ---------------------------------------------------------------------------
// kproj[k,d] = sum_n proj_k[n,k] * kv[n,d]  (kv row stride kvs)
// ---------------------------------------------------------------------------
__global__ void __launch_bounds__(128) kproj_kernel(
    const float* __restrict__ kv, int kvs, const float* __restrict__ pk,
    float* __restrict__ kp)
{
    const int k = blockIdx.x;
    const int d = threadIdx.x;
    float s0 = 0.f, s1 = 0.f, s2 = 0.f, s3 = 0.f;
#pragma unroll 4
    for (int n = 0; n < N_NODES; n += 4) {
        s0 += pk[(size_t)(n + 0) * KPROJ + k] * kv[(size_t)(n + 0) * kvs + d];
        s1 += pk[(size_t)(n + 1) * KPROJ + k] * kv[(size_t)(n + 1) * kvs + d];
        s2 += pk[(size_t)(n + 2) * KPROJ + k] * kv[(size_t)(n + 2) * kvs + d];
        s3 += pk[(size_t)(n + 3) * KPROJ + k] * kv[(size_t)(n + 3) * kvs + d];
    }
    kp[(size_t)k * DH + d] = (s0 + s1) + (s2 + s3);
}

// ---------------------------------------------------------------------------
// Fused attention (per node, 8 warps = 8 heads) -> bf16 hi/lo output
// ---------------------------------------------------------------------------
__global__ void __launch_bounds__(256) attn_kernel(
    const float* __restrict__ q, int qs, const float* __restrict__ kproj,
    __nv_bfloat16* __restrict__ oh, __nv_bfloat16* __restrict__ ol)
{
    __shared__ float q_s[DIM];
    __shared__ float prob[HEADS][KPROJ];

    const int n = blockIdx.x;
    for (int i = threadIdx.x; i < DIM; i += 256)
        q_s[i] = q[(size_t)n * qs + i];
    __syncthreads();

    const int w = threadIdx.x >> 5;
    const int l = threadIdx.x & 31;
    const float4* qh4 = (const float4*)(q_s + w * DH);

    float d8[8];
#pragma unroll
    for (int j = 0; j < 8; j++) {
        const int k = j * 32 + l;
        const float4* kr4 = (const float4*)(kproj + (size_t)k * DH);
        float s = 0.f;
#pragma unroll
        for (int d4 = 0; d4 < DH / 4; d4++) {
            float4 qq = qh4[d4], kk = kr4[d4];
            s += qq.x * kk.x + qq.y * kk.y + qq.z * kk.z + qq.w * kk.w;
        }
        d8[j] = s * 0.088388347648318447f;
    }
    float mx = d8[0];
#pragma unroll
    for (int j = 1; j < 8; j++) mx = fmaxf(mx, d8[j]);
#pragma unroll
    for (int o = 16; o; o >>= 1) mx = fmaxf(mx, __shfl_xor_sync(0xFFFFFFFFu, mx, o));
    float sum = 0.f;
#pragma unroll
    for (int j = 0; j < 8; j++) { d8[j] = expf(d8[j] - mx); sum += d8[j]; }
#pragma unroll
    for (int o = 16; o; o >>= 1) sum += __shfl_xor_sync(0xFFFFFFFFu, sum, o);
    const float inv = 1.f / sum;
#pragma unroll
    for (int j = 0; j < 8; j++) prob[w][j * 32 + l] = d8[j] * inv;
    __syncwarp();

    float o0 = 0.f, o1 = 0.f, o2 = 0.f, o3 = 0.f;
    for (int k = 0; k < KPROJ; k++) {
        const float p = prob[w][k];
        const float* kr = kproj + (size_t)k * DH + l;
        o0 += p * kr[0];  o1 += p * kr[32];
        o2 += p * kr[64]; o3 += p * kr[96];
    }
    const size_t ob = (size_t)n * DIM + w * DH + l;
    float ov[4] = {o0, o1, o2, o3};
#pragma unroll
    for (int j = 0; j < 4; j++) {
        __nv_bfloat16 h = __float2bfloat16(ov[j]);
        oh[ob + 32 * j] = h;
        ol[ob + 32 * j] = __float2bfloat16(ov[j] - __bfloat162float(h));
    }
}

// ---------------------------------------------------------------------------
// LayerNorm + residual (in-place safe)
// ---------------------------------------------------------------------------
__global__ void __launch_bounds__(256) ln_res_kernel(
    const float* __restrict__ src, const float* __restrict__ resid,
    const float* __restrict__ gamma, const float* __restrict__ beta,
    float* __restrict__ dst)
{
    const int row = blockIdx.x;
    const int t = threadIdx.x;
    const float4 v = *(const float4*)&src[(size_t)row * DIM + t * 4];

    float sum = v.x + v.y + v.z + v.w;
    float sq = v.x * v.x + v.y * v.y + v.z * v.z + v.w * v.w;
#pragma unroll
    for (int o = 16; o; o >>= 1) {
        sum += __shfl_xor_sync(0xFFFFFFFFu, sum, o);
        sq  += __shfl_xor_sync(0xFFFFFFFFu, sq, o);
    }
    __shared__ float ssum[8], ssq[8];
    const int w = t >> 5, l = t & 31;
    if (l == 0) { ssum[w] = sum; ssq[w] = sq; }
    __syncthreads();
    sum = 0.f; sq = 0.f;
#pragma unroll
    for (int i = 0; i < 8; i++) { sum += ssum[i]; sq += ssq[i]; }

    const float mu = sum * (1.f / DIM);
    const float var = sq * (1.f / DIM) - mu * mu;
    const float rstd = rsqrtf(var + 1e-5f);

    const float4 g = *(const float4*)&gamma[t * 4];
    const float4 b = *(const float4*)&beta[t * 4];
    const float4 rr = *(const float4*)&resid[(size_t)row * DIM + t * 4];
    float4 o;
    o.x = (v.x - mu) * rstd * g.x + b.x + rr.x;
    o.y = (v.y - mu) * rstd * g.y + b.y + rr.y;
    o.z = (v.z - mu) * rstd * g.z + b.z + rr.z;
    o.w = (v.w - mu) * rstd * g.w + b.w + rr.w;
    *(float4*)&dst[(size_t)row * DIM + t * 4] = o;
}

// ---------------------------------------------------------------------------
// kernel_launch
// ---------------------------------------------------------------------------
extern "C" void kernel_launch(void* const* d_in, const int* in_sizes, int n_in,
                              void* d_out, int out_size)
{
    const float* node       = (const float*)d_in[0];
    const float* edge       = (const float*)d_in[1];
    const float* w_query    = (const float*)d_in[2];
    const float* b_query    = (const float*)d_in[3];
    const float* w_edge     = (const float*)d_in[4];
    const float* b_edge     = (const float*)d_in[5];
    const float* w_to_q     = (const float*)d_in[6];
    const float* w_to_k     = (const float*)d_in[7];
    const float* proj_k     = (const float*)d_in[8];
    const float* w_out      = (const float*)d_in[9];
    const float* b_out      = (const float*)d_in[10];
    const float* gamma_node = (const float*)d_in[11];
    const float* beta_node  = (const float*)d_in[12];
    const float* gamma_edge = (const float*)d_in[13];
    const float* beta_edge  = (const float*)d_in[14];

    float* x_out = (float*)d_out;
    float* y_out = (float*)d_out + (size_t)N_NODES * DIM;

    __nv_bfloat16 *eh, *el, *weTh, *weTl, *nh, *nl, *wqTh, *wqTl;
    __nv_bfloat16 *wqkTh, *wqkTl, *woTh, *woTl, *xqh, *xql, *ah, *al;
    float *qkv, *kp, *xattn;
    cudaGetSymbolAddress((void**)&eh, g_eh);
    cudaGetSymbolAddress((void**)&el, g_el);
    cudaGetSymbolAddress((void**)&weTh, g_weT_h);
    cudaGetSymbolAddress((void**)&weTl, g_weT_l);
    cudaGetSymbolAddress((void**)&nh, g_nh);
    cudaGetSymbolAddress((void**)&nl, g_nl);
    cudaGetSymbolAddress((void**)&wqTh, g_wqT_h);
    cudaGetSymbolAddress((void**)&wqTl, g_wqT_l);
    cudaGetSymbolAddress((void**)&wqkTh, g_wqkT_h);
    cudaGetSymbolAddress((void**)&wqkTl, g_wqkT_l);
    cudaGetSymbolAddress((void**)&woTh, g_woT_h);
    cudaGetSymbolAddress((void**)&woTl, g_woT_l);
    cudaGetSymbolAddress((void**)&xqh, g_xqh);
    cudaGetSymbolAddress((void**)&xql, g_xql);
    cudaGetSymbolAddress((void**)&ah, g_ah);
    cudaGetSymbolAddress((void**)&al, g_al);
    cudaGetSymbolAddress((void**)&qkv, g_qkv);
    cudaGetSymbolAddress((void**)&kp, g_kproj);
    cudaGetSymbolAddress((void**)&xattn, g_xattn);

    static bool attr_set = false;
    if (!attr_set) {
        cudaFuncSetAttribute(gemm_bf16s,
                             cudaFuncAttributeMaxDynamicSharedMemorySize, SM_TOTAL);
        attr_set = true;
    }

    // ---------------- edge path (dominant) ----------------
    {
        const int n4 = N_EDGES * DIM / 4;
        split_kernel<<<(n4 + 255) / 256, 256>>>(
            (const float4*)edge, (__nv_bfloat162*)eh, (__nv_bfloat162*)el, n4);
    }
    tsplit_kernel<<<dim3(32, 32), dim3(32, 8)>>>(w_edge, weTh, weTl, DIM);
    gemm_bf16s<<<dim3(8, 256), 256, SM_TOTAL>>>(
        eh, el, weTh, weTl, b_edge, y_out, nullptr, nullptr, DIM);
    ln_res_kernel<<<N_EDGES, 256>>>(y_out, edge, gamma_edge, beta_edge, y_out);

    // ---------------- node path ----------------
    {
        const int n4 = N_NODES * DIM / 4;
        split_kernel<<<(n4 + 255) / 256, 256>>>(
            (const float4*)node, (__nv_bfloat162*)nh, (__nv_bfloat162*)nl, n4);
    }
    tsplit_kernel<<<dim3(32, 32), dim3(32, 8)>>>(w_query, wqTh, wqTl, DIM);
    gemm_bf16s<<<dim3(8, 8), 256, SM_TOTAL>>>(
        nh, nl, wqTh, wqTl, b_query, nullptr, xqh, xql, DIM);

    tsplit_kernel<<<dim3(32, 32), dim3(32, 8)>>>(w_to_q, wqkTh, wqkTl, DIM);
    tsplit_kernel<<<dim3(4, 32), dim3(32, 8)>>>(
        w_to_k, wqkTh + (size_t)1024 * 1024, wqkTl + (size_t)1024 * 1024, DH);
    gemm_bf16s<<<dim3(9, 8), 256, SM_TOTAL>>>(
        xqh, xql, wqkTh, wqkTl, nullptr, qkv, nullptr, nullptr, QKV_N);

    kproj_kernel<<<KPROJ, 128>>>(qkv + 1024, QKV_N, proj_k, kp);
    attn_kernel<<<N_NODES, 256>>>(qkv, QKV_N, kp, ah, al);

    tsplit_kernel<<<dim3(32, 32), dim3(32, 8)>>>(w_out, woTh, woTl, DIM);
    gemm_bf16s<<<dim3(8, 8), 256, SM_TOTAL>>>(
        ah, al, woTh, woTl, b_out, xattn, nullptr, nullptr, DIM);
    ln_res_kernel<<<N_NODES, 256>>>(xattn, node, gamma_node, beta_node, x_out);
}

// round 4
// speedup vs baseline: 3.0213x; 1.1674x over previous
#include <cuda_runtime.h>
#include <cuda_bf16.h>
#include <cuda_fp16.h>
#include <math.h>
#include <stdint.h>

#define N_NODES 1024
#define N_EDGES 32768
#define DIM     1024
#define HEADS   8
#define DH      128
#define KPROJ   256
#define QKV_N   1152   // w_to_q (1024) ++ w_to_k (128), fused GEMM

// ---------------------------------------------------------------------------
// Scratch (device globals -- no allocation allowed)
// ---------------------------------------------------------------------------
__device__ __half        g_ehh[N_EDGES * DIM], g_ehl[N_EDGES * DIM];   // edge fp16 hi/lo
__device__ __half        g_weT16[DIM * DIM];                           // w_edge^T fp16 hi
__device__ __nv_bfloat16 g_nh[N_NODES * DIM],  g_nl[N_NODES * DIM];    // node hi/lo
__device__ __nv_bfloat16 g_wqT_h[DIM * DIM],   g_wqT_l[DIM * DIM];     // w_query^T
__device__ __nv_bfloat16 g_wqkT_h[QKV_N * DIM], g_wqkT_l[QKV_N * DIM]; // [w_to_q|w_to_k]^T
__device__ __nv_bfloat16 g_woT_h[DIM * DIM],   g_woT_l[DIM * DIM];     // w_out^T
__device__ __nv_bfloat16 g_xqh[N_NODES * DIM], g_xql[N_NODES * DIM];   // xq hi/lo
__device__ float         g_qkv[N_NODES * QKV_N];                       // [q | kv] fp32
__device__ float         g_kproj[KPROJ * DH];
__device__ __nv_bfloat16 g_ah[N_NODES * DIM],  g_al[N_NODES * DIM];    // attn out hi/lo
__device__ float         g_xattn[N_NODES * DIM];

// ---------------------------------------------------------------------------
// Generic-ISA PTX helpers (NO arch-specific 'a' instructions)
// ---------------------------------------------------------------------------
__device__ __forceinline__ uint32_t smem_u32(const void* p) {
    uint32_t a;
    asm("{ .reg .u64 t; cvta.to.shared.u64 t, %1; cvt.u32.u64 %0, t; }"
        : "=r"(a) : "l"(p));
    return a;
}

#define CP_ASYNC16(dst, src) \
    asm volatile("cp.async.cg.shared.global [%0], [%1], 16;" :: "r"(dst), "l"(src))
#define CP_COMMIT() asm volatile("cp.async.commit_group;" ::: "memory")
#define CP_WAIT1()  asm volatile("cp.async.wait_group 1;" ::: "memory")
#define CP_WAIT2()  asm volatile("cp.async.wait_group 2;" ::: "memory")

#define LDSM4(r, addr) \
    asm volatile("ldmatrix.sync.aligned.m8n8.x4.shared.b16 {%0,%1,%2,%3}, [%4];" \
        : "=r"((r)[0]), "=r"((r)[1]), "=r"((r)[2]), "=r"((r)[3]) : "r"(addr))
#define LDSM2(r, addr) \
    asm volatile("ldmatrix.sync.aligned.m8n8.x2.shared.b16 {%0,%1}, [%2];" \
        : "=r"((r)[0]), "=r"((r)[1]) : "r"(addr))

__device__ __forceinline__ void mma16816(float* c, const uint32_t* a, const uint32_t* b) {
    asm volatile(
        "mma.sync.aligned.m16n8k16.row.col.f32.bf16.bf16.f32 "
        "{%0,%1,%2,%3}, {%4,%5,%6,%7}, {%8,%9}, {%0,%1,%2,%3};"
        : "+f"(c[0]), "+f"(c[1]), "+f"(c[2]), "+f"(c[3])
        : "r"(a[0]), "r"(a[1]), "r"(a[2]), "r"(a[3]), "r"(b[0]), "r"(b[1]));
}

__device__ __forceinline__ void mma16816h(float* c, const uint32_t* a, const uint32_t* b) {
    asm volatile(
        "mma.sync.aligned.m16n8k16.row.col.f32.f16.f16.f32 "
        "{%0,%1,%2,%3}, {%4,%5,%6,%7}, {%8,%9}, {%0,%1,%2,%3};"
        : "+f"(c[0]), "+f"(c[1]), "+f"(c[2]), "+f"(c[3])
        : "r"(a[0]), "r"(a[1]), "r"(a[2]), "r"(a[3]), "r"(b[0]), "r"(b[1]));
}

// ---------------------------------------------------------------------------
// Shared GEMM geometry: BM=BN=128, BK=32, 256 threads (8 warps, 2x4 warp grid,
// warp tile 64x32). Smem rows padded to 80B -> conflict-free ldmatrix.
// ---------------------------------------------------------------------------
#define GK 1024
#define NT_K 32                    // 1024 / BK
#define ROWB 80                    // padded smem row stride (bytes) for 32 halves
#define TILE_BYTES (128 * ROWB)    // 10240
#define SM_HDR 512

// ===========================================================================
// EDGE GEMM (fp16, 2-term): C = Ah*Bh + Al*Bh  (+bias) -> fp32
// A split fp16 hi/lo [M,1024]; B transposed fp16 hi [N,1024].
// 4-stage cp.async pipeline, 3 tiles per stage (Ah, Al, Bh).
// ===========================================================================
#define STAGE2_BYTES (3 * TILE_BYTES)             // 30720
#define SM2_TOTAL (SM_HDR + 4 * STAGE2_BYTES)     // 123392

__global__ void __launch_bounds__(256, 1) gemm_f16_2t(
    const __half* __restrict__ Ah, const __half* __restrict__ Al,
    const __half* __restrict__ BhT, const float* __restrict__ bias,
    float* __restrict__ Cf, int Nt)
{
    extern __shared__ char smem[];
    const uint32_t sb = smem_u32(smem);
    const int tid = threadIdx.x;
    const int wid = tid >> 5;
    const int lane = tid & 31;
    const int bm = blockIdx.y * 128;
    const int bn = blockIdx.x * 128;

    if (tid < 128) ((float*)smem)[tid] = bias ? bias[bn + tid] : 0.f;

    const __half* srcs[3] = {
        Ah + (size_t)bm * GK, Al + (size_t)bm * GK, BhT + (size_t)bn * GK };

    auto load_stage = [&](int kt, int s) {
        const uint32_t base = sb + SM_HDR + s * STAGE2_BYTES;
#pragma unroll
        for (int t = 0; t < 3; t++) {
#pragma unroll
            for (int i = 0; i < 2; i++) {
                const int idx = i * 256 + tid;      // 0..511
                const int row = idx >> 2, seg = idx & 3;
                const void* g = srcs[t] + (size_t)row * GK + kt * 32 + seg * 8;
                CP_ASYNC16(base + t * TILE_BYTES + row * ROWB + seg * 16, g);
            }
        }
    };

    // prologue: stages 0, 1, 2
    load_stage(0, 0); CP_COMMIT();
    load_stage(1, 1); CP_COMMIT();
    load_stage(2, 2); CP_COMMIT();

    const int wm = (wid >> 2) * 64;
    const int wn = (wid & 3) * 32;
    const uint32_t aoff = (uint32_t)(lane & 15) * ROWB + (uint32_t)(lane >> 4) * 16;
    const int l15 = lane & 15;
    const uint32_t boff = (uint32_t)(l15 & 7) * ROWB + (uint32_t)(l15 >> 3) * 16;

    float acc[4][4][4];
#pragma unroll
    for (int mt = 0; mt < 4; mt++)
#pragma unroll
        for (int nt = 0; nt < 4; nt++)
#pragma unroll
            for (int j = 0; j < 4; j++) acc[mt][nt][j] = 0.f;

    for (int kt = 0; kt < NT_K; kt++) {
        CP_WAIT2();          // tile kt resident (>=2 younger groups may be pending)
        __syncthreads();     // also: all warps done reading stage (kt-1)%4

        if (kt + 3 < NT_K) { load_stage(kt + 3, (kt + 3) & 3); CP_COMMIT(); }

        const uint32_t st = sb + SM_HDR + (kt & 3) * STAGE2_BYTES;
        const uint32_t tAh = st;
        const uint32_t tAl = st + TILE_BYTES;
        const uint32_t tBh = st + 2 * TILE_BYTES;

#pragma unroll
        for (int kh = 0; kh < 2; kh++) {
            const uint32_t kb = kh * 32;
            uint32_t aF[4][4], bH[4][2];
#pragma unroll
            for (int nt = 0; nt < 4; nt++)
                LDSM2(bH[nt], tBh + (uint32_t)(wn + nt * 8) * ROWB + kb + boff);
#pragma unroll
            for (int mt = 0; mt < 4; mt++)
                LDSM4(aF[mt], tAh + (uint32_t)(wm + mt * 16) * ROWB + kb + aoff);
#pragma unroll
            for (int mt = 0; mt < 4; mt++)
#pragma unroll
                for (int nt = 0; nt < 4; nt++)
                    mma16816h(acc[mt][nt], aF[mt], bH[nt]);
#pragma unroll
            for (int mt = 0; mt < 4; mt++)
                LDSM4(aF[mt], tAl + (uint32_t)(wm + mt * 16) * ROWB + kb + aoff);
#pragma unroll
            for (int mt = 0; mt < 4; mt++)
#pragma unroll
                for (int nt = 0; nt < 4; nt++)
                    mma16816h(acc[mt][nt], aF[mt], bH[nt]);
        }
    }

    const float* bs = (const float*)smem;
#pragma unroll
    for (int mt = 0; mt < 4; mt++) {
#pragma unroll
        for (int nt = 0; nt < 4; nt++) {
            const int c = wn + nt * 8 + (lane & 3) * 2;
            const size_t r0 = (size_t)bm + wm + mt * 16 + (lane >> 2);
            *(float2*)&Cf[r0 * Nt + bn + c] =
                make_float2(acc[mt][nt][0] + bs[c], acc[mt][nt][1] + bs[c + 1]);
            *(float2*)&Cf[(r0 + 8) * Nt + bn + c] =
                make_float2(acc[mt][nt][2] + bs[c], acc[mt][nt][3] + bs[c + 1]);
        }
    }
}

// ===========================================================================
// NODE GEMM (bf16, 3-term): C ~= Ah*Bh + Ah*Bl + Al*Bh  (proven, rel ~5e-6)
// ===========================================================================
#define STAGE_BYTES (4 * TILE_BYTES)
#define SM_TOTAL (SM_HDR + 3 * STAGE_BYTES)   // 123392

__global__ void __launch_bounds__(256, 1) gemm_bf16s(
    const __nv_bfloat16* __restrict__ Ah, const __nv_bfloat16* __restrict__ Al,
    const __nv_bfloat16* __restrict__ BhT, const __nv_bfloat16* __restrict__ BlT,
    const float* __restrict__ bias,
    float* __restrict__ Cf, __nv_bfloat16* __restrict__ Ch, __nv_bfloat16* __restrict__ Cl,
    int Nt)
{
    extern __shared__ char smem[];
    const uint32_t sb = smem_u32(smem);
    const int tid = threadIdx.x;
    const int wid = tid >> 5;
    const int lane = tid & 31;
    const int bm = blockIdx.y * 128;
    const int bn = blockIdx.x * 128;

    if (tid < 128) ((float*)smem)[tid] = bias ? bias[bn + tid] : 0.f;

    const __nv_bfloat16* srcs[4] = {
        Ah + (size_t)bm * GK, Al + (size_t)bm * GK,
        BhT + (size_t)bn * GK, BlT + (size_t)bn * GK };

    auto load_stage = [&](int kt, int s) {
        const uint32_t base = sb + SM_HDR + s * STAGE_BYTES;
#pragma unroll
        for (int t = 0; t < 4; t++) {
#pragma unroll
            for (int i = 0; i < 2; i++) {
                const int idx = i * 256 + tid;
                const int row = idx >> 2, seg = idx & 3;
                const void* g = srcs[t] + (size_t)row * GK + kt * 32 + seg * 8;
                CP_ASYNC16(base + t * TILE_BYTES + row * ROWB + seg * 16, g);
            }
        }
    };

    load_stage(0, 0); CP_COMMIT();
    load_stage(1, 1); CP_COMMIT();

    const int wm = (wid >> 2) * 64;
    const int wn = (wid & 3) * 32;
    const uint32_t aoff = (uint32_t)(lane & 15) * ROWB + (uint32_t)(lane >> 4) * 16;
    const int l15 = lane & 15;
    const uint32_t boff = (uint32_t)(l15 & 7) * ROWB + (uint32_t)(l15 >> 3) * 16;

    float acc[4][4][4];
#pragma unroll
    for (int mt = 0; mt < 4; mt++)
#pragma unroll
        for (int nt = 0; nt < 4; nt++)
#pragma unroll
            for (int j = 0; j < 4; j++) acc[mt][nt][j] = 0.f;

    for (int kt = 0; kt < NT_K; kt++) {
        CP_WAIT1();
        __syncthreads();

        if (kt + 2 < NT_K) { load_stage(kt + 2, (kt + 2) % 3); CP_COMMIT(); }

        const uint32_t st = sb + SM_HDR + (kt % 3) * STAGE_BYTES;
        const uint32_t tAh = st;
        const uint32_t tAl = st + TILE_BYTES;
        const uint32_t tBh = st + 2 * TILE_BYTES;
        const uint32_t tBl = st + 3 * TILE_BYTES;

#pragma unroll
        for (int kh = 0; kh < 2; kh++) {
            const uint32_t kb = kh * 32;
            uint32_t aF[4][4], bH[4][2], bL[4][2];
#pragma unroll
            for (int nt = 0; nt < 4; nt++) {
                const uint32_t bo = (uint32_t)(wn + nt * 8) * ROWB + kb + boff;
                LDSM2(bH[nt], tBh + bo);
                LDSM2(bL[nt], tBl + bo);
            }
#pragma unroll
            for (int mt = 0; mt < 4; mt++)
                LDSM4(aF[mt], tAh + (uint32_t)(wm + mt * 16) * ROWB + kb + aoff);
#pragma unroll
            for (int mt = 0; mt < 4; mt++)
#pragma unroll
                for (int nt = 0; nt < 4; nt++) {
                    mma16816(acc[mt][nt], aF[mt], bH[nt]);
                    mma16816(acc[mt][nt], aF[mt], bL[nt]);
                }
#pragma unroll
            for (int mt = 0; mt < 4; mt++)
                LDSM4(aF[mt], tAl + (uint32_t)(wm + mt * 16) * ROWB + kb + aoff);
#pragma unroll
            for (int mt = 0; mt < 4; mt++)
#pragma unroll
                for (int nt = 0; nt < 4; nt++)
                    mma16816(acc[mt][nt], aF[mt], bH[nt]);
        }
    }

    const float* bs = (const float*)smem;
#pragma unroll
    for (int mt = 0; mt < 4; mt++) {
#pragma unroll
        for (int nt = 0; nt < 4; nt++) {
            const int c = wn + nt * 8 + (lane & 3) * 2;
            const size_t r0 = (size_t)bm + wm + mt * 16 + (lane >> 2);
            const float v0 = acc[mt][nt][0] + bs[c];
            const float v1 = acc[mt][nt][1] + bs[c + 1];
            const float v2 = acc[mt][nt][2] + bs[c];
            const float v3 = acc[mt][nt][3] + bs[c + 1];
            if (Cf) {
                *(float2*)&Cf[r0 * Nt + bn + c]       = make_float2(v0, v1);
                *(float2*)&Cf[(r0 + 8) * Nt + bn + c] = make_float2(v2, v3);
            }
            if (Ch) {
                __nv_bfloat16 h0 = __float2bfloat16(v0), h1 = __float2bfloat16(v1);
                __nv_bfloat16 h2 = __float2bfloat16(v2), h3 = __float2bfloat16(v3);
                *(__nv_bfloat162*)&Ch[r0 * Nt + bn + c] = __halves2bfloat162(h0, h1);
                *(__nv_bfloat162*)&Ch[(r0 + 8) * Nt + bn + c] = __halves2bfloat162(h2, h3);
                *(__nv_bfloat162*)&Cl[r0 * Nt + bn + c] = __halves2bfloat162(
                    __float2bfloat16(v0 - __bfloat162float(h0)),
                    __float2bfloat16(v1 - __bfloat162float(h1)));
                *(__nv_bfloat162*)&Cl[(r0 + 8) * Nt + bn + c] = __halves2bfloat162(
                    __float2bfloat16(v2 - __bfloat162float(h2)),
                    __float2bfloat16(v3 - __bfloat162float(h3)));
            }
        }
    }
}

// ---------------------------------------------------------------------------
// fp32 -> fp16 hi/lo split (elementwise)
// ---------------------------------------------------------------------------
__global__ void __launch_bounds__(256) split_f16_kernel(
    const float4* __restrict__ in, __half2* __restrict__ oh,
    __half2* __restrict__ ol, int n4)
{
    int i = blockIdx.x * 256 + threadIdx.x;
    if (i >= n4) return;
    float4 v = in[i];
    __half h0 = __float2half(v.x), h1 = __float2half(v.y);
    __half h2 = __float2half(v.z), h3 = __float2half(v.w);
    oh[2 * i + 0] = __halves2half2(h0, h1);
    oh[2 * i + 1] = __halves2half2(h2, h3);
    ol[2 * i + 0] = __halves2half2(
        __float2half(v.x - __half2float(h0)), __float2half(v.y - __half2float(h1)));
    ol[2 * i + 1] = __halves2half2(
        __float2half(v.z - __half2float(h2)), __float2half(v.w - __half2float(h3)));
}

// ---------------------------------------------------------------------------
// w[K,N] fp32 -> out[N,1024] fp16 (transpose, hi only); K == 1024.
// ---------------------------------------------------------------------------
__global__ void __launch_bounds__(256) t_f16_kernel(
    const float* __restrict__ w, __half* __restrict__ oh, int N)
{
    __shared__ float t[32][33];
    const int n0 = blockIdx.x * 32, k0 = blockIdx.y * 32;
    const int tx = threadIdx.x, ty = threadIdx.y;
#pragma unroll
    for (int i = 0; i < 4; i++)
        t[ty + i * 8][tx] = w[(size_t)(k0 + ty + i * 8) * N + n0 + tx];
    __syncthreads();
#pragma unroll
    for (int i = 0; i < 4; i++) {
        const int n = n0 + ty + i * 8, k = k0 + tx;
        oh[(size_t)n * 1024 + k] = __float2half(t[tx][ty + i * 8]);
    }
}

// ---------------------------------------------------------------------------
// fp32 -> bf16 hi/lo split (elementwise)  [node path]
// ---------------------------------------------------------------------------
__global__ void __launch_bounds__(256) split_kernel(
    const float4* __restrict__ in, __nv_bfloat162* __restrict__ oh,
    __nv_bfloat162* __restrict__ ol, int n4)
{
    int i = blockIdx.x * 256 + threadIdx.x;
    if (i >= n4) return;
    float4 v = in[i];
    __nv_bfloat16 h0 = __float2bfloat16(v.x), h1 = __float2bfloat16(v.y);
    __nv_bfloat16 h2 = __float2bfloat16(v.z), h3 = __float2bfloat16(v.w);
    oh[2 * i + 0] = __halves2bfloat162(h0, h1);
    oh[2 * i + 1] = __halves2bfloat162(h2, h3);
    ol[2 * i + 0] = __halves2bfloat162(
        __float2bfloat16(v.x - __bfloat162float(h0)),
        __float2bfloat16(v.y - __bfloat162float(h1)));
    ol[2 * i + 1] = __halves2bfloat162(
        __float2bfloat16(v.z - __bfloat162float(h2)),
        __float2bfloat16(v.w - __bfloat162float(h3)));
}

// ---------------------------------------------------------------------------
// w[K,N] fp32 -> out[N,1024] bf16 hi/lo (transpose + split); K == 1024.
// ---------------------------------------------------------------------------
__global__ void __launch_bounds__(256) tsplit_kernel(
    const float* __restrict__ w, __nv_bfloat16* __restrict__ oh,
    __nv_bfloat16* __restrict__ ol, int N)
{
    __shared__ float t[32][33];
    const int n0 = blockIdx.x * 32, k0 = blockIdx.y * 32;
    const int tx = threadIdx.x, ty = threadIdx.y;
#pragma unroll
    for (int i = 0; i < 4; i++)
        t[ty + i * 8][tx] = w[(size_t)(k0 + ty + i * 8) * N + n0 + tx];
    __syncthreads();
#pragma unroll
    for (int i = 0; i < 4; i++) {
        const int n = n0 + ty + i * 8, k = k0 + tx;
        const float v = t[tx][ty + i * 8];
        __nv_bfloat16 h = __float2bfloat16(v);
        oh[(size_t)n * 1024 + k] = h;
        ol[(size_t)n * 1024 + k] = __float2bfloat16(v - __bfloat162float(h));
    }
}

// ---------------------------------------------------------------------------
// kproj[k,d] = sum_n proj_k[n,k] * kv[n,d]  (kv row stride kvs)
// ---------------------------------------------------------------------------
__global__ void __launch_bounds__(128) kproj_kernel(
    const float* __restrict__ kv, int kvs, const float* __restrict__ pk,
    float* __restrict__ kp)
{
    const int k = blockIdx.x;
    const int d = threadIdx.x;
    float s0 = 0.f, s1 = 0.f, s2 = 0.f, s3 = 0.f;
#pragma unroll 4
    for (int n = 0; n < N_NODES; n += 4) {
        s0 += pk[(size_t)(n + 0) * KPROJ + k] * kv[(size_t)(n + 0) * kvs + d];
        s1 += pk[(size_t)(n + 1) * KPROJ + k] * kv[(size_t)(n + 1) * kvs + d];
        s2 += pk[(size_t)(n + 2) * KPROJ + k] * kv[(size_t)(n + 2) * kvs + d];
        s3 += pk[(size_t)(n + 3) * KPROJ + k] * kv[(size_t)(n + 3) * kvs + d];
    }
    kp[(size_t)k * DH + d] = (s0 + s1) + (s2 + s3);
}

// ---------------------------------------------------------------------------
// Fused attention (per node, 8 warps = 8 heads) -> bf16 hi/lo output
// ---------------------------------------------------------------------------
__global__ void __launch_bounds__(256) attn_kernel(
    const float* __restrict__ q, int qs, const float* __restrict__ kproj,
    __nv_bfloat16* __restrict__ oh, __nv_bfloat16* __restrict__ ol)
{
    __shared__ float q_s[DIM];
    __shared__ float prob[HEADS][KPROJ];

    const int n = blockIdx.x;
    for (int i = threadIdx.x; i < DIM; i += 256)
        q_s[i] = q[(size_t)n * qs + i];
    __syncthreads();

    const int w = threadIdx.x >> 5;
    const int l = threadIdx.x & 31;
    const float4* qh4 = (const float4*)(q_s + w * DH);

    float d8[8];
#pragma unroll
    for (int j = 0; j < 8; j++) {
        const int k = j * 32 + l;
        const float4* kr4 = (const float4*)(kproj + (size_t)k * DH);
        float s = 0.f;
#pragma unroll
        for (int d4 = 0; d4 < DH / 4; d4++) {
            float4 qq = qh4[d4], kk = kr4[d4];
            s += qq.x * kk.x + qq.y * kk.y + qq.z * kk.z + qq.w * kk.w;
        }
        d8[j] = s * 0.088388347648318447f;
    }
    float mx = d8[0];
#pragma unroll
    for (int j = 1; j < 8; j++) mx = fmaxf(mx, d8[j]);
#pragma unroll
    for (int o = 16; o; o >>= 1) mx = fmaxf(mx, __shfl_xor_sync(0xFFFFFFFFu, mx, o));
    float sum = 0.f;
#pragma unroll
    for (int j = 0; j < 8; j++) { d8[j] = expf(d8[j] - mx); sum += d8[j]; }
#pragma unroll
    for (int o = 16; o; o >>= 1) sum += __shfl_xor_sync(0xFFFFFFFFu, sum, o);
    const float inv = 1.f / sum;
#pragma unroll
    for (int j = 0; j < 8; j++) prob[w][j * 32 + l] = d8[j] * inv;
    __syncwarp();

    float o0 = 0.f, o1 = 0.f, o2 = 0.f, o3 = 0.f;
    for (int k = 0; k < KPROJ; k++) {
        const float p = prob[w][k];
        const float* kr = kproj + (size_t)k * DH + l;
        o0 += p * kr[0];  o1 += p * kr[32];
        o2 += p * kr[64]; o3 += p * kr[96];
    }
    const size_t ob = (size_t)n * DIM + w * DH + l;
    float ov[4] = {o0, o1, o2, o3};
#pragma unroll
    for (int j = 0; j < 4; j++) {
        __nv_bfloat16 h = __float2bfloat16(ov[j]);
        oh[ob + 32 * j] = h;
        ol[ob + 32 * j] = __float2bfloat16(ov[j] - __bfloat162float(h));
    }
}

// ---------------------------------------------------------------------------
// LayerNorm + residual (in-place safe)
// ---------------------------------------------------------------------------
__global__ void __launch_bounds__(256) ln_res_kernel(
    const float* __restrict__ src, const float* __restrict__ resid,
    const float* __restrict__ gamma, const float* __restrict__ beta,
    float* __restrict__ dst)
{
    const int row = blockIdx.x;
    const int t = threadIdx.x;
    const float4 v = *(const float4*)&src[(size_t)row * DIM + t * 4];

    float sum = v.x + v.y + v.z + v.w;
    float sq = v.x * v.x + v.y * v.y + v.z * v.z + v.w * v.w;
#pragma unroll
    for (int o = 16; o; o >>= 1) {
        sum += __shfl_xor_sync(0xFFFFFFFFu, sum, o);
        sq  += __shfl_xor_sync(0xFFFFFFFFu, sq, o);
    }
    __shared__ float ssum[8], ssq[8];
    const int w = t >> 5, l = t & 31;
    if (l == 0) { ssum[w] = sum; ssq[w] = sq; }
    __syncthreads();
    sum = 0.f; sq = 0.f;
#pragma unroll
    for (int i = 0; i < 8; i++) { sum += ssum[i]; sq += ssq[i]; }

    const float mu = sum * (1.f / DIM);
    const float var = sq * (1.f / DIM) - mu * mu;
    const float rstd = rsqrtf(var + 1e-5f);

    const float4 g = *(const float4*)&gamma[t * 4];
    const float4 b = *(const float4*)&beta[t * 4];
    const float4 rr = *(const float4*)&resid[(size_t)row * DIM + t * 4];
    float4 o;
    o.x = (v.x - mu) * rstd * g.x + b.x + rr.x;
    o.y = (v.y - mu) * rstd * g.y + b.y + rr.y;
    o.z = (v.z - mu) * rstd * g.z + b.z + rr.z;
    o.w = (v.w - mu) * rstd * g.w + b.w + rr.w;
    *(float4*)&dst[(size_t)row * DIM + t * 4] = o;
}

// ---------------------------------------------------------------------------
// kernel_launch
// ---------------------------------------------------------------------------
extern "C" void kernel_launch(void* const* d_in, const int* in_sizes, int n_in,
                              void* d_out, int out_size)
{
    const float* node       = (const float*)d_in[0];
    const float* edge       = (const float*)d_in[1];
    const float* w_query    = (const float*)d_in[2];
    const float* b_query    = (const float*)d_in[3];
    const float* w_edge     = (const float*)d_in[4];
    const float* b_edge     = (const float*)d_in[5];
    const float* w_to_q     = (const float*)d_in[6];
    const float* w_to_k     = (const float*)d_in[7];
    const float* proj_k     = (const float*)d_in[8];
    const float* w_out      = (const float*)d_in[9];
    const float* b_out      = (const float*)d_in[10];
    const float* gamma_node = (const float*)d_in[11];
    const float* beta_node  = (const float*)d_in[12];
    const float* gamma_edge = (const float*)d_in[13];
    const float* beta_edge  = (const float*)d_in[14];

    float* x_out = (float*)d_out;
    float* y_out = (float*)d_out + (size_t)N_NODES * DIM;

    __half *ehh, *ehl, *weT16;
    __nv_bfloat16 *nh, *nl, *wqTh, *wqTl;
    __nv_bfloat16 *wqkTh, *wqkTl, *woTh, *woTl, *xqh, *xql, *ah, *al;
    float *qkv, *kp, *xattn;
    cudaGetSymbolAddress((void**)&ehh, g_ehh);
    cudaGetSymbolAddress((void**)&ehl, g_ehl);
    cudaGetSymbolAddress((void**)&weT16, g_weT16);
    cudaGetSymbolAddress((void**)&nh, g_nh);
    cudaGetSymbolAddress((void**)&nl, g_nl);
    cudaGetSymbolAddress((void**)&wqTh, g_wqT_h);
    cudaGetSymbolAddress((void**)&wqTl, g_wqT_l);
    cudaGetSymbolAddress((void**)&wqkTh, g_wqkT_h);
    cudaGetSymbolAddress((void**)&wqkTl, g_wqkT_l);
    cudaGetSymbolAddress((void**)&woTh, g_woT_h);
    cudaGetSymbolAddress((void**)&woTl, g_woT_l);
    cudaGetSymbolAddress((void**)&xqh, g_xqh);
    cudaGetSymbolAddress((void**)&xql, g_xql);
    cudaGetSymbolAddress((void**)&ah, g_ah);
    cudaGetSymbolAddress((void**)&al, g_al);
    cudaGetSymbolAddress((void**)&qkv, g_qkv);
    cudaGetSymbolAddress((void**)&kp, g_kproj);
    cudaGetSymbolAddress((void**)&xattn, g_xattn);

    static bool attr_set = false;
    if (!attr_set) {
        cudaFuncSetAttribute(gemm_bf16s,
                             cudaFuncAttributeMaxDynamicSharedMemorySize, SM_TOTAL);
        cudaFuncSetAttribute(gemm_f16_2t,
                             cudaFuncAttributeMaxDynamicSharedMemorySize, SM2_TOTAL);
        attr_set = true;
    }

    // ---------------- edge path (dominant, fp16 2-term) ----------------
    {
        const int n4 = N_EDGES * DIM / 4;
        split_f16_kernel<<<(n4 + 255) / 256, 256>>>(
            (const float4*)edge, (__half2*)ehh, (__half2*)ehl, n4);
    }
    t_f16_kernel<<<dim3(32, 32), dim3(32, 8)>>>(w_edge, weT16, DIM);
    gemm_f16_2t<<<dim3(8, 256), 256, SM2_TOTAL>>>(
        ehh, ehl, weT16, b_edge, y_out, DIM);
    ln_res_kernel<<<N_EDGES, 256>>>(y_out, edge, gamma_edge, beta_edge, y_out);

    // ---------------- node path (bf16 3-term, high precision) ----------------
    {
        const int n4 = N_NODES * DIM / 4;
        split_kernel<<<(n4 + 255) / 256, 256>>>(
            (const float4*)node, (__nv_bfloat162*)nh, (__nv_bfloat162*)nl, n4);
    }
    tsplit_kernel<<<dim3(32, 32), dim3(32, 8)>>>(w_query, wqTh, wqTl, DIM);
    gemm_bf16s<<<dim3(8, 8), 256, SM_TOTAL>>>(
        nh, nl, wqTh, wqTl, b_query, nullptr, xqh, xql, DIM);

    tsplit_kernel<<<dim3(32, 32), dim3(32, 8)>>>(w_to_q, wqkTh, wqkTl, DIM);
    tsplit_kernel<<<dim3(4, 32), dim3(32, 8)>>>(
        w_to_k, wqkTh + (size_t)1024 * 1024, wqkTl + (size_t)1024 * 1024, DH);
    gemm_bf16s<<<dim3(9, 8), 256, SM_TOTAL>>>(
        xqh, xql, wqkTh, wqkTl, nullptr, qkv, nullptr, nullptr, QKV_N);

    kproj_kernel<<<KPROJ, 128>>>(qkv + 1024, QKV_N, proj_k, kp);
    attn_kernel<<<N_NODES, 256>>>(qkv, QKV_N, kp, ah, al);

    tsplit_kernel<<<dim3(32, 32), dim3(32, 8)>>>(w_out, woTh, woTl, DIM);
    gemm_bf16s<<<dim3(8, 8), 256, SM_TOTAL>>>(
        ah, al, woTh, woTl, b_out, xattn, nullptr, nullptr, DIM);
    ln_res_kernel<<<N_NODES, 256>>>(xattn, node, gamma_node, beta_node, x_out);
}

// round 5
// speedup vs baseline: 3.6124x; 1.1956x over previous
#include <cuda_runtime.h>
#include <cuda_bf16.h>
#include <cuda_fp16.h>
#include <math.h>
#include <stdint.h>

#define N_NODES 1024
#define N_EDGES 32768
#define DIM     1024
#define HEADS   8
#define DH      128
#define KPROJ   256
#define QKV_N   1152   // w_to_q (1024) ++ w_to_k (128), fused GEMM

// ---------------------------------------------------------------------------
// Scratch (device globals -- no allocation allowed)
// ---------------------------------------------------------------------------
__device__ __half        g_e16[N_EDGES * DIM];                         // edge fp16
__device__ __half        g_weT16[DIM * DIM];                           // w_edge^T fp16
__device__ __nv_bfloat16 g_nh[N_NODES * DIM],  g_nl[N_NODES * DIM];    // node hi/lo
__device__ __nv_bfloat16 g_wqT_h[DIM * DIM],   g_wqT_l[DIM * DIM];     // w_query^T
__device__ __nv_bfloat16 g_wqkT_h[QKV_N * DIM], g_wqkT_l[QKV_N * DIM]; // [w_to_q|w_to_k]^T
__device__ __nv_bfloat16 g_woT_h[DIM * DIM],   g_woT_l[DIM * DIM];     // w_out^T
__device__ __nv_bfloat16 g_xqh[N_NODES * DIM], g_xql[N_NODES * DIM];   // xq hi/lo
__device__ float         g_qkv[N_NODES * QKV_N];                       // [q | kv] fp32
__device__ float         g_kproj[KPROJ * DH];
__device__ __nv_bfloat16 g_ah[N_NODES * DIM],  g_al[N_NODES * DIM];    // attn out hi/lo
__device__ float         g_xattn[N_NODES * DIM];

// ---------------------------------------------------------------------------
// Generic-ISA PTX helpers (NO arch-specific 'a' instructions)
// ---------------------------------------------------------------------------
__device__ __forceinline__ uint32_t smem_u32(const void* p) {
    uint32_t a;
    asm("{ .reg .u64 t; cvta.to.shared.u64 t, %1; cvt.u32.u64 %0, t; }"
        : "=r"(a) : "l"(p));
    return a;
}

#define CP_ASYNC16(dst, src) \
    asm volatile("cp.async.cg.shared.global [%0], [%1], 16;" :: "r"(dst), "l"(src))
#define CP_COMMIT() asm volatile("cp.async.commit_group;" ::: "memory")
#define CP_WAIT1()  asm volatile("cp.async.wait_group 1;" ::: "memory")
#define CP_WAIT2()  asm volatile("cp.async.wait_group 2;" ::: "memory")

#define LDSM4(r, addr) \
    asm volatile("ldmatrix.sync.aligned.m8n8.x4.shared.b16 {%0,%1,%2,%3}, [%4];" \
        : "=r"((r)[0]), "=r"((r)[1]), "=r"((r)[2]), "=r"((r)[3]) : "r"(addr))
#define LDSM2(r, addr) \
    asm volatile("ldmatrix.sync.aligned.m8n8.x2.shared.b16 {%0,%1}, [%2];" \
        : "=r"((r)[0]), "=r"((r)[1]) : "r"(addr))

__device__ __forceinline__ void mma16816(float* c, const uint32_t* a, const uint32_t* b) {
    asm volatile(
        "mma.sync.aligned.m16n8k16.row.col.f32.bf16.bf16.f32 "
        "{%0,%1,%2,%3}, {%4,%5,%6,%7}, {%8,%9}, {%0,%1,%2,%3};"
        : "+f"(c[0]), "+f"(c[1]), "+f"(c[2]), "+f"(c[3])
        : "r"(a[0]), "r"(a[1]), "r"(a[2]), "r"(a[3]), "r"(b[0]), "r"(b[1]));
}

__device__ __forceinline__ void mma16816h(float* c, const uint32_t* a, const uint32_t* b) {
    asm volatile(
        "mma.sync.aligned.m16n8k16.row.col.f32.f16.f16.f32 "
        "{%0,%1,%2,%3}, {%4,%5,%6,%7}, {%8,%9}, {%0,%1,%2,%3};"
        : "+f"(c[0]), "+f"(c[1]), "+f"(c[2]), "+f"(c[3])
        : "r"(a[0]), "r"(a[1]), "r"(a[2]), "r"(a[3]), "r"(b[0]), "r"(b[1]));
}

// ---------------------------------------------------------------------------
// Shared GEMM geometry: BM=BN=128, BK=32, 256 threads (8 warps, 2x4 warp grid,
// warp tile 64x32). Smem rows padded to 80B -> conflict-free ldmatrix.
// ---------------------------------------------------------------------------
#define GK 1024
#define NT_K 32                    // 1024 / BK
#define ROWB 80                    // padded smem row stride (bytes) for 32 halves
#define TILE_BYTES (128 * ROWB)    // 10240
#define SM_HDR 512

// ===========================================================================
// EDGE GEMM (fp16, 1-term): C = A16 * B16  (+bias) -> fp32
// A fp16 [M,1024]; B transposed fp16 [N,1024].
// 4-stage cp.async pipeline, 2 tiles per stage (A, B).
// ===========================================================================
#define STAGE1_BYTES (2 * TILE_BYTES)             // 20480
#define SM1_TOTAL (SM_HDR + 4 * STAGE1_BYTES)     // 82432

__global__ void __launch_bounds__(256, 1) gemm_f16_1t(
    const __half* __restrict__ A16, const __half* __restrict__ BhT,
    const float* __restrict__ bias, float* __restrict__ Cf, int Nt)
{
    extern __shared__ char smem[];
    const uint32_t sb = smem_u32(smem);
    const int tid = threadIdx.x;
    const int wid = tid >> 5;
    const int lane = tid & 31;
    const int bm = blockIdx.y * 128;
    const int bn = blockIdx.x * 128;

    if (tid < 128) ((float*)smem)[tid] = bias ? bias[bn + tid] : 0.f;

    const __half* srcs[2] = { A16 + (size_t)bm * GK, BhT + (size_t)bn * GK };

    auto load_stage = [&](int kt, int s) {
        const uint32_t base = sb + SM_HDR + s * STAGE1_BYTES;
#pragma unroll
        for (int t = 0; t < 2; t++) {
#pragma unroll
            for (int i = 0; i < 2; i++) {
                const int idx = i * 256 + tid;      // 0..511
                const int row = idx >> 2, seg = idx & 3;
                const void* g = srcs[t] + (size_t)row * GK + kt * 32 + seg * 8;
                CP_ASYNC16(base + t * TILE_BYTES + row * ROWB + seg * 16, g);
            }
        }
    };

    // prologue: stages 0, 1, 2
    load_stage(0, 0); CP_COMMIT();
    load_stage(1, 1); CP_COMMIT();
    load_stage(2, 2); CP_COMMIT();

    const int wm = (wid >> 2) * 64;
    const int wn = (wid & 3) * 32;
    const uint32_t aoff = (uint32_t)(lane & 15) * ROWB + (uint32_t)(lane >> 4) * 16;
    const int l15 = lane & 15;
    const uint32_t boff = (uint32_t)(l15 & 7) * ROWB + (uint32_t)(l15 >> 3) * 16;

    float acc[4][4][4];
#pragma unroll
    for (int mt = 0; mt < 4; mt++)
#pragma unroll
        for (int nt = 0; nt < 4; nt++)
#pragma unroll
            for (int j = 0; j < 4; j++) acc[mt][nt][j] = 0.f;

    for (int kt = 0; kt < NT_K; kt++) {
        CP_WAIT2();          // tile kt resident (<=2 younger groups pending)
        __syncthreads();     // also: all warps done reading stage (kt-1)&3

        if (kt + 3 < NT_K) { load_stage(kt + 3, (kt + 3) & 3); CP_COMMIT(); }

        const uint32_t st = sb + SM_HDR + (kt & 3) * STAGE1_BYTES;
        const uint32_t tA = st;
        const uint32_t tB = st + TILE_BYTES;

#pragma unroll
        for (int kh = 0; kh < 2; kh++) {
            const uint32_t kb = kh * 32;
            uint32_t aF[4][4], bH[4][2];
#pragma unroll
            for (int nt = 0; nt < 4; nt++)
                LDSM2(bH[nt], tB + (uint32_t)(wn + nt * 8) * ROWB + kb + boff);
#pragma unroll
            for (int mt = 0; mt < 4; mt++)
                LDSM4(aF[mt], tA + (uint32_t)(wm + mt * 16) * ROWB + kb + aoff);
#pragma unroll
            for (int mt = 0; mt < 4; mt++)
#pragma unroll
                for (int nt = 0; nt < 4; nt++)
                    mma16816h(acc[mt][nt], aF[mt], bH[nt]);
        }
    }

    const float* bs = (const float*)smem;
#pragma unroll
    for (int mt = 0; mt < 4; mt++) {
#pragma unroll
        for (int nt = 0; nt < 4; nt++) {
            const int c = wn + nt * 8 + (lane & 3) * 2;
            const size_t r0 = (size_t)bm + wm + mt * 16 + (lane >> 2);
            *(float2*)&Cf[r0 * Nt + bn + c] =
                make_float2(acc[mt][nt][0] + bs[c], acc[mt][nt][1] + bs[c + 1]);
            *(float2*)&Cf[(r0 + 8) * Nt + bn + c] =
                make_float2(acc[mt][nt][2] + bs[c], acc[mt][nt][3] + bs[c + 1]);
        }
    }
}

// ===========================================================================
// NODE GEMM (bf16, 3-term): C ~= Ah*Bh + Ah*Bl + Al*Bh  (proven, rel ~5e-6)
// ===========================================================================
#define STAGE_BYTES (4 * TILE_BYTES)
#define SM_TOTAL (SM_HDR + 3 * STAGE_BYTES)   // 123392

__global__ void __launch_bounds__(256, 1) gemm_bf16s(
    const __nv_bfloat16* __restrict__ Ah, const __nv_bfloat16* __restrict__ Al,
    const __nv_bfloat16* __restrict__ BhT, const __nv_bfloat16* __restrict__ BlT,
    const float* __restrict__ bias,
    float* __restrict__ Cf, __nv_bfloat16* __restrict__ Ch, __nv_bfloat16* __restrict__ Cl,
    int Nt)
{
    extern __shared__ char smem[];
    const uint32_t sb = smem_u32(smem);
    const int tid = threadIdx.x;
    const int wid = tid >> 5;
    const int lane = tid & 31;
    const int bm = blockIdx.y * 128;
    const int bn = blockIdx.x * 128;

    if (tid < 128) ((float*)smem)[tid] = bias ? bias[bn + tid] : 0.f;

    const __nv_bfloat16* srcs[4] = {
        Ah + (size_t)bm * GK, Al + (size_t)bm * GK,
        BhT + (size_t)bn * GK, BlT + (size_t)bn * GK };

    auto load_stage = [&](int kt, int s) {
        const uint32_t base = sb + SM_HDR + s * STAGE_BYTES;
#pragma unroll
        for (int t = 0; t < 4; t++) {
#pragma unroll
            for (int i = 0; i < 2; i++) {
                const int idx = i * 256 + tid;
                const int row = idx >> 2, seg = idx & 3;
                const void* g = srcs[t] + (size_t)row * GK + kt * 32 + seg * 8;
                CP_ASYNC16(base + t * TILE_BYTES + row * ROWB + seg * 16, g);
            }
        }
    };

    load_stage(0, 0); CP_COMMIT();
    load_stage(1, 1); CP_COMMIT();

    const int wm = (wid >> 2) * 64;
    const int wn = (wid & 3) * 32;
    const uint32_t aoff = (uint32_t)(lane & 15) * ROWB + (uint32_t)(lane >> 4) * 16;
    const int l15 = lane & 15;
    const uint32_t boff = (uint32_t)(l15 & 7) * ROWB + (uint32_t)(l15 >> 3) * 16;

    float acc[4][4][4];
#pragma unroll
    for (int mt = 0; mt < 4; mt++)
#pragma unroll
        for (int nt = 0; nt < 4; nt++)
#pragma unroll
            for (int j = 0; j < 4; j++) acc[mt][nt][j] = 0.f;

    for (int kt = 0; kt < NT_K; kt++) {
        CP_WAIT1();
        __syncthreads();

        if (kt + 2 < NT_K) { load_stage(kt + 2, (kt + 2) % 3); CP_COMMIT(); }

        const uint32_t st = sb + SM_HDR + (kt % 3) * STAGE_BYTES;
        const uint32_t tAh = st;
        const uint32_t tAl = st + TILE_BYTES;
        const uint32_t tBh = st + 2 * TILE_BYTES;
        const uint32_t tBl = st + 3 * TILE_BYTES;

#pragma unroll
        for (int kh = 0; kh < 2; kh++) {
            const uint32_t kb = kh * 32;
            uint32_t aF[4][4], bH[4][2], bL[4][2];
#pragma unroll
            for (int nt = 0; nt < 4; nt++) {
                const uint32_t bo = (uint32_t)(wn + nt * 8) * ROWB + kb + boff;
                LDSM2(bH[nt], tBh + bo);
                LDSM2(bL[nt], tBl + bo);
            }
#pragma unroll
            for (int mt = 0; mt < 4; mt++)
                LDSM4(aF[mt], tAh + (uint32_t)(wm + mt * 16) * ROWB + kb + aoff);
#pragma unroll
            for (int mt = 0; mt < 4; mt++)
#pragma unroll
                for (int nt = 0; nt < 4; nt++) {
                    mma16816(acc[mt][nt], aF[mt], bH[nt]);
                    mma16816(acc[mt][nt], aF[mt], bL[nt]);
                }
#pragma unroll
            for (int mt = 0; mt < 4; mt++)
                LDSM4(aF[mt], tAl + (uint32_t)(wm + mt * 16) * ROWB + kb + aoff);
#pragma unroll
            for (int mt = 0; mt < 4; mt++)
#pragma unroll
                for (int nt = 0; nt < 4; nt++)
                    mma16816(acc[mt][nt], aF[mt], bH[nt]);
        }
    }

    const float* bs = (const float*)smem;
#pragma unroll
    for (int mt = 0; mt < 4; mt++) {
#pragma unroll
        for (int nt = 0; nt < 4; nt++) {
            const int c = wn + nt * 8 + (lane & 3) * 2;
            const size_t r0 = (size_t)bm + wm + mt * 16 + (lane >> 2);
            const float v0 = acc[mt][nt][0] + bs[c];
            const float v1 = acc[mt][nt][1] + bs[c + 1];
            const float v2 = acc[mt][nt][2] + bs[c];
            const float v3 = acc[mt][nt][3] + bs[c + 1];
            if (Cf) {
                *(float2*)&Cf[r0 * Nt + bn + c]       = make_float2(v0, v1);
                *(float2*)&Cf[(r0 + 8) * Nt + bn + c] = make_float2(v2, v3);
            }
            if (Ch) {
                __nv_bfloat16 h0 = __float2bfloat16(v0), h1 = __float2bfloat16(v1);
                __nv_bfloat16 h2 = __float2bfloat16(v2), h3 = __float2bfloat16(v3);
                *(__nv_bfloat162*)&Ch[r0 * Nt + bn + c] = __halves2bfloat162(h0, h1);
                *(__nv_bfloat162*)&Ch[(r0 + 8) * Nt + bn + c] = __halves2bfloat162(h2, h3);
                *(__nv_bfloat162*)&Cl[r0 * Nt + bn + c] = __halves2bfloat162(
                    __float2bfloat16(v0 - __bfloat162float(h0)),
                    __float2bfloat16(v1 - __bfloat162float(h1)));
                *(__nv_bfloat162*)&Cl[(r0 + 8) * Nt + bn + c] = __halves2bfloat162(
                    __float2bfloat16(v2 - __bfloat162float(h2)),
                    __float2bfloat16(v3 - __bfloat162float(h3)));
            }
        }
    }
}

// ---------------------------------------------------------------------------
// fp32 -> fp16 convert (elementwise, hi only)
// ---------------------------------------------------------------------------
__global__ void __launch_bounds__(256) conv_f16_kernel(
    const float4* __restrict__ in, __half2* __restrict__ oh, int n4)
{
    int i = blockIdx.x * 256 + threadIdx.x;
    if (i >= n4) return;
    float4 v = in[i];
    oh[2 * i + 0] = __halves2half2(__float2half(v.x), __float2half(v.y));
    oh[2 * i + 1] = __halves2half2(__float2half(v.z), __float2half(v.w));
}

// ---------------------------------------------------------------------------
// w[K,N] fp32 -> out[N,1024] fp16 (transpose, hi only); K == 1024.
// ---------------------------------------------------------------------------
__global__ void __launch_bounds__(256) t_f16_kernel(
    const float* __restrict__ w, __half* __restrict__ oh, int N)
{
    __shared__ float t[32][33];
    const int n0 = blockIdx.x * 32, k0 = blockIdx.y * 32;
    const int tx = threadIdx.x, ty = threadIdx.y;
#pragma unroll
    for (int i = 0; i < 4; i++)
        t[ty + i * 8][tx] = w[(size_t)(k0 + ty + i * 8) * N + n0 + tx];
    __syncthreads();
#pragma unroll
    for (int i = 0; i < 4; i++) {
        const int n = n0 + ty + i * 8, k = k0 + tx;
        oh[(size_t)n * 1024 + k] = __float2half(t[tx][ty + i * 8]);
    }
}

// ---------------------------------------------------------------------------
// fp32 -> bf16 hi/lo split (elementwise)  [node path]
// ---------------------------------------------------------------------------
__global__ void __launch_bounds__(256) split_kernel(
    const float4* __restrict__ in, __nv_bfloat162* __restrict__ oh,
    __nv_bfloat162* __restrict__ ol, int n4)
{
    int i = blockIdx.x * 256 + threadIdx.x;
    if (i >= n4) return;
    float4 v = in[i];
    __nv_bfloat16 h0 = __float2bfloat16(v.x), h1 = __float2bfloat16(v.y);
    __nv_bfloat16 h2 = __float2bfloat16(v.z), h3 = __float2bfloat16(v.w);
    oh[2 * i + 0] = __halves2bfloat162(h0, h1);
    oh[2 * i + 1] = __halves2bfloat162(h2, h3);
    ol[2 * i + 0] = __halves2bfloat162(
        __float2bfloat16(v.x - __bfloat162float(h0)),
        __float2bfloat16(v.y - __bfloat162float(h1)));
    ol[2 * i + 1] = __halves2bfloat162(
        __float2bfloat16(v.z - __bfloat162float(h2)),
        __float2bfloat16(v.w - __bfloat162float(h3)));
}

// ---------------------------------------------------------------------------
// w[K,N] fp32 -> out[N,1024] bf16 hi/lo (transpose + split); K == 1024.
// ---------------------------------------------------------------------------
__global__ void __launch_bounds__(256) tsplit_kernel(
    const float* __restrict__ w, __nv_bfloat16* __restrict__ oh,
    __nv_bfloat16* __restrict__ ol, int N)
{
    __shared__ float t[32][33];
    const int n0 = blockIdx.x * 32, k0 = blockIdx.y * 32;
    const int tx = threadIdx.x, ty = threadIdx.y;
#pragma unroll
    for (int i = 0; i < 4; i++)
        t[ty + i * 8][tx] = w[(size_t)(k0 + ty + i * 8) * N + n0 + tx];
    __syncthreads();
#pragma unroll
    for (int i = 0; i < 4; i++) {
        const int n = n0 + ty + i * 8, k = k0 + tx;
        const float v = t[tx][ty + i * 8];
        __nv_bfloat16 h = __float2bfloat16(v);
        oh[(size_t)n * 1024 + k] = h;
        ol[(size_t)n * 1024 + k] = __float2bfloat16(v - __bfloat162float(h));
    }
}

// ---------------------------------------------------------------------------
// kproj[k,d] = sum_n proj_k[n,k] * kv[n,d]  (kv row stride kvs)
// ---------------------------------------------------------------------------
__global__ void __launch_bounds__(128) kproj_kernel(
    const float* __restrict__ kv, int kvs, const float* __restrict__ pk,
    float* __restrict__ kp)
{
    const int k = blockIdx.x;
    const int d = threadIdx.x;
    float s0 = 0.f, s1 = 0.f, s2 = 0.f, s3 = 0.f;
#pragma unroll 4
    for (int n = 0; n < N_NODES; n += 4) {
        s0 += pk[(size_t)(n + 0) * KPROJ + k] * kv[(size_t)(n + 0) * kvs + d];
        s1 += pk[(size_t)(n + 1) * KPROJ + k] * kv[(size_t)(n + 1) * kvs + d];
        s2 += pk[(size_t)(n + 2) * KPROJ + k] * kv[(size_t)(n + 2) * kvs + d];
        s3 += pk[(size_t)(n + 3) * KPROJ + k] * kv[(size_t)(n + 3) * kvs + d];
    }
    kp[(size_t)k * DH + d] = (s0 + s1) + (s2 + s3);
}

// ---------------------------------------------------------------------------
// Fused attention (per node, 8 warps = 8 heads) -> bf16 hi/lo output
// ---------------------------------------------------------------------------
__global__ void __launch_bounds__(256) attn_kernel(
    const float* __restrict__ q, int qs, const float* __restrict__ kproj,
    __nv_bfloat16* __restrict__ oh, __nv_bfloat16* __restrict__ ol)
{
    __shared__ float q_s[DIM];
    __shared__ float prob[HEADS][KPROJ];

    const int n = blockIdx.x;
    for (int i = threadIdx.x; i < DIM; i += 256)
        q_s[i] = q[(size_t)n * qs + i];
    __syncthreads();

    const int w = threadIdx.x >> 5;
    const int l = threadIdx.x & 31;
    const float4* qh4 = (const float4*)(q_s + w * DH);

    float d8[8];
#pragma unroll
    for (int j = 0; j < 8; j++) {
        const int k = j * 32 + l;
        const float4* kr4 = (const float4*)(kproj + (size_t)k * DH);
        float s = 0.f;
#pragma unroll
        for (int d4 = 0; d4 < DH / 4; d4++) {
            float4 qq = qh4[d4], kk = kr4[d4];
            s += qq.x * kk.x + qq.y * kk.y + qq.z * kk.z + qq.w * kk.w;
        }
        d8[j] = s * 0.088388347648318447f;
    }
    float mx = d8[0];
#pragma unroll
    for (int j = 1; j < 8; j++) mx = fmaxf(mx, d8[j]);
#pragma unroll
    for (int o = 16; o; o >>= 1) mx = fmaxf(mx, __shfl_xor_sync(0xFFFFFFFFu, mx, o));
    float sum = 0.f;
#pragma unroll
    for (int j = 0; j < 8; j++) { d8[j] = expf(d8[j] - mx); sum += d8[j]; }
#pragma unroll
    for (int o = 16; o; o >>= 1) sum += __shfl_xor_sync(0xFFFFFFFFu, sum, o);
    const float inv = 1.f / sum;
#pragma unroll
    for (int j = 0; j < 8; j++) prob[w][j * 32 + l] = d8[j] * inv;
    __syncwarp();

    float o0 = 0.f, o1 = 0.f, o2 = 0.f, o3 = 0.f;
    for (int k = 0; k < KPROJ; k++) {
        const float p = prob[w][k];
        const float* kr = kproj + (size_t)k * DH + l;
        o0 += p * kr[0];  o1 += p * kr[32];
        o2 += p * kr[64]; o3 += p * kr[96];
    }
    const size_t ob = (size_t)n * DIM + w * DH + l;
    float ov[4] = {o0, o1, o2, o3};
#pragma unroll
    for (int j = 0; j < 4; j++) {
        __nv_bfloat16 h = __float2bfloat16(ov[j]);
        oh[ob + 32 * j] = h;
        ol[ob + 32 * j] = __float2bfloat16(ov[j] - __bfloat162float(h));
    }
}

// ---------------------------------------------------------------------------
// LayerNorm + residual (in-place safe)
// ---------------------------------------------------------------------------
__global__ void __launch_bounds__(256) ln_res_kernel(
    const float* __restrict__ src, const float* __restrict__ resid,
    const float* __restrict__ gamma, const float* __restrict__ beta,
    float* __restrict__ dst)
{
    const int row = blockIdx.x;
    const int t = threadIdx.x;
    const float4 v = *(const float4*)&src[(size_t)row * DIM + t * 4];

    float sum = v.x + v.y + v.z + v.w;
    float sq = v.x * v.x + v.y * v.y + v.z * v.z + v.w * v.w;
#pragma unroll
    for (int o = 16; o; o >>= 1) {
        sum += __shfl_xor_sync(0xFFFFFFFFu, sum, o);
        sq  += __shfl_xor_sync(0xFFFFFFFFu, sq, o);
    }
    __shared__ float ssum[8], ssq[8];
    const int w = t >> 5, l = t & 31;
    if (l == 0) { ssum[w] = sum; ssq[w] = sq; }
    __syncthreads();
    sum = 0.f; sq = 0.f;
#pragma unroll
    for (int i = 0; i < 8; i++) { sum += ssum[i]; sq += ssq[i]; }

    const float mu = sum * (1.f / DIM);
    const float var = sq * (1.f / DIM) - mu * mu;
    const float rstd = rsqrtf(var + 1e-5f);

    const float4 g = *(const float4*)&gamma[t * 4];
    const float4 b = *(const float4*)&beta[t * 4];
    const float4 rr = *(const float4*)&resid[(size_t)row * DIM + t * 4];
    float4 o;
    o.x = (v.x - mu) * rstd * g.x + b.x + rr.x;
    o.y = (v.y - mu) * rstd * g.y + b.y + rr.y;
    o.z = (v.z - mu) * rstd * g.z + b.z + rr.z;
    o.w = (v.w - mu) * rstd * g.w + b.w + rr.w;
    *(float4*)&dst[(size_t)row * DIM + t * 4] = o;
}

// ---------------------------------------------------------------------------
// kernel_launch
// ---------------------------------------------------------------------------
extern "C" void kernel_launch(void* const* d_in, const int* in_sizes, int n_in,
                              void* d_out, int out_size)
{
    const float* node       = (const float*)d_in[0];
    const float* edge       = (const float*)d_in[1];
    const float* w_query    = (const float*)d_in[2];
    const float* b_query    = (const float*)d_in[3];
    const float* w_edge     = (const float*)d_in[4];
    const float* b_edge     = (const float*)d_in[5];
    const float* w_to_q     = (const float*)d_in[6];
    const float* w_to_k     = (const float*)d_in[7];
    const float* proj_k     = (const float*)d_in[8];
    const float* w_out      = (const float*)d_in[9];
    const float* b_out      = (const float*)d_in[10];
    const float* gamma_node = (const float*)d_in[11];
    const float* beta_node  = (const float*)d_in[12];
    const float* gamma_edge = (const float*)d_in[13];
    const float* beta_edge  = (const float*)d_in[14];

    float* x_out = (float*)d_out;
    float* y_out = (float*)d_out + (size_t)N_NODES * DIM;

    __half *e16, *weT16;
    __nv_bfloat16 *nh, *nl, *wqTh, *wqTl;
    __nv_bfloat16 *wqkTh, *wqkTl, *woTh, *woTl, *xqh, *xql, *ah, *al;
    float *qkv, *kp, *xattn;
    cudaGetSymbolAddress((void**)&e16, g_e16);
    cudaGetSymbolAddress((void**)&weT16, g_weT16);
    cudaGetSymbolAddress((void**)&nh, g_nh);
    cudaGetSymbolAddress((void**)&nl, g_nl);
    cudaGetSymbolAddress((void**)&wqTh, g_wqT_h);
    cudaGetSymbolAddress((void**)&wqTl, g_wqT_l);
    cudaGetSymbolAddress((void**)&wqkTh, g_wqkT_h);
    cudaGetSymbolAddress((void**)&wqkTl, g_wqkT_l);
    cudaGetSymbolAddress((void**)&woTh, g_woT_h);
    cudaGetSymbolAddress((void**)&woTl, g_woT_l);
    cudaGetSymbolAddress((void**)&xqh, g_xqh);
    cudaGetSymbolAddress((void**)&xql, g_xql);
    cudaGetSymbolAddress((void**)&ah, g_ah);
    cudaGetSymbolAddress((void**)&al, g_al);
    cudaGetSymbolAddress((void**)&qkv, g_qkv);
    cudaGetSymbolAddress((void**)&kp, g_kproj);
    cudaGetSymbolAddress((void**)&xattn, g_xattn);

    static bool attr_set = false;
    if (!attr_set) {
        cudaFuncSetAttribute(gemm_bf16s,
                             cudaFuncAttributeMaxDynamicSharedMemorySize, SM_TOTAL);
        cudaFuncSetAttribute(gemm_f16_1t,
                             cudaFuncAttributeMaxDynamicSharedMemorySize, SM1_TOTAL);
        attr_set = true;
    }

    // ---------------- edge path (dominant, fp16 1-term) ----------------
    {
        const int n4 = N_EDGES * DIM / 4;
        conv_f16_kernel<<<(n4 + 255) / 256, 256>>>(
            (const float4*)edge, (__half2*)e16, n4);
    }
    t_f16_kernel<<<dim3(32, 32), dim3(32, 8)>>>(w_edge, weT16, DIM);
    gemm_f16_1t<<<dim3(8, 256), 256, SM1_TOTAL>>>(e16, weT16, b_edge, y_out, DIM);
    ln_res_kernel<<<N_EDGES, 256>>>(y_out, edge, gamma_edge, beta_edge, y_out);

    // ---------------- node path (bf16 3-term, high precision) ----------------
    {
        const int n4 = N_NODES * DIM / 4;
        split_kernel<<<(n4 + 255) / 256, 256>>>(
            (const float4*)node, (__nv_bfloat162*)nh, (__nv_bfloat162*)nl, n4);
    }
    tsplit_kernel<<<dim3(32, 32), dim3(32, 8)>>>(w_query, wqTh, wqTl, DIM);
    gemm_bf16s<<<dim3(8, 8), 256, SM_TOTAL>>>(
        nh, nl, wqTh, wqTl, b_query, nullptr, xqh, xql, DIM);

    tsplit_kernel<<<dim3(32, 32), dim3(32, 8)>>>(w_to_q, wqkTh, wqkTl, DIM);
    tsplit_kernel<<<dim3(4, 32), dim3(32, 8)>>>(
        w_to_k, wqkTh + (size_t)1024 * 1024, wqkTl + (size_t)1024 * 1024, DH);
    gemm_bf16s<<<dim3(9, 8), 256, SM_TOTAL>>>(
        xqh, xql, wqkTh, wqkTl, nullptr, qkv, nullptr, nullptr, QKV_N);

    kproj_kernel<<<KPROJ, 128>>>(qkv + 1024, QKV_N, proj_k, kp);
    attn_kernel<<<N_NODES, 256>>>(qkv, QKV_N, kp, ah, al);

    tsplit_kernel<<<dim3(32, 32), dim3(32, 8)>>>(w_out, woTh, woTl, DIM);
    gemm_bf16s<<<dim3(8, 8), 256, SM_TOTAL>>>(
        ah, al, woTh, woTl, b_out, xattn, nullptr, nullptr, DIM);
    ln_res_kernel<<<N_NODES, 256>>>(xattn, node, gamma_node, beta_node, x_out);
}

// round 6
// speedup vs baseline: 4.1381x; 1.1455x over previous
#include <cuda_runtime.h>
#include <cuda_bf16.h>
#include <cuda_fp16.h>
#include <math.h>
#include <stdint.h>

#define N_NODES 1024
#define N_EDGES 32768
#define DIM     1024
#define HEADS   8
#define DH      128
#define KPROJ   256
#define QKV_N   1152   // w_to_q (1024) ++ w_to_k (128), fused GEMM

// ---------------------------------------------------------------------------
// Scratch (device globals -- no allocation allowed)
// ---------------------------------------------------------------------------
__device__ __half        g_e16[N_EDGES * DIM];                         // edge fp16
__device__ __half        g_weT16[DIM * DIM];                           // w_edge^T fp16
__device__ __nv_bfloat16 g_nh[N_NODES * DIM],  g_nl[N_NODES * DIM];    // node hi/lo
__device__ __nv_bfloat16 g_wqT_h[DIM * DIM],   g_wqT_l[DIM * DIM];     // w_query^T
__device__ __nv_bfloat16 g_wqkT_h[QKV_N * DIM], g_wqkT_l[QKV_N * DIM]; // [w_to_q|w_to_k]^T
__device__ __nv_bfloat16 g_woT_h[DIM * DIM],   g_woT_l[DIM * DIM];     // w_out^T
__device__ __nv_bfloat16 g_xqh[N_NODES * DIM], g_xql[N_NODES * DIM];   // xq hi/lo
__device__ float         g_qkv[N_NODES * QKV_N];                       // [q | kv] fp32
__device__ float         g_kproj[KPROJ * DH];
__device__ __nv_bfloat16 g_ah[N_NODES * DIM],  g_al[N_NODES * DIM];    // attn out hi/lo
__device__ float         g_xattn[N_NODES * DIM];

// ---------------------------------------------------------------------------
// Generic-ISA PTX helpers (NO arch-specific 'a' instructions)
// ---------------------------------------------------------------------------
__device__ __forceinline__ uint32_t smem_u32(const void* p) {
    uint32_t a;
    asm("{ .reg .u64 t; cvta.to.shared.u64 t, %1; cvt.u32.u64 %0, t; }"
        : "=r"(a) : "l"(p));
    return a;
}

#define CP_ASYNC16(dst, src) \
    asm volatile("cp.async.cg.shared.global [%0], [%1], 16;" :: "r"(dst), "l"(src))
#define CP_COMMIT() asm volatile("cp.async.commit_group;" ::: "memory")
#define CP_WAIT1()  asm volatile("cp.async.wait_group 1;" ::: "memory")

#define LDSM4(r, addr) \
    asm volatile("ldmatrix.sync.aligned.m8n8.x4.shared.b16 {%0,%1,%2,%3}, [%4];" \
        : "=r"((r)[0]), "=r"((r)[1]), "=r"((r)[2]), "=r"((r)[3]) : "r"(addr))
#define LDSM2(r, addr) \
    asm volatile("ldmatrix.sync.aligned.m8n8.x2.shared.b16 {%0,%1}, [%2];" \
        : "=r"((r)[0]), "=r"((r)[1]) : "r"(addr))

__device__ __forceinline__ void mma16816(float* c, const uint32_t* a, const uint32_t* b) {
    asm volatile(
        "mma.sync.aligned.m16n8k16.row.col.f32.bf16.bf16.f32 "
        "{%0,%1,%2,%3}, {%4,%5,%6,%7}, {%8,%9}, {%0,%1,%2,%3};"
        : "+f"(c[0]), "+f"(c[1]), "+f"(c[2]), "+f"(c[3])
        : "r"(a[0]), "r"(a[1]), "r"(a[2]), "r"(a[3]), "r"(b[0]), "r"(b[1]));
}

__device__ __forceinline__ void mma16816h(float* c, const uint32_t* a, const uint32_t* b) {
    asm volatile(
        "mma.sync.aligned.m16n8k16.row.col.f32.f16.f16.f32 "
        "{%0,%1,%2,%3}, {%4,%5,%6,%7}, {%8,%9}, {%0,%1,%2,%3};"
        : "+f"(c[0]), "+f"(c[1]), "+f"(c[2]), "+f"(c[3])
        : "r"(a[0]), "r"(a[1]), "r"(a[2]), "r"(a[3]), "r"(b[0]), "r"(b[1]));
}

#define GK 1024

// ===========================================================================
// EDGE GEMM (fp16, 1-term, SW128 swizzle): C = A16 * B16 (+bias) -> fp32
// BM=BN=128, BK=64 (rows = 128 B exactly), chunk' = chunk ^ (row&7) swizzle:
// all ldmatrix reads and cp.async writes are bank-conflict-free.
// 3-stage cp.async pipeline, 2 CTAs/SM.
// ===========================================================================
#define E_NTK 16                     // 1024 / 64
#define E_TILE 16384                 // 128 rows x 128 B
#define E_STAGE (2 * E_TILE)         // A + B
#define E_SM (512 + 3 * E_STAGE)     // 98816

__global__ void __launch_bounds__(256, 2) gemm_f16_sw(
    const __half* __restrict__ A16, const __half* __restrict__ BhT,
    const float* __restrict__ bias, float* __restrict__ Cf, int Nt)
{
    extern __shared__ char smem[];
    const uint32_t sb = smem_u32(smem);
    const int tid = threadIdx.x;
    const int wid = tid >> 5;
    const int lane = tid & 31;
    const int bm = blockIdx.y * 128;
    const int bn = blockIdx.x * 128;

    if (tid < 128) ((float*)smem)[tid] = bias ? bias[bn + tid] : 0.f;

    const __half* srcA = A16 + (size_t)bm * GK;
    const __half* srcB = BhT + (size_t)bn * GK;

    // 128 rows x 8 chunks(16B) per tile = 1024 chunks; 4 per thread per tile.
    auto load_stage = [&](int kt, int s) {
        const uint32_t base = sb + 512 + s * E_STAGE;
#pragma unroll
        for (int i = 0; i < 4; i++) {
            const int idx = i * 256 + tid;          // 0..1023
            const int row = idx >> 3, c = idx & 7;
            const uint32_t sw = (uint32_t)row * 128 + (uint32_t)((c ^ (row & 7)) << 4);
            CP_ASYNC16(base + sw, srcA + (size_t)row * GK + kt * 64 + c * 8);
        }
#pragma unroll
        for (int i = 0; i < 4; i++) {
            const int idx = i * 256 + tid;
            const int row = idx >> 3, c = idx & 7;
            const uint32_t sw = (uint32_t)row * 128 + (uint32_t)((c ^ (row & 7)) << 4);
            CP_ASYNC16(base + E_TILE + sw, srcB + (size_t)row * GK + kt * 64 + c * 8);
        }
    };

    load_stage(0, 0); CP_COMMIT();
    load_stage(1, 1); CP_COMMIT();

    const int wm = (wid >> 2) * 64;       // 0 or 64
    const int wn = (wid & 3) * 32;        // 0,32,64,96
    const int l7 = lane & 7;

    float acc[4][4][4];
#pragma unroll
    for (int mt = 0; mt < 4; mt++)
#pragma unroll
        for (int nt = 0; nt < 4; nt++)
#pragma unroll
            for (int j = 0; j < 4; j++) acc[mt][nt][j] = 0.f;

    for (int kt = 0; kt < E_NTK; kt++) {
        CP_WAIT1();
        __syncthreads();

        if (kt + 2 < E_NTK) { load_stage(kt + 2, (kt + 2) % 3); CP_COMMIT(); }

        const uint32_t st = sb + 512 + (kt % 3) * E_STAGE;
        const uint32_t tA = st;
        const uint32_t tB = st + E_TILE;

        // A lane row: wm + mt*16 + (lane&15); row&7 == lane&7.
        const uint32_t aRow = tA + (uint32_t)(wm + (lane & 15)) * 128;
        const uint32_t bRow = tB + (uint32_t)(wn + l7) * 128;

#pragma unroll
        for (int kh = 0; kh < 4; kh++) {
            const uint32_t aChunk = (uint32_t)(((kh << 1) | (lane >> 4)) ^ l7) << 4;
            const uint32_t bChunk = (uint32_t)(((kh << 1) | ((lane >> 3) & 1)) ^ l7) << 4;
            uint32_t aF[4][4], bH[4][2];
#pragma unroll
            for (int nt = 0; nt < 4; nt++)
                LDSM2(bH[nt], bRow + (uint32_t)(nt * 8) * 128 + bChunk);
#pragma unroll
            for (int mt = 0; mt < 4; mt++)
                LDSM4(aF[mt], aRow + (uint32_t)(mt * 16) * 128 + aChunk);
#pragma unroll
            for (int mt = 0; mt < 4; mt++)
#pragma unroll
                for (int nt = 0; nt < 4; nt++)
                    mma16816h(acc[mt][nt], aF[mt], bH[nt]);
        }
    }

    const float* bs = (const float*)smem;
#pragma unroll
    for (int mt = 0; mt < 4; mt++) {
#pragma unroll
        for (int nt = 0; nt < 4; nt++) {
            const int c = wn + nt * 8 + (lane & 3) * 2;
            const size_t r0 = (size_t)bm + wm + mt * 16 + (lane >> 2);
            *(float2*)&Cf[r0 * Nt + bn + c] =
                make_float2(acc[mt][nt][0] + bs[c], acc[mt][nt][1] + bs[c + 1]);
            *(float2*)&Cf[(r0 + 8) * Nt + bn + c] =
                make_float2(acc[mt][nt][2] + bs[c], acc[mt][nt][3] + bs[c + 1]);
        }
    }
}

// ===========================================================================
// NODE GEMM (bf16, 3-term, 80B-pad layout -- unchanged, proven)
// ===========================================================================
#define NT_K 32
#define ROWB 80
#define TILE_BYTES (128 * ROWB)
#define SM_HDR 512
#define STAGE_BYTES (4 * TILE_BYTES)
#define SM_TOTAL (SM_HDR + 3 * STAGE_BYTES)

__global__ void __launch_bounds__(256, 1) gemm_bf16s(
    const __nv_bfloat16* __restrict__ Ah, const __nv_bfloat16* __restrict__ Al,
    const __nv_bfloat16* __restrict__ BhT, const __nv_bfloat16* __restrict__ BlT,
    const float* __restrict__ bias,
    float* __restrict__ Cf, __nv_bfloat16* __restrict__ Ch, __nv_bfloat16* __restrict__ Cl,
    int Nt)
{
    extern __shared__ char smem[];
    const uint32_t sb = smem_u32(smem);
    const int tid = threadIdx.x;
    const int wid = tid >> 5;
    const int lane = tid & 31;
    const int bm = blockIdx.y * 128;
    const int bn = blockIdx.x * 128;

    if (tid < 128) ((float*)smem)[tid] = bias ? bias[bn + tid] : 0.f;

    const __nv_bfloat16* srcs[4] = {
        Ah + (size_t)bm * GK, Al + (size_t)bm * GK,
        BhT + (size_t)bn * GK, BlT + (size_t)bn * GK };

    auto load_stage = [&](int kt, int s) {
        const uint32_t base = sb + SM_HDR + s * STAGE_BYTES;
#pragma unroll
        for (int t = 0; t < 4; t++) {
#pragma unroll
            for (int i = 0; i < 2; i++) {
                const int idx = i * 256 + tid;
                const int row = idx >> 2, seg = idx & 3;
                const void* g = srcs[t] + (size_t)row * GK + kt * 32 + seg * 8;
                CP_ASYNC16(base + t * TILE_BYTES + row * ROWB + seg * 16, g);
            }
        }
    };

    load_stage(0, 0); CP_COMMIT();
    load_stage(1, 1); CP_COMMIT();

    const int wm = (wid >> 2) * 64;
    const int wn = (wid & 3) * 32;
    const uint32_t aoff = (uint32_t)(lane & 15) * ROWB + (uint32_t)(lane >> 4) * 16;
    const int l15 = lane & 15;
    const uint32_t boff = (uint32_t)(l15 & 7) * ROWB + (uint32_t)(l15 >> 3) * 16;

    float acc[4][4][4];
#pragma unroll
    for (int mt = 0; mt < 4; mt++)
#pragma unroll
        for (int nt = 0; nt < 4; nt++)
#pragma unroll
            for (int j = 0; j < 4; j++) acc[mt][nt][j] = 0.f;

    for (int kt = 0; kt < NT_K; kt++) {
        CP_WAIT1();
        __syncthreads();

        if (kt + 2 < NT_K) { load_stage(kt + 2, (kt + 2) % 3); CP_COMMIT(); }

        const uint32_t st = sb + SM_HDR + (kt % 3) * STAGE_BYTES;
        const uint32_t tAh = st;
        const uint32_t tAl = st + TILE_BYTES;
        const uint32_t tBh = st + 2 * TILE_BYTES;
        const uint32_t tBl = st + 3 * TILE_BYTES;

#pragma unroll
        for (int kh = 0; kh < 2; kh++) {
            const uint32_t kb = kh * 32;
            uint32_t aF[4][4], bH[4][2], bL[4][2];
#pragma unroll
            for (int nt = 0; nt < 4; nt++) {
                const uint32_t bo = (uint32_t)(wn + nt * 8) * ROWB + kb + boff;
                LDSM2(bH[nt], tBh + bo);
                LDSM2(bL[nt], tBl + bo);
            }
#pragma unroll
            for (int mt = 0; mt < 4; mt++)
                LDSM4(aF[mt], tAh + (uint32_t)(wm + mt * 16) * ROWB + kb + aoff);
#pragma unroll
            for (int mt = 0; mt < 4; mt++)
#pragma unroll
                for (int nt = 0; nt < 4; nt++) {
                    mma16816(acc[mt][nt], aF[mt], bH[nt]);
                    mma16816(acc[mt][nt], aF[mt], bL[nt]);
                }
#pragma unroll
            for (int mt = 0; mt < 4; mt++)
                LDSM4(aF[mt], tAl + (uint32_t)(wm + mt * 16) * ROWB + kb + aoff);
#pragma unroll
            for (int mt = 0; mt < 4; mt++)
#pragma unroll
                for (int nt = 0; nt < 4; nt++)
                    mma16816(acc[mt][nt], aF[mt], bH[nt]);
        }
    }

    const float* bs = (const float*)smem;
#pragma unroll
    for (int mt = 0; mt < 4; mt++) {
#pragma unroll
        for (int nt = 0; nt < 4; nt++) {
            const int c = wn + nt * 8 + (lane & 3) * 2;
            const size_t r0 = (size_t)bm + wm + mt * 16 + (lane >> 2);
            const float v0 = acc[mt][nt][0] + bs[c];
            const float v1 = acc[mt][nt][1] + bs[c + 1];
            const float v2 = acc[mt][nt][2] + bs[c];
            const float v3 = acc[mt][nt][3] + bs[c + 1];
            if (Cf) {
                *(float2*)&Cf[r0 * Nt + bn + c]       = make_float2(v0, v1);
                *(float2*)&Cf[(r0 + 8) * Nt + bn + c] = make_float2(v2, v3);
            }
            if (Ch) {
                __nv_bfloat16 h0 = __float2bfloat16(v0), h1 = __float2bfloat16(v1);
                __nv_bfloat16 h2 = __float2bfloat16(v2), h3 = __float2bfloat16(v3);
                *(__nv_bfloat162*)&Ch[r0 * Nt + bn + c] = __halves2bfloat162(h0, h1);
                *(__nv_bfloat162*)&Ch[(r0 + 8) * Nt + bn + c] = __halves2bfloat162(h2, h3);
                *(__nv_bfloat162*)&Cl[r0 * Nt + bn + c] = __halves2bfloat162(
                    __float2bfloat16(v0 - __bfloat162float(h0)),
                    __float2bfloat16(v1 - __bfloat162float(h1)));
                *(__nv_bfloat162*)&Cl[(r0 + 8) * Nt + bn + c] = __halves2bfloat162(
                    __float2bfloat16(v2 - __bfloat162float(h2)),
                    __float2bfloat16(v3 - __bfloat162float(h3)));
            }
        }
    }
}

// ---------------------------------------------------------------------------
// fp32 -> fp16 convert (elementwise)
// ---------------------------------------------------------------------------
__global__ void __launch_bounds__(256) conv_f16_kernel(
    const float4* __restrict__ in, __half2* __restrict__ oh, int n4)
{
    int i = blockIdx.x * 256 + threadIdx.x;
    if (i >= n4) return;
    float4 v = in[i];
    oh[2 * i + 0] = __halves2half2(__float2half(v.x), __float2half(v.y));
    oh[2 * i + 1] = __halves2half2(__float2half(v.z), __float2half(v.w));
}

// ---------------------------------------------------------------------------
// w[K,N] fp32 -> out[N,1024] fp16 (transpose); K == 1024.
// ---------------------------------------------------------------------------
__global__ void __launch_bounds__(256) t_f16_kernel(
    const float* __restrict__ w, __half* __restrict__ oh, int N)
{
    __shared__ float t[32][33];
    const int n0 = blockIdx.x * 32, k0 = blockIdx.y * 32;
    const int tx = threadIdx.x, ty = threadIdx.y;
#pragma unroll
    for (int i = 0; i < 4; i++)
        t[ty + i * 8][tx] = w[(size_t)(k0 + ty + i * 8) * N + n0 + tx];
    __syncthreads();
#pragma unroll
    for (int i = 0; i < 4; i++) {
        const int n = n0 + ty + i * 8, k = k0 + tx;
        oh[(size_t)n * 1024 + k] = __float2half(t[tx][ty + i * 8]);
    }
}

// ---------------------------------------------------------------------------
// fp32 -> bf16 hi/lo split (elementwise)  [node path]
// ---------------------------------------------------------------------------
__global__ void __launch_bounds__(256) split_kernel(
    const float4* __restrict__ in, __nv_bfloat162* __restrict__ oh,
    __nv_bfloat162* __restrict__ ol, int n4)
{
    int i = blockIdx.x * 256 + threadIdx.x;
    if (i >= n4) return;
    float4 v = in[i];
    __nv_bfloat16 h0 = __float2bfloat16(v.x), h1 = __float2bfloat16(v.y);
    __nv_bfloat16 h2 = __float2bfloat16(v.z), h3 = __float2bfloat16(v.w);
    oh[2 * i + 0] = __halves2bfloat162(h0, h1);
    oh[2 * i + 1] = __halves2bfloat162(h2, h3);
    ol[2 * i + 0] = __halves2bfloat162(
        __float2bfloat16(v.x - __bfloat162float(h0)),
        __float2bfloat16(v.y - __bfloat162float(h1)));
    ol[2 * i + 1] = __halves2bfloat162(
        __float2bfloat16(v.z - __bfloat162float(h2)),
        __float2bfloat16(v.w - __bfloat162float(h3)));
}

// ---------------------------------------------------------------------------
// w[K,N] fp32 -> out[N,1024] bf16 hi/lo (transpose + split); K == 1024.
// ---------------------------------------------------------------------------
__global__ void __launch_bounds__(256) tsplit_kernel(
    const float* __restrict__ w, __nv_bfloat16* __restrict__ oh,
    __nv_bfloat16* __restrict__ ol, int N)
{
    __shared__ float t[32][33];
    const int n0 = blockIdx.x * 32, k0 = blockIdx.y * 32;
    const int tx = threadIdx.x, ty = threadIdx.y;
#pragma unroll
    for (int i = 0; i < 4; i++)
        t[ty + i * 8][tx] = w[(size_t)(k0 + ty + i * 8) * N + n0 + tx];
    __syncthreads();
#pragma unroll
    for (int i = 0; i < 4; i++) {
        const int n = n0 + ty + i * 8, k = k0 + tx;
        const float v = t[tx][ty + i * 8];
        __nv_bfloat16 h = __float2bfloat16(v);
        oh[(size_t)n * 1024 + k] = h;
        ol[(size_t)n * 1024 + k] = __float2bfloat16(v - __bfloat162float(h));
    }
}

// ---------------------------------------------------------------------------
// kproj[k,d] = sum_n proj_k[n,k] * kv[n,d]  (kv row stride kvs)
// ---------------------------------------------------------------------------
__global__ void __launch_bounds__(128) kproj_kernel(
    const float* __restrict__ kv, int kvs, const float* __restrict__ pk,
    float* __restrict__ kp)
{
    const int k = blockIdx.x;
    const int d = threadIdx.x;
    float s0 = 0.f, s1 = 0.f, s2 = 0.f, s3 = 0.f;
#pragma unroll 4
    for (int n = 0; n < N_NODES; n += 4) {
        s0 += pk[(size_t)(n + 0) * KPROJ + k] * kv[(size_t)(n + 0) * kvs + d];
        s1 += pk[(size_t)(n + 1) * KPROJ + k] * kv[(size_t)(n + 1) * kvs + d];
        s2 += pk[(size_t)(n + 2) * KPROJ + k] * kv[(size_t)(n + 2) * kvs + d];
        s3 += pk[(size_t)(n + 3) * KPROJ + k] * kv[(size_t)(n + 3) * kvs + d];
    }
    kp[(size_t)k * DH + d] = (s0 + s1) + (s2 + s3);
}

// ---------------------------------------------------------------------------
// Fused attention (per node, 8 warps = 8 heads) -> bf16 hi/lo output
// ---------------------------------------------------------------------------
__global__ void __launch_bounds__(256) attn_kernel(
    const float* __restrict__ q, int qs, const float* __restrict__ kproj,
    __nv_bfloat16* __restrict__ oh, __nv_bfloat16* __restrict__ ol)
{
    __shared__ float q_s[DIM];
    __shared__ float prob[HEADS][KPROJ];

    const int n = blockIdx.x;
    for (int i = threadIdx.x; i < DIM; i += 256)
        q_s[i] = q[(size_t)n * qs + i];
    __syncthreads();

    const int w = threadIdx.x >> 5;
    const int l = threadIdx.x & 31;
    const float4* qh4 = (const float4*)(q_s + w * DH);

    float d8[8];
#pragma unroll
    for (int j = 0; j < 8; j++) {
        const int k = j * 32 + l;
        const float4* kr4 = (const float4*)(kproj + (size_t)k * DH);
        float s = 0.f;
#pragma unroll
        for (int d4 = 0; d4 < DH / 4; d4++) {
            float4 qq = qh4[d4], kk = kr4[d4];
            s += qq.x * kk.x + qq.y * kk.y + qq.z * kk.z + qq.w * kk.w;
        }
        d8[j] = s * 0.088388347648318447f;
    }
    float mx = d8[0];
#pragma unroll
    for (int j = 1; j < 8; j++) mx = fmaxf(mx, d8[j]);
#pragma unroll
    for (int o = 16; o; o >>= 1) mx = fmaxf(mx, __shfl_xor_sync(0xFFFFFFFFu, mx, o));
    float sum = 0.f;
#pragma unroll
    for (int j = 0; j < 8; j++) { d8[j] = expf(d8[j] - mx); sum += d8[j]; }
#pragma unroll
    for (int o = 16; o; o >>= 1) sum += __shfl_xor_sync(0xFFFFFFFFu, sum, o);
    const float inv = 1.f / sum;
#pragma unroll
    for (int j = 0; j < 8; j++) prob[w][j * 32 + l] = d8[j] * inv;
    __syncwarp();

    float o0 = 0.f, o1 = 0.f, o2 = 0.f, o3 = 0.f;
    for (int k = 0; k < KPROJ; k++) {
        const float p = prob[w][k];
        const float* kr = kproj + (size_t)k * DH + l;
        o0 += p * kr[0];  o1 += p * kr[32];
        o2 += p * kr[64]; o3 += p * kr[96];
    }
    const size_t ob = (size_t)n * DIM + w * DH + l;
    float ov[4] = {o0, o1, o2, o3};
#pragma unroll
    for (int j = 0; j < 4; j++) {
        __nv_bfloat16 h = __float2bfloat16(ov[j]);
        oh[ob + 32 * j] = h;
        ol[ob + 32 * j] = __float2bfloat16(ov[j] - __bfloat162float(h));
    }
}

// ---------------------------------------------------------------------------
// LayerNorm + residual (in-place safe)
// ---------------------------------------------------------------------------
__global__ void __launch_bounds__(256) ln_res_kernel(
    const float* __restrict__ src, const float* __restrict__ resid,
    const float* __restrict__ gamma, const float* __restrict__ beta,
    float* __restrict__ dst)
{
    const int row = blockIdx.x;
    const int t = threadIdx.x;
    const float4 v = *(const float4*)&src[(size_t)row * DIM + t * 4];

    float sum = v.x + v.y + v.z + v.w;
    float sq = v.x * v.x + v.y * v.y + v.z * v.z + v.w * v.w;
#pragma unroll
    for (int o = 16; o; o >>= 1) {
        sum += __shfl_xor_sync(0xFFFFFFFFu, sum, o);
        sq  += __shfl_xor_sync(0xFFFFFFFFu, sq, o);
    }
    __shared__ float ssum[8], ssq[8];
    const int w = t >> 5, l = t & 31;
    if (l == 0) { ssum[w] = sum; ssq[w] = sq; }
    __syncthreads();
    sum = 0.f; sq = 0.f;
#pragma unroll
    for (int i = 0; i < 8; i++) { sum += ssum[i]; sq += ssq[i]; }

    const float mu = sum * (1.f / DIM);
    const float var = sq * (1.f / DIM) - mu * mu;
    const float rstd = rsqrtf(var + 1e-5f);

    const float4 g = *(const float4*)&gamma[t * 4];
    const float4 b = *(const float4*)&beta[t * 4];
    const float4 rr = *(const float4*)&resid[(size_t)row * DIM + t * 4];
    float4 o;
    o.x = (v.x - mu) * rstd * g.x + b.x + rr.x;
    o.y = (v.y - mu) * rstd * g.y + b.y + rr.y;
    o.z = (v.z - mu) * rstd * g.z + b.z + rr.z;
    o.w = (v.w - mu) * rstd * g.w + b.w + rr.w;
    *(float4*)&dst[(size_t)row * DIM + t * 4] = o;
}

// ---------------------------------------------------------------------------
// kernel_launch
// ---------------------------------------------------------------------------
extern "C" void kernel_launch(void* const* d_in, const int* in_sizes, int n_in,
                              void* d_out, int out_size)
{
    const float* node       = (const float*)d_in[0];
    const float* edge       = (const float*)d_in[1];
    const float* w_query    = (const float*)d_in[2];
    const float* b_query    = (const float*)d_in[3];
    const float* w_edge     = (const float*)d_in[4];
    const float* b_edge     = (const float*)d_in[5];
    const float* w_to_q     = (const float*)d_in[6];
    const float* w_to_k     = (const float*)d_in[7];
    const float* proj_k     = (const float*)d_in[8];
    const float* w_out      = (const float*)d_in[9];
    const float* b_out      = (const float*)d_in[10];
    const float* gamma_node = (const float*)d_in[11];
    const float* beta_node  = (const float*)d_in[12];
    const float* gamma_edge = (const float*)d_in[13];
    const float* beta_edge  = (const float*)d_in[14];

    float* x_out = (float*)d_out;
    float* y_out = (float*)d_out + (size_t)N_NODES * DIM;

    __half *e16, *weT16;
    __nv_bfloat16 *nh, *nl, *wqTh, *wqTl;
    __nv_bfloat16 *wqkTh, *wqkTl, *woTh, *woTl, *xqh, *xql, *ah, *al;
    float *qkv, *kp, *xattn;
    cudaGetSymbolAddress((void**)&e16, g_e16);
    cudaGetSymbolAddress((void**)&weT16, g_weT16);
    cudaGetSymbolAddress((void**)&nh, g_nh);
    cudaGetSymbolAddress((void**)&nl, g_nl);
    cudaGetSymbolAddress((void**)&wqTh, g_wqT_h);
    cudaGetSymbolAddress((void**)&wqTl, g_wqT_l);
    cudaGetSymbolAddress((void**)&wqkTh, g_wqkT_h);
    cudaGetSymbolAddress((void**)&wqkTl, g_wqkT_l);
    cudaGetSymbolAddress((void**)&woTh, g_woT_h);
    cudaGetSymbolAddress((void**)&woTl, g_woT_l);
    cudaGetSymbolAddress((void**)&xqh, g_xqh);
    cudaGetSymbolAddress((void**)&xql, g_xql);
    cudaGetSymbolAddress((void**)&ah, g_ah);
    cudaGetSymbolAddress((void**)&al, g_al);
    cudaGetSymbolAddress((void**)&qkv, g_qkv);
    cudaGetSymbolAddress((void**)&kp, g_kproj);
    cudaGetSymbolAddress((void**)&xattn, g_xattn);

    static bool attr_set = false;
    if (!attr_set) {
        cudaFuncSetAttribute(gemm_bf16s,
                             cudaFuncAttributeMaxDynamicSharedMemorySize, SM_TOTAL);
        cudaFuncSetAttribute(gemm_f16_sw,
                             cudaFuncAttributeMaxDynamicSharedMemorySize, E_SM);
        attr_set = true;
    }

    // launch order puts gemm_f16_sw at index 3 (the slot ncu has been
    // profiling) so the next profile captures the GEMM, not ln_res.
    {
        const int n4 = N_EDGES * DIM / 4;
        conv_f16_kernel<<<(n4 + 255) / 256, 256>>>(
            (const float4*)edge, (__half2*)e16, n4);
    }
    t_f16_kernel<<<dim3(32, 32), dim3(32, 8)>>>(w_edge, weT16, DIM);
    {
        const int n4 = N_NODES * DIM / 4;
        split_kernel<<<(n4 + 255) / 256, 256>>>(
            (const float4*)node, (__nv_bfloat162*)nh, (__nv_bfloat162*)nl, n4);
    }
    gemm_f16_sw<<<dim3(8, 256), 256, E_SM>>>(e16, weT16, b_edge, y_out, DIM);
    ln_res_kernel<<<N_EDGES, 256>>>(y_out, edge, gamma_edge, beta_edge, y_out);

    // ---------------- node path (bf16 3-term, high precision) ----------------
    tsplit_kernel<<<dim3(32, 32), dim3(32, 8)>>>(w_query, wqTh, wqTl, DIM);
    gemm_bf16s<<<dim3(8, 8), 256, SM_TOTAL>>>(
        nh, nl, wqTh, wqTl, b_query, nullptr, xqh, xql, DIM);

    tsplit_kernel<<<dim3(32, 32), dim3(32, 8)>>>(w_to_q, wqkTh, wqkTl, DIM);
    tsplit_kernel<<<dim3(4, 32), dim3(32, 8)>>>(
        w_to_k, wqkTh + (size_t)1024 * 1024, wqkTl + (size_t)1024 * 1024, DH);
    gemm_bf16s<<<dim3(9, 8), 256, SM_TOTAL>>>(
        xqh, xql, wqkTh, wqkTl, nullptr, qkv, nullptr, nullptr, QKV_N);

    kproj_kernel<<<KPROJ, 128>>>(qkv + 1024, QKV_N, proj_k, kp);
    attn_kernel<<<N_NODES, 256>>>(qkv, QKV_N, kp, ah, al);

    tsplit_kernel<<<dim3(32, 32), dim3(32, 8)>>>(w_out, woTh, woTl, DIM);
    gemm_bf16s<<<dim3(8, 8), 256, SM_TOTAL>>>(
        ah, al, woTh, woTl, b_out, xattn, nullptr, nullptr, DIM);
    ln_res_kernel<<<N_NODES, 256>>>(xattn, node, gamma_node, beta_node, x_out);
}

// round 7
// speedup vs baseline: 4.6160x; 1.1155x over previous
#include <cuda_runtime.h>
#include <cuda_bf16.h>
#include <cuda_fp16.h>
#include <math.h>
#include <stdint.h>

#define N_NODES 1024
#define N_EDGES 32768
#define DIM     1024
#define HEADS   8
#define DH      128
#define KPROJ   256
#define QKV_N   1152   // w_to_q (1024) ++ w_to_k (128), fused GEMM

// ---------------------------------------------------------------------------
// Scratch (device globals -- no allocation allowed)
// ---------------------------------------------------------------------------
__device__ __half        g_e16[N_EDGES * DIM];                         // edge fp16
__device__ __half        g_weT16[DIM * DIM];                           // w_edge^T fp16
__device__ __nv_bfloat16 g_nh[N_NODES * DIM],  g_nl[N_NODES * DIM];    // node hi/lo
__device__ __nv_bfloat16 g_wqT_h[DIM * DIM],   g_wqT_l[DIM * DIM];     // w_query^T
__device__ __nv_bfloat16 g_wqkT_h[QKV_N * DIM], g_wqkT_l[QKV_N * DIM]; // [w_to_q|w_to_k]^T
__device__ __nv_bfloat16 g_woT_h[DIM * DIM],   g_woT_l[DIM * DIM];     // w_out^T
__device__ __nv_bfloat16 g_xqh[N_NODES * DIM], g_xql[N_NODES * DIM];   // xq hi/lo
__device__ float         g_qkv[N_NODES * QKV_N];                       // [q | kv] fp32
__device__ float         g_kproj[KPROJ * DH];
__device__ __nv_bfloat16 g_ah[N_NODES * DIM],  g_al[N_NODES * DIM];    // attn out hi/lo
__device__ float         g_xattn[N_NODES * DIM];

// ---------------------------------------------------------------------------
// Generic-ISA PTX helpers
// ---------------------------------------------------------------------------
__device__ __forceinline__ uint32_t smem_u32(const void* p) {
    uint32_t a;
    asm("{ .reg .u64 t; cvta.to.shared.u64 t, %1; cvt.u32.u64 %0, t; }"
        : "=r"(a) : "l"(p));
    return a;
}

#define CP_ASYNC16(dst, src) \
    asm volatile("cp.async.cg.shared.global [%0], [%1], 16;" :: "r"(dst), "l"(src))
#define CP_COMMIT() asm volatile("cp.async.commit_group;" ::: "memory")
#define CP_WAIT1()  asm volatile("cp.async.wait_group 1;" ::: "memory")

#define LDSM4(r, addr) \
    asm volatile("ldmatrix.sync.aligned.m8n8.x4.shared.b16 {%0,%1,%2,%3}, [%4];" \
        : "=r"((r)[0]), "=r"((r)[1]), "=r"((r)[2]), "=r"((r)[3]) : "r"(addr))
#define LDSM2(r, addr) \
    asm volatile("ldmatrix.sync.aligned.m8n8.x2.shared.b16 {%0,%1}, [%2];" \
        : "=r"((r)[0]), "=r"((r)[1]) : "r"(addr))

__device__ __forceinline__ void mma16816(float* c, const uint32_t* a, const uint32_t* b) {
    asm volatile(
        "mma.sync.aligned.m16n8k16.row.col.f32.bf16.bf16.f32 "
        "{%0,%1,%2,%3}, {%4,%5,%6,%7}, {%8,%9}, {%0,%1,%2,%3};"
        : "+f"(c[0]), "+f"(c[1]), "+f"(c[2]), "+f"(c[3])
        : "r"(a[0]), "r"(a[1]), "r"(a[2]), "r"(a[3]), "r"(b[0]), "r"(b[1]));
}

__device__ __forceinline__ void mma16816h(float* c, const uint32_t* a, const uint32_t* b) {
    asm volatile(
        "mma.sync.aligned.m16n8k16.row.col.f32.f16.f16.f32 "
        "{%0,%1,%2,%3}, {%4,%5,%6,%7}, {%8,%9}, {%0,%1,%2,%3};"
        : "+f"(c[0]), "+f"(c[1]), "+f"(c[2]), "+f"(c[3])
        : "r"(a[0]), "r"(a[1]), "r"(a[2]), "r"(a[3]), "r"(b[0]), "r"(b[1]));
}

#define GK 1024

// ===========================================================================
// EDGE GEMM (fp16, 1-term, SW128 swizzle) -- unchanged from R6 (proven 171us)
// ===========================================================================
#define E_NTK 16
#define E_TILE 16384
#define E_STAGE (2 * E_TILE)
#define E_SM (512 + 3 * E_STAGE)

__global__ void __launch_bounds__(256, 2) gemm_f16_sw(
    const __half* __restrict__ A16, const __half* __restrict__ BhT,
    const float* __restrict__ bias, float* __restrict__ Cf, int Nt)
{
    extern __shared__ char smem[];
    const uint32_t sb = smem_u32(smem);
    const int tid = threadIdx.x;
    const int wid = tid >> 5;
    const int lane = tid & 31;
    const int bm = blockIdx.y * 128;
    const int bn = blockIdx.x * 128;

    if (tid < 128) ((float*)smem)[tid] = bias ? bias[bn + tid] : 0.f;

    const __half* srcA = A16 + (size_t)bm * GK;
    const __half* srcB = BhT + (size_t)bn * GK;

    auto load_stage = [&](int kt, int s) {
        const uint32_t base = sb + 512 + s * E_STAGE;
#pragma unroll
        for (int i = 0; i < 4; i++) {
            const int idx = i * 256 + tid;
            const int row = idx >> 3, c = idx & 7;
            const uint32_t sw = (uint32_t)row * 128 + (uint32_t)((c ^ (row & 7)) << 4);
            CP_ASYNC16(base + sw, srcA + (size_t)row * GK + kt * 64 + c * 8);
        }
#pragma unroll
        for (int i = 0; i < 4; i++) {
            const int idx = i * 256 + tid;
            const int row = idx >> 3, c = idx & 7;
            const uint32_t sw = (uint32_t)row * 128 + (uint32_t)((c ^ (row & 7)) << 4);
            CP_ASYNC16(base + E_TILE + sw, srcB + (size_t)row * GK + kt * 64 + c * 8);
        }
    };

    load_stage(0, 0); CP_COMMIT();
    load_stage(1, 1); CP_COMMIT();

    const int wm = (wid >> 2) * 64;
    const int wn = (wid & 3) * 32;
    const int l7 = lane & 7;

    float acc[4][4][4];
#pragma unroll
    for (int mt = 0; mt < 4; mt++)
#pragma unroll
        for (int nt = 0; nt < 4; nt++)
#pragma unroll
            for (int j = 0; j < 4; j++) acc[mt][nt][j] = 0.f;

    for (int kt = 0; kt < E_NTK; kt++) {
        CP_WAIT1();
        __syncthreads();

        if (kt + 2 < E_NTK) { load_stage(kt + 2, (kt + 2) % 3); CP_COMMIT(); }

        const uint32_t st = sb + 512 + (kt % 3) * E_STAGE;
        const uint32_t aRow = st + (uint32_t)(wm + (lane & 15)) * 128;
        const uint32_t bRow = st + E_TILE + (uint32_t)(wn + l7) * 128;

#pragma unroll
        for (int kh = 0; kh < 4; kh++) {
            const uint32_t aChunk = (uint32_t)(((kh << 1) | (lane >> 4)) ^ l7) << 4;
            const uint32_t bChunk = (uint32_t)(((kh << 1) | ((lane >> 3) & 1)) ^ l7) << 4;
            uint32_t aF[4][4], bH[4][2];
#pragma unroll
            for (int nt = 0; nt < 4; nt++)
                LDSM2(bH[nt], bRow + (uint32_t)(nt * 8) * 128 + bChunk);
#pragma unroll
            for (int mt = 0; mt < 4; mt++)
                LDSM4(aF[mt], aRow + (uint32_t)(mt * 16) * 128 + aChunk);
#pragma unroll
            for (int mt = 0; mt < 4; mt++)
#pragma unroll
                for (int nt = 0; nt < 4; nt++)
                    mma16816h(acc[mt][nt], aF[mt], bH[nt]);
        }
    }

    const float* bs = (const float*)smem;
#pragma unroll
    for (int mt = 0; mt < 4; mt++) {
#pragma unroll
        for (int nt = 0; nt < 4; nt++) {
            const int c = wn + nt * 8 + (lane & 3) * 2;
            const size_t r0 = (size_t)bm + wm + mt * 16 + (lane >> 2);
            *(float2*)&Cf[r0 * Nt + bn + c] =
                make_float2(acc[mt][nt][0] + bs[c], acc[mt][nt][1] + bs[c + 1]);
            *(float2*)&Cf[(r0 + 8) * Nt + bn + c] =
                make_float2(acc[mt][nt][2] + bs[c], acc[mt][nt][3] + bs[c + 1]);
        }
    }
}

// ===========================================================================
// NODE GEMM (bf16 3-term, SW128 swizzle): BM=64, BN=128, BK=64.
// grid (N/128, M/64) -> 128-144 CTAs (full-chip wave). 8 warps, warp 32x32.
// Stage: Ah(8K) Al(8K) Bh(16K) Bl(16K) = 48K; 3 stages.
// ===========================================================================
#define N_NTK 16
#define N_ATILE 8192                  // 64 rows x 128 B
#define N_BTILE 16384                 // 128 rows x 128 B
#define N_STAGE (2 * N_ATILE + 2 * N_BTILE)   // 49152
#define N_SM (512 + 3 * N_STAGE)              // 147968

__global__ void __launch_bounds__(256, 1) gemm_bf16_sw(
    const __nv_bfloat16* __restrict__ Ah, const __nv_bfloat16* __restrict__ Al,
    const __nv_bfloat16* __restrict__ BhT, const __nv_bfloat16* __restrict__ BlT,
    const float* __restrict__ bias,
    float* __restrict__ Cf, __nv_bfloat16* __restrict__ Ch, __nv_bfloat16* __restrict__ Cl,
    int Nt)
{
    extern __shared__ char smem[];
    const uint32_t sb = smem_u32(smem);
    const int tid = threadIdx.x;
    const int wid = tid >> 5;
    const int lane = tid & 31;
    const int bm = blockIdx.y * 64;
    const int bn = blockIdx.x * 128;

    if (tid < 128) ((float*)smem)[tid] = bias ? bias[bn + tid] : 0.f;

    const __nv_bfloat16* sAh = Ah + (size_t)bm * GK;
    const __nv_bfloat16* sAl = Al + (size_t)bm * GK;
    const __nv_bfloat16* sBh = BhT + (size_t)bn * GK;
    const __nv_bfloat16* sBl = BlT + (size_t)bn * GK;

    auto load_stage = [&](int kt, int s) {
        const uint32_t base = sb + 512 + s * N_STAGE;
        // Ah, Al: 64 rows x 8 chunks = 512 chunks each -> 2 iters of 256
#pragma unroll
        for (int i = 0; i < 2; i++) {
            const int idx = i * 256 + tid;
            const int row = idx >> 3, c = idx & 7;
            const uint32_t sw = (uint32_t)row * 128 + (uint32_t)((c ^ (row & 7)) << 4);
            CP_ASYNC16(base + sw, sAh + (size_t)row * GK + kt * 64 + c * 8);
            CP_ASYNC16(base + N_ATILE + sw, sAl + (size_t)row * GK + kt * 64 + c * 8);
        }
        // Bh, Bl: 128 rows x 8 chunks = 1024 chunks each -> 4 iters
#pragma unroll
        for (int i = 0; i < 4; i++) {
            const int idx = i * 256 + tid;
            const int row = idx >> 3, c = idx & 7;
            const uint32_t sw = (uint32_t)row * 128 + (uint32_t)((c ^ (row & 7)) << 4);
            CP_ASYNC16(base + 2 * N_ATILE + sw, sBh + (size_t)row * GK + kt * 64 + c * 8);
            CP_ASYNC16(base + 2 * N_ATILE + N_BTILE + sw,
                       sBl + (size_t)row * GK + kt * 64 + c * 8);
        }
    };

    load_stage(0, 0); CP_COMMIT();
    load_stage(1, 1); CP_COMMIT();

    const int wm = (wid >> 2) * 32;       // 0 or 32
    const int wn = (wid & 3) * 32;        // 0,32,64,96
    const int l7 = lane & 7;

    float acc[2][4][4];
#pragma unroll
    for (int mt = 0; mt < 2; mt++)
#pragma unroll
        for (int nt = 0; nt < 4; nt++)
#pragma unroll
            for (int j = 0; j < 4; j++) acc[mt][nt][j] = 0.f;

    for (int kt = 0; kt < N_NTK; kt++) {
        CP_WAIT1();
        __syncthreads();

        if (kt + 2 < N_NTK) { load_stage(kt + 2, (kt + 2) % 3); CP_COMMIT(); }

        const uint32_t st = sb + 512 + (kt % 3) * N_STAGE;
        const uint32_t ahRow = st + (uint32_t)(wm + (lane & 15)) * 128;
        const uint32_t alRow = ahRow + N_ATILE;
        const uint32_t bhRow = st + 2 * N_ATILE + (uint32_t)(wn + l7) * 128;
        const uint32_t blRow = bhRow + N_BTILE;

#pragma unroll
        for (int kh = 0; kh < 4; kh++) {
            const uint32_t aChunk = (uint32_t)(((kh << 1) | (lane >> 4)) ^ l7) << 4;
            const uint32_t bChunk = (uint32_t)(((kh << 1) | ((lane >> 3) & 1)) ^ l7) << 4;
            uint32_t aH[2][4], aL[2][4], bH[4][2], bL[4][2];
#pragma unroll
            for (int nt = 0; nt < 4; nt++) {
                LDSM2(bH[nt], bhRow + (uint32_t)(nt * 8) * 128 + bChunk);
                LDSM2(bL[nt], blRow + (uint32_t)(nt * 8) * 128 + bChunk);
            }
#pragma unroll
            for (int mt = 0; mt < 2; mt++) {
                LDSM4(aH[mt], ahRow + (uint32_t)(mt * 16) * 128 + aChunk);
                LDSM4(aL[mt], alRow + (uint32_t)(mt * 16) * 128 + aChunk);
            }
#pragma unroll
            for (int mt = 0; mt < 2; mt++)
#pragma unroll
                for (int nt = 0; nt < 4; nt++) {
                    mma16816(acc[mt][nt], aH[mt], bH[nt]);
                    mma16816(acc[mt][nt], aH[mt], bL[nt]);
                    mma16816(acc[mt][nt], aL[mt], bH[nt]);
                }
        }
    }

    const float* bs = (const float*)smem;
#pragma unroll
    for (int mt = 0; mt < 2; mt++) {
#pragma unroll
        for (int nt = 0; nt < 4; nt++) {
            const int c = wn + nt * 8 + (lane & 3) * 2;
            const size_t r0 = (size_t)bm + wm + mt * 16 + (lane >> 2);
            const float v0 = acc[mt][nt][0] + bs[c];
            const float v1 = acc[mt][nt][1] + bs[c + 1];
            const float v2 = acc[mt][nt][2] + bs[c];
            const float v3 = acc[mt][nt][3] + bs[c + 1];
            if (Cf) {
                *(float2*)&Cf[r0 * Nt + bn + c]       = make_float2(v0, v1);
                *(float2*)&Cf[(r0 + 8) * Nt + bn + c] = make_float2(v2, v3);
            }
            if (Ch) {
                __nv_bfloat16 h0 = __float2bfloat16(v0), h1 = __float2bfloat16(v1);
                __nv_bfloat16 h2 = __float2bfloat16(v2), h3 = __float2bfloat16(v3);
                *(__nv_bfloat162*)&Ch[r0 * Nt + bn + c] = __halves2bfloat162(h0, h1);
                *(__nv_bfloat162*)&Ch[(r0 + 8) * Nt + bn + c] = __halves2bfloat162(h2, h3);
                *(__nv_bfloat162*)&Cl[r0 * Nt + bn + c] = __halves2bfloat162(
                    __float2bfloat16(v0 - __bfloat162float(h0)),
                    __float2bfloat16(v1 - __bfloat162float(h1)));
                *(__nv_bfloat162*)&Cl[(r0 + 8) * Nt + bn + c] = __halves2bfloat162(
                    __float2bfloat16(v2 - __bfloat162float(h2)),
                    __float2bfloat16(v3 - __bfloat162float(h3)));
            }
        }
    }
}

// ---------------------------------------------------------------------------
// fp32 -> fp16 convert (elementwise)
// ---------------------------------------------------------------------------
__global__ void __launch_bounds__(256) conv_f16_kernel(
    const float4* __restrict__ in, __half2* __restrict__ oh, int n4)
{
    int i = blockIdx.x * 256 + threadIdx.x;
    if (i >= n4) return;
    float4 v = in[i];
    oh[2 * i + 0] = __halves2half2(__float2half(v.x), __float2half(v.y));
    oh[2 * i + 1] = __halves2half2(__float2half(v.z), __float2half(v.w));
}

// ---------------------------------------------------------------------------
// w[K,N] fp32 -> out[N,1024] fp16 (transpose); K == 1024.
// ---------------------------------------------------------------------------
__global__ void __launch_bounds__(256) t_f16_kernel(
    const float* __restrict__ w, __half* __restrict__ oh, int N)
{
    __shared__ float t[32][33];
    const int n0 = blockIdx.x * 32, k0 = blockIdx.y * 32;
    const int tx = threadIdx.x, ty = threadIdx.y;
#pragma unroll
    for (int i = 0; i < 4; i++)
        t[ty + i * 8][tx] = w[(size_t)(k0 + ty + i * 8) * N + n0 + tx];
    __syncthreads();
#pragma unroll
    for (int i = 0; i < 4; i++) {
        const int n = n0 + ty + i * 8, k = k0 + tx;
        oh[(size_t)n * 1024 + k] = __float2half(t[tx][ty + i * 8]);
    }
}

// ---------------------------------------------------------------------------
// fp32 -> bf16 hi/lo split (elementwise)  [node path]
// ---------------------------------------------------------------------------
__global__ void __launch_bounds__(256) split_kernel(
    const float4* __restrict__ in, __nv_bfloat162* __restrict__ oh,
    __nv_bfloat162* __restrict__ ol, int n4)
{
    int i = blockIdx.x * 256 + threadIdx.x;
    if (i >= n4) return;
    float4 v = in[i];
    __nv_bfloat16 h0 = __float2bfloat16(v.x), h1 = __float2bfloat16(v.y);
    __nv_bfloat16 h2 = __float2bfloat16(v.z), h3 = __float2bfloat16(v.w);
    oh[2 * i + 0] = __halves2bfloat162(h0, h1);
    oh[2 * i + 1] = __halves2bfloat162(h2, h3);
    ol[2 * i + 0] = __halves2bfloat162(
        __float2bfloat16(v.x - __bfloat162float(h0)),
        __float2bfloat16(v.y - __bfloat162float(h1)));
    ol[2 * i + 1] = __halves2bfloat162(
        __float2bfloat16(v.z - __bfloat162float(h2)),
        __float2bfloat16(v.w - __bfloat162float(h3)));
}

// ---------------------------------------------------------------------------
// w[K,N] fp32 -> out[N,1024] bf16 hi/lo (transpose + split); K == 1024.
// ---------------------------------------------------------------------------
__global__ void __launch_bounds__(256) tsplit_kernel(
    const float* __restrict__ w, __nv_bfloat16* __restrict__ oh,
    __nv_bfloat16* __restrict__ ol, int N)
{
    __shared__ float t[32][33];
    const int n0 = blockIdx.x * 32, k0 = blockIdx.y * 32;
    const int tx = threadIdx.x, ty = threadIdx.y;
#pragma unroll
    for (int i = 0; i < 4; i++)
        t[ty + i * 8][tx] = w[(size_t)(k0 + ty + i * 8) * N + n0 + tx];
    __syncthreads();
#pragma unroll
    for (int i = 0; i < 4; i++) {
        const int n = n0 + ty + i * 8, k = k0 + tx;
        const float v = t[tx][ty + i * 8];
        __nv_bfloat16 h = __float2bfloat16(v);
        oh[(size_t)n * 1024 + k] = h;
        ol[(size_t)n * 1024 + k] = __float2bfloat16(v - __bfloat162float(h));
    }
}

// ---------------------------------------------------------------------------
// kproj[k,d] = sum_n proj_k[n,k] * kv[n,d]  (kv row stride kvs)
// ---------------------------------------------------------------------------
__global__ void __launch_bounds__(128) kproj_kernel(
    const float* __restrict__ kv, int kvs, const float* __restrict__ pk,
    float* __restrict__ kp)
{
    const int k = blockIdx.x;
    const int d = threadIdx.x;
    float s0 = 0.f, s1 = 0.f, s2 = 0.f, s3 = 0.f;
#pragma unroll 4
    for (int n = 0; n < N_NODES; n += 4) {
        s0 += pk[(size_t)(n + 0) * KPROJ + k] * kv[(size_t)(n + 0) * kvs + d];
        s1 += pk[(size_t)(n + 1) * KPROJ + k] * kv[(size_t)(n + 1) * kvs + d];
        s2 += pk[(size_t)(n + 2) * KPROJ + k] * kv[(size_t)(n + 2) * kvs + d];
        s3 += pk[(size_t)(n + 3) * KPROJ + k] * kv[(size_t)(n + 3) * kvs + d];
    }
    kp[(size_t)k * DH + d] = (s0 + s1) + (s2 + s3);
}

// ---------------------------------------------------------------------------
// Fused attention (per node, 8 warps = 8 heads) -> bf16 hi/lo output
// ---------------------------------------------------------------------------
__global__ void __launch_bounds__(256) attn_kernel(
    const float* __restrict__ q, int qs, const float* __restrict__ kproj,
    __nv_bfloat16* __restrict__ oh, __nv_bfloat16* __restrict__ ol)
{
    __shared__ float q_s[DIM];
    __shared__ float prob[HEADS][KPROJ];

    const int n = blockIdx.x;
    for (int i = threadIdx.x; i < DIM; i += 256)
        q_s[i] = q[(size_t)n * qs + i];
    __syncthreads();

    const int w = threadIdx.x >> 5;
    const int l = threadIdx.x & 31;
    const float4* qh4 = (const float4*)(q_s + w * DH);

    float d8[8];
#pragma unroll
    for (int j = 0; j < 8; j++) {
        const int k = j * 32 + l;
        const float4* kr4 = (const float4*)(kproj + (size_t)k * DH);
        float s = 0.f;
#pragma unroll
        for (int d4 = 0; d4 < DH / 4; d4++) {
            float4 qq = qh4[d4], kk = kr4[d4];
            s += qq.x * kk.x + qq.y * kk.y + qq.z * kk.z + qq.w * kk.w;
        }
        d8[j] = s * 0.088388347648318447f;
    }
    float mx = d8[0];
#pragma unroll
    for (int j = 1; j < 8; j++) mx = fmaxf(mx, d8[j]);
#pragma unroll
    for (int o = 16; o; o >>= 1) mx = fmaxf(mx, __shfl_xor_sync(0xFFFFFFFFu, mx, o));
    float sum = 0.f;
#pragma unroll
    for (int j = 0; j < 8; j++) { d8[j] = expf(d8[j] - mx); sum += d8[j]; }
#pragma unroll
    for (int o = 16; o; o >>= 1) sum += __shfl_xor_sync(0xFFFFFFFFu, sum, o);
    const float inv = 1.f / sum;
#pragma unroll
    for (int j = 0; j < 8; j++) prob[w][j * 32 + l] = d8[j] * inv;
    __syncwarp();

    float o0 = 0.f, o1 = 0.f, o2 = 0.f, o3 = 0.f;
    for (int k = 0; k < KPROJ; k++) {
        const float p = prob[w][k];
        const float* kr = kproj + (size_t)k * DH + l;
        o0 += p * kr[0];  o1 += p * kr[32];
        o2 += p * kr[64]; o3 += p * kr[96];
    }
    const size_t ob = (size_t)n * DIM + w * DH + l;
    float ov[4] = {o0, o1, o2, o3};
#pragma unroll
    for (int j = 0; j < 4; j++) {
        __nv_bfloat16 h = __float2bfloat16(ov[j]);
        oh[ob + 32 * j] = h;
        ol[ob + 32 * j] = __float2bfloat16(ov[j] - __bfloat162float(h));
    }
}

// ---------------------------------------------------------------------------
// LayerNorm + residual (in-place safe)
// ---------------------------------------------------------------------------
__global__ void __launch_bounds__(256) ln_res_kernel(
    const float* __restrict__ src, const float* __restrict__ resid,
    const float* __restrict__ gamma, const float* __restrict__ beta,
    float* __restrict__ dst)
{
    const int row = blockIdx.x;
    const int t = threadIdx.x;
    const float4 v = *(const float4*)&src[(size_t)row * DIM + t * 4];

    float sum = v.x + v.y + v.z + v.w;
    float sq = v.x * v.x + v.y * v.y + v.z * v.z + v.w * v.w;
#pragma unroll
    for (int o = 16; o; o >>= 1) {
        sum += __shfl_xor_sync(0xFFFFFFFFu, sum, o);
        sq  += __shfl_xor_sync(0xFFFFFFFFu, sq, o);
    }
    __shared__ float ssum[8], ssq[8];
    const int w = t >> 5, l = t & 31;
    if (l == 0) { ssum[w] = sum; ssq[w] = sq; }
    __syncthreads();
    sum = 0.f; sq = 0.f;
#pragma unroll
    for (int i = 0; i < 8; i++) { sum += ssum[i]; sq += ssq[i]; }

    const float mu = sum * (1.f / DIM);
    const float var = sq * (1.f / DIM) - mu * mu;
    const float rstd = rsqrtf(var + 1e-5f);

    const float4 g = *(const float4*)&gamma[t * 4];
    const float4 b = *(const float4*)&beta[t * 4];
    const float4 rr = *(const float4*)&resid[(size_t)row * DIM + t * 4];
    float4 o;
    o.x = (v.x - mu) * rstd * g.x + b.x + rr.x;
    o.y = (v.y - mu) * rstd * g.y + b.y + rr.y;
    o.z = (v.z - mu) * rstd * g.z + b.z + rr.z;
    o.w = (v.w - mu) * rstd * g.w + b.w + rr.w;
    *(float4*)&dst[(size_t)row * DIM + t * 4] = o;
}

// ---------------------------------------------------------------------------
// kernel_launch
// ---------------------------------------------------------------------------
extern "C" void kernel_launch(void* const* d_in, const int* in_sizes, int n_in,
                              void* d_out, int out_size)
{
    const float* node       = (const float*)d_in[0];
    const float* edge       = (const float*)d_in[1];
    const float* w_query    = (const float*)d_in[2];
    const float* b_query    = (const float*)d_in[3];
    const float* w_edge     = (const float*)d_in[4];
    const float* b_edge     = (const float*)d_in[5];
    const float* w_to_q     = (const float*)d_in[6];
    const float* w_to_k     = (const float*)d_in[7];
    const float* proj_k     = (const float*)d_in[8];
    const float* w_out      = (const float*)d_in[9];
    const float* b_out      = (const float*)d_in[10];
    const float* gamma_node = (const float*)d_in[11];
    const float* beta_node  = (const float*)d_in[12];
    const float* gamma_edge = (const float*)d_in[13];
    const float* beta_edge  = (const float*)d_in[14];

    float* x_out = (float*)d_out;
    float* y_out = (float*)d_out + (size_t)N_NODES * DIM;

    __half *e16, *weT16;
    __nv_bfloat16 *nh, *nl, *wqTh, *wqTl;
    __nv_bfloat16 *wqkTh, *wqkTl, *woTh, *woTl, *xqh, *xql, *ah, *al;
    float *qkv, *kp, *xattn;
    cudaGetSymbolAddress((void**)&e16, g_e16);
    cudaGetSymbolAddress((void**)&weT16, g_weT16);
    cudaGetSymbolAddress((void**)&nh, g_nh);
    cudaGetSymbolAddress((void**)&nl, g_nl);
    cudaGetSymbolAddress((void**)&wqTh, g_wqT_h);
    cudaGetSymbolAddress((void**)&wqTl, g_wqT_l);
    cudaGetSymbolAddress((void**)&wqkTh, g_wqkT_h);
    cudaGetSymbolAddress((void**)&wqkTl, g_wqkT_l);
    cudaGetSymbolAddress((void**)&woTh, g_woT_h);
    cudaGetSymbolAddress((void**)&woTl, g_woT_l);
    cudaGetSymbolAddress((void**)&xqh, g_xqh);
    cudaGetSymbolAddress((void**)&xql, g_xql);
    cudaGetSymbolAddress((void**)&ah, g_ah);
    cudaGetSymbolAddress((void**)&al, g_al);
    cudaGetSymbolAddress((void**)&qkv, g_qkv);
    cudaGetSymbolAddress((void**)&kp, g_kproj);
    cudaGetSymbolAddress((void**)&xattn, g_xattn);

    static bool attr_set = false;
    if (!attr_set) {
        cudaFuncSetAttribute(gemm_bf16_sw,
                             cudaFuncAttributeMaxDynamicSharedMemorySize, N_SM);
        cudaFuncSetAttribute(gemm_f16_sw,
                             cudaFuncAttributeMaxDynamicSharedMemorySize, E_SM);
        attr_set = true;
    }

    // order: node GEMM #1 at launch slot 4 (the ncu-captured slot).
    {
        const int n4 = N_EDGES * DIM / 4;
        conv_f16_kernel<<<(n4 + 255) / 256, 256>>>(
            (const float4*)edge, (__half2*)e16, n4);
    }
    {
        const int n4 = N_NODES * DIM / 4;
        split_kernel<<<(n4 + 255) / 256, 256>>>(
            (const float4*)node, (__nv_bfloat162*)nh, (__nv_bfloat162*)nl, n4);
    }
    tsplit_kernel<<<dim3(32, 32), dim3(32, 8)>>>(w_query, wqTh, wqTl, DIM);
    gemm_bf16_sw<<<dim3(8, 16), 256, N_SM>>>(
        nh, nl, wqTh, wqTl, b_query, nullptr, xqh, xql, DIM);

    t_f16_kernel<<<dim3(32, 32), dim3(32, 8)>>>(w_edge, weT16, DIM);
    gemm_f16_sw<<<dim3(8, 256), 256, E_SM>>>(e16, weT16, b_edge, y_out, DIM);
    ln_res_kernel<<<N_EDGES, 256>>>(y_out, edge, gamma_edge, beta_edge, y_out);

    tsplit_kernel<<<dim3(32, 32), dim3(32, 8)>>>(w_to_q, wqkTh, wqkTl, DIM);
    tsplit_kernel<<<dim3(4, 32), dim3(32, 8)>>>(
        w_to_k, wqkTh + (size_t)1024 * 1024, wqkTl + (size_t)1024 * 1024, DH);
    gemm_bf16_sw<<<dim3(9, 16), 256, N_SM>>>(
        xqh, xql, wqkTh, wqkTl, nullptr, qkv, nullptr, nullptr, QKV_N);

    kproj_kernel<<<KPROJ, 128>>>(qkv + 1024, QKV_N, proj_k, kp);
    attn_kernel<<<N_NODES, 256>>>(qkv, QKV_N, kp, ah, al);

    tsplit_kernel<<<dim3(32, 32), dim3(32, 8)>>>(w_out, woTh, woTl, DIM);
    gemm_bf16_sw<<<dim3(8, 16), 256, N_SM>>>(
        ah, al, woTh, woTl, b_out, xattn, nullptr, nullptr, DIM);
    ln_res_kernel<<<N_NODES, 256>>>(xattn, node, gamma_node, beta_node, x_out);
}

// round 8
// speedup vs baseline: 5.6349x; 1.2207x over previous
#include <cuda_runtime.h>
#include <cuda_bf16.h>
#include <cuda_fp16.h>
#include <math.h>
#include <stdint.h>

#define N_NODES 1024
#define N_EDGES 32768
#define DIM     1024
#define HEADS   8
#define DH      128
#define KPROJ   256
#define QKV_N   1152   // w_to_q (1024) ++ w_to_k (128), fused GEMM

// ---------------------------------------------------------------------------
// Scratch (device globals -- no allocation allowed)
// ---------------------------------------------------------------------------
__device__ __half        g_e16[N_EDGES * DIM];                         // edge fp16
__device__ __half        g_weT16[DIM * DIM];                           // w_edge^T fp16
__device__ __nv_bfloat16 g_nh[N_NODES * DIM],  g_nl[N_NODES * DIM];    // node hi/lo
__device__ __nv_bfloat16 g_wqT_h[DIM * DIM],   g_wqT_l[DIM * DIM];     // w_query^T
__device__ __nv_bfloat16 g_wqkT_h[QKV_N * DIM], g_wqkT_l[QKV_N * DIM]; // [w_to_q|w_to_k]^T
__device__ __nv_bfloat16 g_woT_h[DIM * DIM],   g_woT_l[DIM * DIM];     // w_out^T
__device__ __nv_bfloat16 g_xqh[N_NODES * DIM], g_xql[N_NODES * DIM];   // xq hi/lo
__device__ float         g_qkv[N_NODES * QKV_N];                       // [q | kv] fp32
__device__ float         g_kproj[KPROJ * DH];
__device__ __nv_bfloat16 g_ah[N_NODES * DIM],  g_al[N_NODES * DIM];    // attn out hi/lo
__device__ float         g_xattn[N_NODES * DIM];

// ---------------------------------------------------------------------------
// Generic-ISA PTX helpers
// ---------------------------------------------------------------------------
__device__ __forceinline__ uint32_t smem_u32(const void* p) {
    uint32_t a;
    asm("{ .reg .u64 t; cvta.to.shared.u64 t, %1; cvt.u32.u64 %0, t; }"
        : "=r"(a) : "l"(p));
    return a;
}

#define CP_ASYNC16(dst, src) \
    asm volatile("cp.async.cg.shared.global [%0], [%1], 16;" :: "r"(dst), "l"(src))
#define CP_COMMIT() asm volatile("cp.async.commit_group;" ::: "memory")
#define CP_WAIT1()  asm volatile("cp.async.wait_group 1;" ::: "memory")

#define LDSM4(r, addr) \
    asm volatile("ldmatrix.sync.aligned.m8n8.x4.shared.b16 {%0,%1,%2,%3}, [%4];" \
        : "=r"((r)[0]), "=r"((r)[1]), "=r"((r)[2]), "=r"((r)[3]) : "r"(addr))
#define LDSM2(r, addr) \
    asm volatile("ldmatrix.sync.aligned.m8n8.x2.shared.b16 {%0,%1}, [%2];" \
        : "=r"((r)[0]), "=r"((r)[1]) : "r"(addr))

__device__ __forceinline__ void mma16816(float* c, const uint32_t* a, const uint32_t* b) {
    asm volatile(
        "mma.sync.aligned.m16n8k16.row.col.f32.bf16.bf16.f32 "
        "{%0,%1,%2,%3}, {%4,%5,%6,%7}, {%8,%9}, {%0,%1,%2,%3};"
        : "+f"(c[0]), "+f"(c[1]), "+f"(c[2]), "+f"(c[3])
        : "r"(a[0]), "r"(a[1]), "r"(a[2]), "r"(a[3]), "r"(b[0]), "r"(b[1]));
}

__device__ __forceinline__ void mma16816h(float* c, const uint32_t* a, const uint32_t* b) {
    asm volatile(
        "mma.sync.aligned.m16n8k16.row.col.f32.f16.f16.f32 "
        "{%0,%1,%2,%3}, {%4,%5,%6,%7}, {%8,%9}, {%0,%1,%2,%3};"
        : "+f"(c[0]), "+f"(c[1]), "+f"(c[2]), "+f"(c[3])
        : "r"(a[0]), "r"(a[1]), "r"(a[2]), "r"(a[3]), "r"(b[0]), "r"(b[1]));
}

#define GK 1024

// ===========================================================================
// EDGE GEMM (fp16, 1-term, SW128 swizzle) -- unchanged (proven 171us)
// ===========================================================================
#define E_NTK 16
#define E_TILE 16384
#define E_STAGE (2 * E_TILE)
#define E_SM (512 + 3 * E_STAGE)

__global__ void __launch_bounds__(256, 2) gemm_f16_sw(
    const __half* __restrict__ A16, const __half* __restrict__ BhT,
    const float* __restrict__ bias, float* __restrict__ Cf, int Nt)
{
    extern __shared__ char smem[];
    const uint32_t sb = smem_u32(smem);
    const int tid = threadIdx.x;
    const int wid = tid >> 5;
    const int lane = tid & 31;
    const int bm = blockIdx.y * 128;
    const int bn = blockIdx.x * 128;

    if (tid < 128) ((float*)smem)[tid] = bias ? bias[bn + tid] : 0.f;

    const __half* srcA = A16 + (size_t)bm * GK;
    const __half* srcB = BhT + (size_t)bn * GK;

    auto load_stage = [&](int kt, int s) {
        const uint32_t base = sb + 512 + s * E_STAGE;
#pragma unroll
        for (int i = 0; i < 4; i++) {
            const int idx = i * 256 + tid;
            const int row = idx >> 3, c = idx & 7;
            const uint32_t sw = (uint32_t)row * 128 + (uint32_t)((c ^ (row & 7)) << 4);
            CP_ASYNC16(base + sw, srcA + (size_t)row * GK + kt * 64 + c * 8);
        }
#pragma unroll
        for (int i = 0; i < 4; i++) {
            const int idx = i * 256 + tid;
            const int row = idx >> 3, c = idx & 7;
            const uint32_t sw = (uint32_t)row * 128 + (uint32_t)((c ^ (row & 7)) << 4);
            CP_ASYNC16(base + E_TILE + sw, srcB + (size_t)row * GK + kt * 64 + c * 8);
        }
    };

    load_stage(0, 0); CP_COMMIT();
    load_stage(1, 1); CP_COMMIT();

    const int wm = (wid >> 2) * 64;
    const int wn = (wid & 3) * 32;
    const int l7 = lane & 7;

    float acc[4][4][4];
#pragma unroll
    for (int mt = 0; mt < 4; mt++)
#pragma unroll
        for (int nt = 0; nt < 4; nt++)
#pragma unroll
            for (int j = 0; j < 4; j++) acc[mt][nt][j] = 0.f;

    for (int kt = 0; kt < E_NTK; kt++) {
        CP_WAIT1();
        __syncthreads();

        if (kt + 2 < E_NTK) { load_stage(kt + 2, (kt + 2) % 3); CP_COMMIT(); }

        const uint32_t st = sb + 512 + (kt % 3) * E_STAGE;
        const uint32_t aRow = st + (uint32_t)(wm + (lane & 15)) * 128;
        const uint32_t bRow = st + E_TILE + (uint32_t)(wn + l7) * 128;

#pragma unroll
        for (int kh = 0; kh < 4; kh++) {
            const uint32_t aChunk = (uint32_t)(((kh << 1) | (lane >> 4)) ^ l7) << 4;
            const uint32_t bChunk = (uint32_t)(((kh << 1) | ((lane >> 3) & 1)) ^ l7) << 4;
            uint32_t aF[4][4], bH[4][2];
#pragma unroll
            for (int nt = 0; nt < 4; nt++)
                LDSM2(bH[nt], bRow + (uint32_t)(nt * 8) * 128 + bChunk);
#pragma unroll
            for (int mt = 0; mt < 4; mt++)
                LDSM4(aF[mt], aRow + (uint32_t)(mt * 16) * 128 + aChunk);
#pragma unroll
            for (int mt = 0; mt < 4; mt++)
#pragma unroll
                for (int nt = 0; nt < 4; nt++)
                    mma16816h(acc[mt][nt], aF[mt], bH[nt]);
        }
    }

    const float* bs = (const float*)smem;
#pragma unroll
    for (int mt = 0; mt < 4; mt++) {
#pragma unroll
        for (int nt = 0; nt < 4; nt++) {
            const int c = wn + nt * 8 + (lane & 3) * 2;
            const size_t r0 = (size_t)bm + wm + mt * 16 + (lane >> 2);
            *(float2*)&Cf[r0 * Nt + bn + c] =
                make_float2(acc[mt][nt][0] + bs[c], acc[mt][nt][1] + bs[c + 1]);
            *(float2*)&Cf[(r0 + 8) * Nt + bn + c] =
                make_float2(acc[mt][nt][2] + bs[c], acc[mt][nt][3] + bs[c + 1]);
        }
    }
}

// ===========================================================================
// NODE GEMM (bf16 3-term, SW128 swizzle) -- unchanged (proven 24.6us)
// ===========================================================================
#define N_NTK 16
#define N_ATILE 8192
#define N_BTILE 16384
#define N_STAGE (2 * N_ATILE + 2 * N_BTILE)
#define N_SM (512 + 3 * N_STAGE)

__global__ void __launch_bounds__(256, 1) gemm_bf16_sw(
    const __nv_bfloat16* __restrict__ Ah, const __nv_bfloat16* __restrict__ Al,
    const __nv_bfloat16* __restrict__ BhT, const __nv_bfloat16* __restrict__ BlT,
    const float* __restrict__ bias,
    float* __restrict__ Cf, __nv_bfloat16* __restrict__ Ch, __nv_bfloat16* __restrict__ Cl,
    int Nt)
{
    extern __shared__ char smem[];
    const uint32_t sb = smem_u32(smem);
    const int tid = threadIdx.x;
    const int wid = tid >> 5;
    const int lane = tid & 31;
    const int bm = blockIdx.y * 64;
    const int bn = blockIdx.x * 128;

    if (tid < 128) ((float*)smem)[tid] = bias ? bias[bn + tid] : 0.f;

    const __nv_bfloat16* sAh = Ah + (size_t)bm * GK;
    const __nv_bfloat16* sAl = Al + (size_t)bm * GK;
    const __nv_bfloat16* sBh = BhT + (size_t)bn * GK;
    const __nv_bfloat16* sBl = BlT + (size_t)bn * GK;

    auto load_stage = [&](int kt, int s) {
        const uint32_t base = sb + 512 + s * N_STAGE;
#pragma unroll
        for (int i = 0; i < 2; i++) {
            const int idx = i * 256 + tid;
            const int row = idx >> 3, c = idx & 7;
            const uint32_t sw = (uint32_t)row * 128 + (uint32_t)((c ^ (row & 7)) << 4);
            CP_ASYNC16(base + sw, sAh + (size_t)row * GK + kt * 64 + c * 8);
            CP_ASYNC16(base + N_ATILE + sw, sAl + (size_t)row * GK + kt * 64 + c * 8);
        }
#pragma unroll
        for (int i = 0; i < 4; i++) {
            const int idx = i * 256 + tid;
            const int row = idx >> 3, c = idx & 7;
            const uint32_t sw = (uint32_t)row * 128 + (uint32_t)((c ^ (row & 7)) << 4);
            CP_ASYNC16(base + 2 * N_ATILE + sw, sBh + (size_t)row * GK + kt * 64 + c * 8);
            CP_ASYNC16(base + 2 * N_ATILE + N_BTILE + sw,
                       sBl + (size_t)row * GK + kt * 64 + c * 8);
        }
    };

    load_stage(0, 0); CP_COMMIT();
    load_stage(1, 1); CP_COMMIT();

    const int wm = (wid >> 2) * 32;
    const int wn = (wid & 3) * 32;
    const int l7 = lane & 7;

    float acc[2][4][4];
#pragma unroll
    for (int mt = 0; mt < 2; mt++)
#pragma unroll
        for (int nt = 0; nt < 4; nt++)
#pragma unroll
            for (int j = 0; j < 4; j++) acc[mt][nt][j] = 0.f;

    for (int kt = 0; kt < N_NTK; kt++) {
        CP_WAIT1();
        __syncthreads();

        if (kt + 2 < N_NTK) { load_stage(kt + 2, (kt + 2) % 3); CP_COMMIT(); }

        const uint32_t st = sb + 512 + (kt % 3) * N_STAGE;
        const uint32_t ahRow = st + (uint32_t)(wm + (lane & 15)) * 128;
        const uint32_t alRow = ahRow + N_ATILE;
        const uint32_t bhRow = st + 2 * N_ATILE + (uint32_t)(wn + l7) * 128;
        const uint32_t blRow = bhRow + N_BTILE;

#pragma unroll
        for (int kh = 0; kh < 4; kh++) {
            const uint32_t aChunk = (uint32_t)(((kh << 1) | (lane >> 4)) ^ l7) << 4;
            const uint32_t bChunk = (uint32_t)(((kh << 1) | ((lane >> 3) & 1)) ^ l7) << 4;
            uint32_t aH[2][4], aL[2][4], bH[4][2], bL[4][2];
#pragma unroll
            for (int nt = 0; nt < 4; nt++) {
                LDSM2(bH[nt], bhRow + (uint32_t)(nt * 8) * 128 + bChunk);
                LDSM2(bL[nt], blRow + (uint32_t)(nt * 8) * 128 + bChunk);
            }
#pragma unroll
            for (int mt = 0; mt < 2; mt++) {
                LDSM4(aH[mt], ahRow + (uint32_t)(mt * 16) * 128 + aChunk);
                LDSM4(aL[mt], alRow + (uint32_t)(mt * 16) * 128 + aChunk);
            }
#pragma unroll
            for (int mt = 0; mt < 2; mt++)
#pragma unroll
                for (int nt = 0; nt < 4; nt++) {
                    mma16816(acc[mt][nt], aH[mt], bH[nt]);
                    mma16816(acc[mt][nt], aH[mt], bL[nt]);
                    mma16816(acc[mt][nt], aL[mt], bH[nt]);
                }
        }
    }

    const float* bs = (const float*)smem;
#pragma unroll
    for (int mt = 0; mt < 2; mt++) {
#pragma unroll
        for (int nt = 0; nt < 4; nt++) {
            const int c = wn + nt * 8 + (lane & 3) * 2;
            const size_t r0 = (size_t)bm + wm + mt * 16 + (lane >> 2);
            const float v0 = acc[mt][nt][0] + bs[c];
            const float v1 = acc[mt][nt][1] + bs[c + 1];
            const float v2 = acc[mt][nt][2] + bs[c];
            const float v3 = acc[mt][nt][3] + bs[c + 1];
            if (Cf) {
                *(float2*)&Cf[r0 * Nt + bn + c]       = make_float2(v0, v1);
                *(float2*)&Cf[(r0 + 8) * Nt + bn + c] = make_float2(v2, v3);
            }
            if (Ch) {
                __nv_bfloat16 h0 = __float2bfloat16(v0), h1 = __float2bfloat16(v1);
                __nv_bfloat16 h2 = __float2bfloat16(v2), h3 = __float2bfloat16(v3);
                *(__nv_bfloat162*)&Ch[r0 * Nt + bn + c] = __halves2bfloat162(h0, h1);
                *(__nv_bfloat162*)&Ch[(r0 + 8) * Nt + bn + c] = __halves2bfloat162(h2, h3);
                *(__nv_bfloat162*)&Cl[r0 * Nt + bn + c] = __halves2bfloat162(
                    __float2bfloat16(v0 - __bfloat162float(h0)),
                    __float2bfloat16(v1 - __bfloat162float(h1)));
                *(__nv_bfloat162*)&Cl[(r0 + 8) * Nt + bn + c] = __halves2bfloat162(
                    __float2bfloat16(v2 - __bfloat162float(h2)),
                    __float2bfloat16(v3 - __bfloat162float(h3)));
            }
        }
    }
}

// ---------------------------------------------------------------------------
// fp32 -> fp16 convert (elementwise)
// ---------------------------------------------------------------------------
__global__ void __launch_bounds__(256) conv_f16_kernel(
    const float4* __restrict__ in, __half2* __restrict__ oh, int n4)
{
    int i = blockIdx.x * 256 + threadIdx.x;
    if (i >= n4) return;
    float4 v = in[i];
    oh[2 * i + 0] = __halves2half2(__float2half(v.x), __float2half(v.y));
    oh[2 * i + 1] = __halves2half2(__float2half(v.z), __float2half(v.w));
}

// ---------------------------------------------------------------------------
// w[K,N] fp32 -> out[N,1024] fp16 (transpose); K == 1024.
// ---------------------------------------------------------------------------
__global__ void __launch_bounds__(256) t_f16_kernel(
    const float* __restrict__ w, __half* __restrict__ oh, int N)
{
    __shared__ float t[32][33];
    const int n0 = blockIdx.x * 32, k0 = blockIdx.y * 32;
    const int tx = threadIdx.x, ty = threadIdx.y;
#pragma unroll
    for (int i = 0; i < 4; i++)
        t[ty + i * 8][tx] = w[(size_t)(k0 + ty + i * 8) * N + n0 + tx];
    __syncthreads();
#pragma unroll
    for (int i = 0; i < 4; i++) {
        const int n = n0 + ty + i * 8, k = k0 + tx;
        oh[(size_t)n * 1024 + k] = __float2half(t[tx][ty + i * 8]);
    }
}

// ---------------------------------------------------------------------------
// fp32 -> bf16 hi/lo split (elementwise)  [node path]
// ---------------------------------------------------------------------------
__global__ void __launch_bounds__(256) split_kernel(
    const float4* __restrict__ in, __nv_bfloat162* __restrict__ oh,
    __nv_bfloat162* __restrict__ ol, int n4)
{
    int i = blockIdx.x * 256 + threadIdx.x;
    if (i >= n4) return;
    float4 v = in[i];
    __nv_bfloat16 h0 = __float2bfloat16(v.x), h1 = __float2bfloat16(v.y);
    __nv_bfloat16 h2 = __float2bfloat16(v.z), h3 = __float2bfloat16(v.w);
    oh[2 * i + 0] = __halves2bfloat162(h0, h1);
    oh[2 * i + 1] = __halves2bfloat162(h2, h3);
    ol[2 * i + 0] = __halves2bfloat162(
        __float2bfloat16(v.x - __bfloat162float(h0)),
        __float2bfloat16(v.y - __bfloat162float(h1)));
    ol[2 * i + 1] = __halves2bfloat162(
        __float2bfloat16(v.z - __bfloat162float(h2)),
        __float2bfloat16(v.w - __bfloat162float(h3)));
}

// ---------------------------------------------------------------------------
// w[K,N] fp32 -> out[N,1024] bf16 hi/lo (transpose + split); K == 1024.
// ---------------------------------------------------------------------------
__global__ void __launch_bounds__(256) tsplit_kernel(
    const float* __restrict__ w, __nv_bfloat16* __restrict__ oh,
    __nv_bfloat16* __restrict__ ol, int N)
{
    __shared__ float t[32][33];
    const int n0 = blockIdx.x * 32, k0 = blockIdx.y * 32;
    const int tx = threadIdx.x, ty = threadIdx.y;
#pragma unroll
    for (int i = 0; i < 4; i++)
        t[ty + i * 8][tx] = w[(size_t)(k0 + ty + i * 8) * N + n0 + tx];
    __syncthreads();
#pragma unroll
    for (int i = 0; i < 4; i++) {
        const int n = n0 + ty + i * 8, k = k0 + tx;
        const float v = t[tx][ty + i * 8];
        __nv_bfloat16 h = __float2bfloat16(v);
        oh[(size_t)n * 1024 + k] = h;
        ol[(size_t)n * 1024 + k] = __float2bfloat16(v - __bfloat162float(h));
    }
}

// ---------------------------------------------------------------------------
// kproj[k,d] = sum_n proj_k[n,k] * kv[n,d]  (kv row stride kvs)
// ---------------------------------------------------------------------------
__global__ void __launch_bounds__(128) kproj_kernel(
    const float* __restrict__ kv, int kvs, const float* __restrict__ pk,
    float* __restrict__ kp)
{
    const int k = blockIdx.x;
    const int d = threadIdx.x;
    float s0 = 0.f, s1 = 0.f, s2 = 0.f, s3 = 0.f;
#pragma unroll 4
    for (int n = 0; n < N_NODES; n += 4) {
        s0 += pk[(size_t)(n + 0) * KPROJ + k] * kv[(size_t)(n + 0) * kvs + d];
        s1 += pk[(size_t)(n + 1) * KPROJ + k] * kv[(size_t)(n + 1) * kvs + d];
        s2 += pk[(size_t)(n + 2) * KPROJ + k] * kv[(size_t)(n + 2) * kvs + d];
        s3 += pk[(size_t)(n + 3) * KPROJ + k] * kv[(size_t)(n + 3) * kvs + d];
    }
    kp[(size_t)k * DH + d] = (s0 + s1) + (s2 + s3);
}

// ---------------------------------------------------------------------------
// Attention v2: 4 nodes per block, kproj staged in smem (pad 132 floats/row),
// q transposed [head][d][node], probs [head][k][node]. All accesses coalesced
// or conflict-free; fp32 math identical to v1.
// ---------------------------------------------------------------------------
#define NPB 4
#define KP_PAD 132
#define ATTN_SMEM ((KPROJ * KP_PAD + NPB * DIM + HEADS * KPROJ * NPB) * 4)

__global__ void __launch_bounds__(256) attn_v2(
    const float* __restrict__ q, int qs, const float* __restrict__ kproj,
    __nv_bfloat16* __restrict__ oh, __nv_bfloat16* __restrict__ ol)
{
    extern __shared__ float sm[];
    float* kp_s = sm;                           // [256][132]
    float* q_s  = sm + KPROJ * KP_PAD;          // [hd 0..1023][node 0..3]
    float* pr_s = q_s + NPB * DIM;              // [head][k][node]

    const int tid = threadIdx.x;
    const int n0 = blockIdx.x * NPB;

    for (int idx = tid; idx < KPROJ * DH; idx += 256) {
        const int r = idx >> 7, c = idx & 127;
        kp_s[r * KP_PAD + c] = kproj[idx];
    }
    for (int idx = tid; idx < NPB * DIM; idx += 256) {
        const int n = idx >> 10, hd = idx & 1023;
        q_s[hd * NPB + n] = q[(size_t)(n0 + n) * qs + hd];
    }
    __syncthreads();

    const int w = tid >> 5;   // head
    const int l = tid & 31;
    const float scale = 0.088388347648318447f;  // DH^-0.5

    // ---- dots: k = j*32 + l, 4 nodes at once
    float d8[NPB][8];
    const float* qb = q_s + w * DH * NPB;
    for (int j = 0; j < 8; j++) {
        const int k = j * 32 + l;
        const float* kr = kp_s + k * KP_PAD;
        float a0 = 0.f, a1 = 0.f, a2 = 0.f, a3 = 0.f;
#pragma unroll
        for (int d4 = 0; d4 < DH / 4; d4++) {
            const float4 kk = *(const float4*)(kr + d4 * 4);
            const float4 q0 = *(const float4*)(qb + (d4 * 4 + 0) * NPB);
            const float4 q1 = *(const float4*)(qb + (d4 * 4 + 1) * NPB);
            const float4 q2 = *(const float4*)(qb + (d4 * 4 + 2) * NPB);
            const float4 q3 = *(const float4*)(qb + (d4 * 4 + 3) * NPB);
            a0 += kk.x * q0.x + kk.y * q1.x + kk.z * q2.x + kk.w * q3.x;
            a1 += kk.x * q0.y + kk.y * q1.y + kk.z * q2.y + kk.w * q3.y;
            a2 += kk.x * q0.z + kk.y * q1.z + kk.z * q2.z + kk.w * q3.z;
            a3 += kk.x * q0.w + kk.y * q1.w + kk.z * q2.w + kk.w * q3.w;
        }
        d8[0][j] = a0 * scale; d8[1][j] = a1 * scale;
        d8[2][j] = a2 * scale; d8[3][j] = a3 * scale;
    }

    // ---- softmax per node (over 256 values spread across warp)
#pragma unroll
    for (int n = 0; n < NPB; n++) {
        float mx = d8[n][0];
#pragma unroll
        for (int j = 1; j < 8; j++) mx = fmaxf(mx, d8[n][j]);
#pragma unroll
        for (int o = 16; o; o >>= 1) mx = fmaxf(mx, __shfl_xor_sync(0xFFFFFFFFu, mx, o));
        float sum = 0.f;
#pragma unroll
        for (int j = 0; j < 8; j++) { d8[n][j] = expf(d8[n][j] - mx); sum += d8[n][j]; }
#pragma unroll
        for (int o = 16; o; o >>= 1) sum += __shfl_xor_sync(0xFFFFFFFFu, sum, o);
        const float inv = 1.f / sum;
#pragma unroll
        for (int j = 0; j < 8; j++)
            pr_s[(w * KPROJ + j * 32 + l) * NPB + n] = d8[n][j] * inv;
    }
    __syncwarp();

    // ---- out: lane handles d = 4l..4l+3, 4 nodes
    float4 o4[NPB];
#pragma unroll
    for (int n = 0; n < NPB; n++) o4[n] = make_float4(0.f, 0.f, 0.f, 0.f);
    const float* prb = pr_s + w * KPROJ * NPB;
#pragma unroll 4
    for (int k = 0; k < KPROJ; k++) {
        const float4 kk = *(const float4*)(kp_s + k * KP_PAD + l * 4);
        const float4 pp = *(const float4*)(prb + k * NPB);
        o4[0].x += pp.x * kk.x; o4[0].y += pp.x * kk.y;
        o4[0].z += pp.x * kk.z; o4[0].w += pp.x * kk.w;
        o4[1].x += pp.y * kk.x; o4[1].y += pp.y * kk.y;
        o4[1].z += pp.y * kk.z; o4[1].w += pp.y * kk.w;
        o4[2].x += pp.z * kk.x; o4[2].y += pp.z * kk.y;
        o4[2].z += pp.z * kk.z; o4[2].w += pp.z * kk.w;
        o4[3].x += pp.w * kk.x; o4[3].y += pp.w * kk.y;
        o4[3].z += pp.w * kk.z; o4[3].w += pp.w * kk.w;
    }

#pragma unroll
    for (int n = 0; n < NPB; n++) {
        const size_t ob = (size_t)(n0 + n) * DIM + w * DH + l * 4;
        const float v[4] = {o4[n].x, o4[n].y, o4[n].z, o4[n].w};
        __nv_bfloat16 h0 = __float2bfloat16(v[0]), h1 = __float2bfloat16(v[1]);
        __nv_bfloat16 h2 = __float2bfloat16(v[2]), h3 = __float2bfloat16(v[3]);
        *(__nv_bfloat162*)&oh[ob]     = __halves2bfloat162(h0, h1);
        *(__nv_bfloat162*)&oh[ob + 2] = __halves2bfloat162(h2, h3);
        *(__nv_bfloat162*)&ol[ob] = __halves2bfloat162(
            __float2bfloat16(v[0] - __bfloat162float(h0)),
            __float2bfloat16(v[1] - __bfloat162float(h1)));
        *(__nv_bfloat162*)&ol[ob + 2] = __halves2bfloat162(
            __float2bfloat16(v[2] - __bfloat162float(h2)),
            __float2bfloat16(v[3] - __bfloat162float(h3)));
    }
}

// ---------------------------------------------------------------------------
// LayerNorm + residual (in-place safe)
// ---------------------------------------------------------------------------
__global__ void __launch_bounds__(256) ln_res_kernel(
    const float* __restrict__ src, const float* __restrict__ resid,
    const float* __restrict__ gamma, const float* __restrict__ beta,
    float* __restrict__ dst)
{
    const int row = blockIdx.x;
    const int t = threadIdx.x;
    const float4 v = *(const float4*)&src[(size_t)row * DIM + t * 4];

    float sum = v.x + v.y + v.z + v.w;
    float sq = v.x * v.x + v.y * v.y + v.z * v.z + v.w * v.w;
#pragma unroll
    for (int o = 16; o; o >>= 1) {
        sum += __shfl_xor_sync(0xFFFFFFFFu, sum, o);
        sq  += __shfl_xor_sync(0xFFFFFFFFu, sq, o);
    }
    __shared__ float ssum[8], ssq[8];
    const int w = t >> 5, l = t & 31;
    if (l == 0) { ssum[w] = sum; ssq[w] = sq; }
    __syncthreads();
    sum = 0.f; sq = 0.f;
#pragma unroll
    for (int i = 0; i < 8; i++) { sum += ssum[i]; sq += ssq[i]; }

    const float mu = sum * (1.f / DIM);
    const float var = sq * (1.f / DIM) - mu * mu;
    const float rstd = rsqrtf(var + 1e-5f);

    const float4 g = *(const float4*)&gamma[t * 4];
    const float4 b = *(const float4*)&beta[t * 4];
    const float4 rr = *(const float4*)&resid[(size_t)row * DIM + t * 4];
    float4 o;
    o.x = (v.x - mu) * rstd * g.x + b.x + rr.x;
    o.y = (v.y - mu) * rstd * g.y + b.y + rr.y;
    o.z = (v.z - mu) * rstd * g.z + b.z + rr.z;
    o.w = (v.w - mu) * rstd * g.w + b.w + rr.w;
    *(float4*)&dst[(size_t)row * DIM + t * 4] = o;
}

// ---------------------------------------------------------------------------
// kernel_launch
// ---------------------------------------------------------------------------
extern "C" void kernel_launch(void* const* d_in, const int* in_sizes, int n_in,
                              void* d_out, int out_size)
{
    const float* node       = (const float*)d_in[0];
    const float* edge       = (const float*)d_in[1];
    const float* w_query    = (const float*)d_in[2];
    const float* b_query    = (const float*)d_in[3];
    const float* w_edge     = (const float*)d_in[4];
    const float* b_edge     = (const float*)d_in[5];
    const float* w_to_q     = (const float*)d_in[6];
    const float* w_to_k     = (const float*)d_in[7];
    const float* proj_k     = (const float*)d_in[8];
    const float* w_out      = (const float*)d_in[9];
    const float* b_out      = (const float*)d_in[10];
    const float* gamma_node = (const float*)d_in[11];
    const float* beta_node  = (const float*)d_in[12];
    const float* gamma_edge = (const float*)d_in[13];
    const float* beta_edge  = (const float*)d_in[14];

    float* x_out = (float*)d_out;
    float* y_out = (float*)d_out + (size_t)N_NODES * DIM;

    __half *e16, *weT16;
    __nv_bfloat16 *nh, *nl, *wqTh, *wqTl;
    __nv_bfloat16 *wqkTh, *wqkTl, *woTh, *woTl, *xqh, *xql, *ah, *al;
    float *qkv, *kp, *xattn;
    cudaGetSymbolAddress((void**)&e16, g_e16);
    cudaGetSymbolAddress((void**)&weT16, g_weT16);
    cudaGetSymbolAddress((void**)&nh, g_nh);
    cudaGetSymbolAddress((void**)&nl, g_nl);
    cudaGetSymbolAddress((void**)&wqTh, g_wqT_h);
    cudaGetSymbolAddress((void**)&wqTl, g_wqT_l);
    cudaGetSymbolAddress((void**)&wqkTh, g_wqkT_h);
    cudaGetSymbolAddress((void**)&wqkTl, g_wqkT_l);
    cudaGetSymbolAddress((void**)&woTh, g_woT_h);
    cudaGetSymbolAddress((void**)&woTl, g_woT_l);
    cudaGetSymbolAddress((void**)&xqh, g_xqh);
    cudaGetSymbolAddress((void**)&xql, g_xql);
    cudaGetSymbolAddress((void**)&ah, g_ah);
    cudaGetSymbolAddress((void**)&al, g_al);
    cudaGetSymbolAddress((void**)&qkv, g_qkv);
    cudaGetSymbolAddress((void**)&kp, g_kproj);
    cudaGetSymbolAddress((void**)&xattn, g_xattn);

    static bool attr_set = false;
    if (!attr_set) {
        cudaFuncSetAttribute(gemm_bf16_sw,
                             cudaFuncAttributeMaxDynamicSharedMemorySize, N_SM);
        cudaFuncSetAttribute(gemm_f16_sw,
                             cudaFuncAttributeMaxDynamicSharedMemorySize, E_SM);
        cudaFuncSetAttribute(attn_v2,
                             cudaFuncAttributeMaxDynamicSharedMemorySize, ATTN_SMEM);
        attr_set = true;
    }

    {
        const int n4 = N_EDGES * DIM / 4;
        conv_f16_kernel<<<(n4 + 255) / 256, 256>>>(
            (const float4*)edge, (__half2*)e16, n4);
    }
    {
        const int n4 = N_NODES * DIM / 4;
        split_kernel<<<(n4 + 255) / 256, 256>>>(
            (const float4*)node, (__nv_bfloat162*)nh, (__nv_bfloat162*)nl, n4);
    }
    tsplit_kernel<<<dim3(32, 32), dim3(32, 8)>>>(w_query, wqTh, wqTl, DIM);
    gemm_bf16_sw<<<dim3(8, 16), 256, N_SM>>>(
        nh, nl, wqTh, wqTl, b_query, nullptr, xqh, xql, DIM);

    t_f16_kernel<<<dim3(32, 32), dim3(32, 8)>>>(w_edge, weT16, DIM);
    gemm_f16_sw<<<dim3(8, 256), 256, E_SM>>>(e16, weT16, b_edge, y_out, DIM);
    ln_res_kernel<<<N_EDGES, 256>>>(y_out, edge, gamma_edge, beta_edge, y_out);

    tsplit_kernel<<<dim3(32, 32), dim3(32, 8)>>>(w_to_q, wqkTh, wqkTl, DIM);
    tsplit_kernel<<<dim3(4, 32), dim3(32, 8)>>>(
        w_to_k, wqkTh + (size_t)1024 * 1024, wqkTl + (size_t)1024 * 1024, DH);
    gemm_bf16_sw<<<dim3(9, 16), 256, N_SM>>>(
        xqh, xql, wqkTh, wqkTl, nullptr, qkv, nullptr, nullptr, QKV_N);

    kproj_kernel<<<KPROJ, 128>>>(qkv + 1024, QKV_N, proj_k, kp);
    attn_v2<<<N_NODES / NPB, 256, ATTN_SMEM>>>(qkv, QKV_N, kp, ah, al);

    tsplit_kernel<<<dim3(32, 32), dim3(32, 8)>>>(w_out, woTh, woTl, DIM);
    gemm_bf16_sw<<<dim3(8, 16), 256, N_SM>>>(
        ah, al, woTh, woTl, b_out, xattn, nullptr, nullptr, DIM);
    ln_res_kernel<<<N_NODES, 256>>>(xattn, node, gamma_node, beta_node, x_out);
}

// round 9
// speedup vs baseline: 6.7113x; 1.1910x over previous
#include <cuda_runtime.h>
#include <cuda_bf16.h>
#include <cuda_fp16.h>
#include <math.h>
#include <stdint.h>

#define N_NODES 1024
#define N_EDGES 32768
#define DIM     1024
#define HEADS   8
#define DH      128
#define KPROJ   256
#define QKV_N   1152   // w_to_q (1024) ++ w_to_k (128), fused GEMM

// ---------------------------------------------------------------------------
// Scratch (device globals -- no allocation allowed)
// ---------------------------------------------------------------------------
__device__ __half        g_e16[N_EDGES * DIM];                         // edge fp16
__device__ __half        g_weT16[DIM * DIM];                           // w_edge^T fp16
__device__ __nv_bfloat16 g_nh[N_NODES * DIM],  g_nl[N_NODES * DIM];    // node hi/lo
__device__ __nv_bfloat16 g_wqT_h[DIM * DIM],   g_wqT_l[DIM * DIM];     // w_query^T
__device__ __nv_bfloat16 g_wqkT_h[QKV_N * DIM], g_wqkT_l[QKV_N * DIM]; // [w_to_q|w_to_k]^T
__device__ __nv_bfloat16 g_woT_h[DIM * DIM],   g_woT_l[DIM * DIM];     // w_out^T
__device__ __nv_bfloat16 g_xqh[N_NODES * DIM], g_xql[N_NODES * DIM];   // xq hi/lo
__device__ float         g_qkv[N_NODES * QKV_N];                       // [q | kv] fp32
__device__ float         g_kproj[KPROJ * DH];
__device__ __nv_bfloat16 g_ah[N_NODES * DIM],  g_al[N_NODES * DIM];    // attn out hi/lo
__device__ float         g_xattn[N_NODES * DIM];

// ---------------------------------------------------------------------------
// Generic-ISA PTX helpers
// ---------------------------------------------------------------------------
__device__ __forceinline__ uint32_t smem_u32(const void* p) {
    uint32_t a;
    asm("{ .reg .u64 t; cvta.to.shared.u64 t, %1; cvt.u32.u64 %0, t; }"
        : "=r"(a) : "l"(p));
    return a;
}

#define CP_ASYNC16(dst, src) \
    asm volatile("cp.async.cg.shared.global [%0], [%1], 16;" :: "r"(dst), "l"(src))
#define CP_COMMIT() asm volatile("cp.async.commit_group;" ::: "memory")
#define CP_WAIT1()  asm volatile("cp.async.wait_group 1;" ::: "memory")

#define LDSM4(r, addr) \
    asm volatile("ldmatrix.sync.aligned.m8n8.x4.shared.b16 {%0,%1,%2,%3}, [%4];" \
        : "=r"((r)[0]), "=r"((r)[1]), "=r"((r)[2]), "=r"((r)[3]) : "r"(addr))

__device__ __forceinline__ void mma16816(float* c, const uint32_t* a, const uint32_t* b) {
    asm volatile(
        "mma.sync.aligned.m16n8k16.row.col.f32.bf16.bf16.f32 "
        "{%0,%1,%2,%3}, {%4,%5,%6,%7}, {%8,%9}, {%0,%1,%2,%3};"
        : "+f"(c[0]), "+f"(c[1]), "+f"(c[2]), "+f"(c[3])
        : "r"(a[0]), "r"(a[1]), "r"(a[2]), "r"(a[3]), "r"(b[0]), "r"(b[1]));
}

__device__ __forceinline__ void mma16816h(float* c, const uint32_t* a, const uint32_t* b) {
    asm volatile(
        "mma.sync.aligned.m16n8k16.row.col.f32.f16.f16.f32 "
        "{%0,%1,%2,%3}, {%4,%5,%6,%7}, {%8,%9}, {%0,%1,%2,%3};"
        : "+f"(c[0]), "+f"(c[1]), "+f"(c[2]), "+f"(c[3])
        : "r"(a[0]), "r"(a[1]), "r"(a[2]), "r"(a[3]), "r"(b[0]), "r"(b[1]));
}

#define GK 1024

// ===========================================================================
// EDGE GEMM (fp16, 1-term, SW128 swizzle). B fragments now via ldmatrix.x4
// spanning two n-tiles (lanes 16-31 -> rows n+8..15) -- halves B ldsm count.
// ===========================================================================
#define E_NTK 16
#define E_TILE 16384
#define E_STAGE (2 * E_TILE)
#define E_SM (512 + 3 * E_STAGE)

__global__ void __launch_bounds__(256, 2) gemm_f16_sw(
    const __half* __restrict__ A16, const __half* __restrict__ BhT,
    const float* __restrict__ bias, float* __restrict__ Cf, int Nt)
{
    extern __shared__ char smem[];
    const uint32_t sb = smem_u32(smem);
    const int tid = threadIdx.x;
    const int wid = tid >> 5;
    const int lane = tid & 31;
    const int bm = blockIdx.y * 128;
    const int bn = blockIdx.x * 128;

    if (tid < 128) ((float*)smem)[tid] = bias ? bias[bn + tid] : 0.f;

    const __half* srcA = A16 + (size_t)bm * GK;
    const __half* srcB = BhT + (size_t)bn * GK;

    auto load_stage = [&](int kt, int s) {
        const uint32_t base = sb + 512 + s * E_STAGE;
#pragma unroll
        for (int i = 0; i < 4; i++) {
            const int idx = i * 256 + tid;
            const int row = idx >> 3, c = idx & 7;
            const uint32_t sw = (uint32_t)row * 128 + (uint32_t)((c ^ (row & 7)) << 4);
            CP_ASYNC16(base + sw, srcA + (size_t)row * GK + kt * 64 + c * 8);
        }
#pragma unroll
        for (int i = 0; i < 4; i++) {
            const int idx = i * 256 + tid;
            const int row = idx >> 3, c = idx & 7;
            const uint32_t sw = (uint32_t)row * 128 + (uint32_t)((c ^ (row & 7)) << 4);
            CP_ASYNC16(base + E_TILE + sw, srcB + (size_t)row * GK + kt * 64 + c * 8);
        }
    };

    load_stage(0, 0); CP_COMMIT();
    load_stage(1, 1); CP_COMMIT();

    const int wm = (wid >> 2) * 64;
    const int wn = (wid & 3) * 32;
    const int l7 = lane & 7;
    // B x4 row offset: lanes 0-15 -> rows n..n+7 (chunks lo/hi), 16-31 -> n+8..n+15
    const int brow_off = l7 + ((lane >> 4) << 3);

    float acc[4][4][4];
#pragma unroll
    for (int mt = 0; mt < 4; mt++)
#pragma unroll
        for (int nt = 0; nt < 4; nt++)
#pragma unroll
            for (int j = 0; j < 4; j++) acc[mt][nt][j] = 0.f;

    for (int kt = 0; kt < E_NTK; kt++) {
        CP_WAIT1();
        __syncthreads();

        if (kt + 2 < E_NTK) { load_stage(kt + 2, (kt + 2) % 3); CP_COMMIT(); }

        const uint32_t st = sb + 512 + (kt % 3) * E_STAGE;
        const uint32_t aRow = st + (uint32_t)(wm + (lane & 15)) * 128;
        const uint32_t bRowBase = st + E_TILE + (uint32_t)(wn + brow_off) * 128;

#pragma unroll
        for (int kh = 0; kh < 4; kh++) {
            const uint32_t aChunk = (uint32_t)(((kh << 1) | (lane >> 4)) ^ l7) << 4;
            const uint32_t bChunk = (uint32_t)(((kh << 1) | ((lane >> 3) & 1)) ^ l7) << 4;
            uint32_t aF[4][4], bF[2][4];
#pragma unroll
            for (int p = 0; p < 2; p++)
                LDSM4(bF[p], bRowBase + (uint32_t)(p * 16) * 128 + bChunk);
#pragma unroll
            for (int mt = 0; mt < 4; mt++)
                LDSM4(aF[mt], aRow + (uint32_t)(mt * 16) * 128 + aChunk);
#pragma unroll
            for (int mt = 0; mt < 4; mt++)
#pragma unroll
                for (int nt = 0; nt < 4; nt++)
                    mma16816h(acc[mt][nt], aF[mt], &bF[nt >> 1][(nt & 1) * 2]);
        }
    }

    const float* bs = (const float*)smem;
#pragma unroll
    for (int mt = 0; mt < 4; mt++) {
#pragma unroll
        for (int nt = 0; nt < 4; nt++) {
            const int c = wn + nt * 8 + (lane & 3) * 2;
            const size_t r0 = (size_t)bm + wm + mt * 16 + (lane >> 2);
            *(float2*)&Cf[r0 * Nt + bn + c] =
                make_float2(acc[mt][nt][0] + bs[c], acc[mt][nt][1] + bs[c + 1]);
            *(float2*)&Cf[(r0 + 8) * Nt + bn + c] =
                make_float2(acc[mt][nt][2] + bs[c], acc[mt][nt][3] + bs[c + 1]);
        }
    }
}

// ===========================================================================
// NODE GEMM (bf16 3-term, SW128 swizzle), B via ldmatrix.x4 (2 n-tiles/op)
// ===========================================================================
#define N_NTK 16
#define N_ATILE 8192
#define N_BTILE 16384
#define N_STAGE (2 * N_ATILE + 2 * N_BTILE)
#define N_SM (512 + 3 * N_STAGE)

__global__ void __launch_bounds__(256, 1) gemm_bf16_sw(
    const __nv_bfloat16* __restrict__ Ah, const __nv_bfloat16* __restrict__ Al,
    const __nv_bfloat16* __restrict__ BhT, const __nv_bfloat16* __restrict__ BlT,
    const float* __restrict__ bias,
    float* __restrict__ Cf, __nv_bfloat16* __restrict__ Ch, __nv_bfloat16* __restrict__ Cl,
    int Nt)
{
    extern __shared__ char smem[];
    const uint32_t sb = smem_u32(smem);
    const int tid = threadIdx.x;
    const int wid = tid >> 5;
    const int lane = tid & 31;
    const int bm = blockIdx.y * 64;
    const int bn = blockIdx.x * 128;

    if (tid < 128) ((float*)smem)[tid] = bias ? bias[bn + tid] : 0.f;

    const __nv_bfloat16* sAh = Ah + (size_t)bm * GK;
    const __nv_bfloat16* sAl = Al + (size_t)bm * GK;
    const __nv_bfloat16* sBh = BhT + (size_t)bn * GK;
    const __nv_bfloat16* sBl = BlT + (size_t)bn * GK;

    auto load_stage = [&](int kt, int s) {
        const uint32_t base = sb + 512 + s * N_STAGE;
#pragma unroll
        for (int i = 0; i < 2; i++) {
            const int idx = i * 256 + tid;
            const int row = idx >> 3, c = idx & 7;
            const uint32_t sw = (uint32_t)row * 128 + (uint32_t)((c ^ (row & 7)) << 4);
            CP_ASYNC16(base + sw, sAh + (size_t)row * GK + kt * 64 + c * 8);
            CP_ASYNC16(base + N_ATILE + sw, sAl + (size_t)row * GK + kt * 64 + c * 8);
        }
#pragma unroll
        for (int i = 0; i < 4; i++) {
            const int idx = i * 256 + tid;
            const int row = idx >> 3, c = idx & 7;
            const uint32_t sw = (uint32_t)row * 128 + (uint32_t)((c ^ (row & 7)) << 4);
            CP_ASYNC16(base + 2 * N_ATILE + sw, sBh + (size_t)row * GK + kt * 64 + c * 8);
            CP_ASYNC16(base + 2 * N_ATILE + N_BTILE + sw,
                       sBl + (size_t)row * GK + kt * 64 + c * 8);
        }
    };

    load_stage(0, 0); CP_COMMIT();
    load_stage(1, 1); CP_COMMIT();

    const int wm = (wid >> 2) * 32;
    const int wn = (wid & 3) * 32;
    const int l7 = lane & 7;
    const int brow_off = l7 + ((lane >> 4) << 3);

    float acc[2][4][4];
#pragma unroll
    for (int mt = 0; mt < 2; mt++)
#pragma unroll
        for (int nt = 0; nt < 4; nt++)
#pragma unroll
            for (int j = 0; j < 4; j++) acc[mt][nt][j] = 0.f;

    for (int kt = 0; kt < N_NTK; kt++) {
        CP_WAIT1();
        __syncthreads();

        if (kt + 2 < N_NTK) { load_stage(kt + 2, (kt + 2) % 3); CP_COMMIT(); }

        const uint32_t st = sb + 512 + (kt % 3) * N_STAGE;
        const uint32_t ahRow = st + (uint32_t)(wm + (lane & 15)) * 128;
        const uint32_t alRow = ahRow + N_ATILE;
        const uint32_t bhRowBase = st + 2 * N_ATILE + (uint32_t)(wn + brow_off) * 128;
        const uint32_t blRowBase = bhRowBase + N_BTILE;

#pragma unroll
        for (int kh = 0; kh < 4; kh++) {
            const uint32_t aChunk = (uint32_t)(((kh << 1) | (lane >> 4)) ^ l7) << 4;
            const uint32_t bChunk = (uint32_t)(((kh << 1) | ((lane >> 3) & 1)) ^ l7) << 4;
            uint32_t aH[2][4], aL[2][4], bHF[2][4], bLF[2][4];
#pragma unroll
            for (int p = 0; p < 2; p++) {
                LDSM4(bHF[p], bhRowBase + (uint32_t)(p * 16) * 128 + bChunk);
                LDSM4(bLF[p], blRowBase + (uint32_t)(p * 16) * 128 + bChunk);
            }
#pragma unroll
            for (int mt = 0; mt < 2; mt++) {
                LDSM4(aH[mt], ahRow + (uint32_t)(mt * 16) * 128 + aChunk);
                LDSM4(aL[mt], alRow + (uint32_t)(mt * 16) * 128 + aChunk);
            }
#pragma unroll
            for (int mt = 0; mt < 2; mt++)
#pragma unroll
                for (int nt = 0; nt < 4; nt++) {
                    const uint32_t* bh = &bHF[nt >> 1][(nt & 1) * 2];
                    const uint32_t* bl = &bLF[nt >> 1][(nt & 1) * 2];
                    mma16816(acc[mt][nt], aH[mt], bh);
                    mma16816(acc[mt][nt], aH[mt], bl);
                    mma16816(acc[mt][nt], aL[mt], bh);
                }
        }
    }

    const float* bs = (const float*)smem;
#pragma unroll
    for (int mt = 0; mt < 2; mt++) {
#pragma unroll
        for (int nt = 0; nt < 4; nt++) {
            const int c = wn + nt * 8 + (lane & 3) * 2;
            const size_t r0 = (size_t)bm + wm + mt * 16 + (lane >> 2);
            const float v0 = acc[mt][nt][0] + bs[c];
            const float v1 = acc[mt][nt][1] + bs[c + 1];
            const float v2 = acc[mt][nt][2] + bs[c];
            const float v3 = acc[mt][nt][3] + bs[c + 1];
            if (Cf) {
                *(float2*)&Cf[r0 * Nt + bn + c]       = make_float2(v0, v1);
                *(float2*)&Cf[(r0 + 8) * Nt + bn + c] = make_float2(v2, v3);
            }
            if (Ch) {
                __nv_bfloat16 h0 = __float2bfloat16(v0), h1 = __float2bfloat16(v1);
                __nv_bfloat16 h2 = __float2bfloat16(v2), h3 = __float2bfloat16(v3);
                *(__nv_bfloat162*)&Ch[r0 * Nt + bn + c] = __halves2bfloat162(h0, h1);
                *(__nv_bfloat162*)&Ch[(r0 + 8) * Nt + bn + c] = __halves2bfloat162(h2, h3);
                *(__nv_bfloat162*)&Cl[r0 * Nt + bn + c] = __halves2bfloat162(
                    __float2bfloat16(v0 - __bfloat162float(h0)),
                    __float2bfloat16(v1 - __bfloat162float(h1)));
                *(__nv_bfloat162*)&Cl[(r0 + 8) * Nt + bn + c] = __halves2bfloat162(
                    __float2bfloat16(v2 - __bfloat162float(h2)),
                    __float2bfloat16(v3 - __bfloat162float(h3)));
            }
        }
    }
}

// ---------------------------------------------------------------------------
// Fused elementwise: blocks [0, 32768): edge fp32 -> fp16;
//                    blocks [32768, 33792): node fp32 -> bf16 hi/lo split.
// ---------------------------------------------------------------------------
#define EDGE_F4 (N_EDGES * DIM / 4)
#define NODE_F4 (N_NODES * DIM / 4)
#define CONV_BLOCKS (EDGE_F4 / 256 + NODE_F4 / 256)

__global__ void __launch_bounds__(256) fused_conv_kernel(
    const float4* __restrict__ edge, __half2* __restrict__ e16,
    const float4* __restrict__ node, __nv_bfloat162* __restrict__ nh,
    __nv_bfloat162* __restrict__ nl)
{
    const int bid = blockIdx.x;
    if (bid < EDGE_F4 / 256) {
        const int i = bid * 256 + threadIdx.x;
        float4 v = edge[i];
        e16[2 * i + 0] = __halves2half2(__float2half(v.x), __float2half(v.y));
        e16[2 * i + 1] = __halves2half2(__float2half(v.z), __float2half(v.w));
    } else {
        const int i = (bid - EDGE_F4 / 256) * 256 + threadIdx.x;
        float4 v = node[i];
        __nv_bfloat16 h0 = __float2bfloat16(v.x), h1 = __float2bfloat16(v.y);
        __nv_bfloat16 h2 = __float2bfloat16(v.z), h3 = __float2bfloat16(v.w);
        nh[2 * i + 0] = __halves2bfloat162(h0, h1);
        nh[2 * i + 1] = __halves2bfloat162(h2, h3);
        nl[2 * i + 0] = __halves2bfloat162(
            __float2bfloat16(v.x - __bfloat162float(h0)),
            __float2bfloat16(v.y - __bfloat162float(h1)));
        nl[2 * i + 1] = __halves2bfloat162(
            __float2bfloat16(v.z - __bfloat162float(h2)),
            __float2bfloat16(v.w - __bfloat162float(h3)));
    }
}

// ---------------------------------------------------------------------------
// Fused weight prep: 5 transpose jobs in one kernel. Block (32,8).
// jobs: 0 w_query->wqT(bf16 hi/lo, N=1024); 1 w_to_q->wqkT(+0); 2 w_to_k->
//       wqkT(+1M, N=128); 3 w_out->woT; 4 w_edge->weT16 (fp16 hi only).
// ---------------------------------------------------------------------------
#define WPREP_BLOCKS (1024 * 4 + 128)

__global__ void __launch_bounds__(256) fused_wprep_kernel(
    const float* __restrict__ w_query, const float* __restrict__ w_to_q,
    const float* __restrict__ w_to_k, const float* __restrict__ w_out,
    const float* __restrict__ w_edge,
    __nv_bfloat16* __restrict__ wqTh, __nv_bfloat16* __restrict__ wqTl,
    __nv_bfloat16* __restrict__ wqkTh, __nv_bfloat16* __restrict__ wqkTl,
    __nv_bfloat16* __restrict__ woTh, __nv_bfloat16* __restrict__ woTl,
    __half* __restrict__ weT16)
{
    __shared__ float t[32][33];
    int bid = blockIdx.x;
    const float* w; __nv_bfloat16 *oh = nullptr, *ol = nullptr; __half* of16 = nullptr;
    int N, nblk;
    if (bid < 1024)      { w = w_query; oh = wqTh; ol = wqTl; N = 1024; nblk = bid; }
    else if (bid < 2048) { w = w_to_q;  oh = wqkTh; ol = wqkTl; N = 1024; nblk = bid - 1024; }
    else if (bid < 2176) { w = w_to_k;  oh = wqkTh + (size_t)1024 * 1024;
                           ol = wqkTl + (size_t)1024 * 1024; N = 128; nblk = bid - 2048; }
    else if (bid < 3200) { w = w_out;   oh = woTh; ol = woTl; N = 1024; nblk = bid - 2176; }
    else                 { w = w_edge;  of16 = weT16; N = 1024; nblk = bid - 3200; }

    const int nx = N / 32;
    const int n0 = (nblk % nx) * 32, k0 = (nblk / nx) * 32;
    const int tx = threadIdx.x, ty = threadIdx.y;
#pragma unroll
    for (int i = 0; i < 4; i++)
        t[ty + i * 8][tx] = w[(size_t)(k0 + ty + i * 8) * N + n0 + tx];
    __syncthreads();
#pragma unroll
    for (int i = 0; i < 4; i++) {
        const int n = n0 + ty + i * 8, k = k0 + tx;
        const float v = t[tx][ty + i * 8];
        if (of16) {
            of16[(size_t)n * 1024 + k] = __float2half(v);
        } else {
            __nv_bfloat16 h = __float2bfloat16(v);
            oh[(size_t)n * 1024 + k] = h;
            ol[(size_t)n * 1024 + k] = __float2bfloat16(v - __bfloat162float(h));
        }
    }
}

// ---------------------------------------------------------------------------
// kproj[k,d] = sum_n proj_k[n,k] * kv[n,d]  (kv row stride kvs)
// ---------------------------------------------------------------------------
__global__ void __launch_bounds__(128) kproj_kernel(
    const float* __restrict__ kv, int kvs, const float* __restrict__ pk,
    float* __restrict__ kp)
{
    const int k = blockIdx.x;
    const int d = threadIdx.x;
    float s0 = 0.f, s1 = 0.f, s2 = 0.f, s3 = 0.f;
#pragma unroll 4
    for (int n = 0; n < N_NODES; n += 4) {
        s0 += pk[(size_t)(n + 0) * KPROJ + k] * kv[(size_t)(n + 0) * kvs + d];
        s1 += pk[(size_t)(n + 1) * KPROJ + k] * kv[(size_t)(n + 1) * kvs + d];
        s2 += pk[(size_t)(n + 2) * KPROJ + k] * kv[(size_t)(n + 2) * kvs + d];
        s3 += pk[(size_t)(n + 3) * KPROJ + k] * kv[(size_t)(n + 3) * kvs + d];
    }
    kp[(size_t)k * DH + d] = (s0 + s1) + (s2 + s3);
}

// ---------------------------------------------------------------------------
// Attention v3: like v2 but dots loop interchanged (d4 outer, j inner) so the
// 4 q-broadcast LDS per d4 are hoisted out of the j loop (LDS count /3.3).
// ---------------------------------------------------------------------------
#define NPB 4
#define KP_PAD 132
#define ATTN_SMEM ((KPROJ * KP_PAD + NPB * DIM + HEADS * KPROJ * NPB) * 4)

__global__ void __launch_bounds__(256) attn_v3(
    const float* __restrict__ q, int qs, const float* __restrict__ kproj,
    __nv_bfloat16* __restrict__ oh, __nv_bfloat16* __restrict__ ol)
{
    extern __shared__ float sm[];
    float* kp_s = sm;                           // [256][132]
    float* q_s  = sm + KPROJ * KP_PAD;          // [hd][node]
    float* pr_s = q_s + NPB * DIM;              // [head][k][node]

    const int tid = threadIdx.x;
    const int n0 = blockIdx.x * NPB;

    for (int idx = tid; idx < KPROJ * DH; idx += 256) {
        const int r = idx >> 7, c = idx & 127;
        kp_s[r * KP_PAD + c] = kproj[idx];
    }
    for (int idx = tid; idx < NPB * DIM; idx += 256) {
        const int n = idx >> 10, hd = idx & 1023;
        q_s[hd * NPB + n] = q[(size_t)(n0 + n) * qs + hd];
    }
    __syncthreads();

    const int w = tid >> 5;   // head
    const int l = tid & 31;
    const float scale = 0.088388347648318447f;  // DH^-0.5

    // ---- dots: d4 outer (q hoisted), j inner
    float d8[NPB][8];
#pragma unroll
    for (int n = 0; n < NPB; n++)
#pragma unroll
        for (int j = 0; j < 8; j++) d8[n][j] = 0.f;

    const float* qb = q_s + w * DH * NPB;
    const float* krow = kp_s + l * KP_PAD;
    for (int d4 = 0; d4 < DH / 4; d4++) {
        const float4 q0 = *(const float4*)(qb + (d4 * 4 + 0) * NPB);
        const float4 q1 = *(const float4*)(qb + (d4 * 4 + 1) * NPB);
        const float4 q2 = *(const float4*)(qb + (d4 * 4 + 2) * NPB);
        const float4 q3 = *(const float4*)(qb + (d4 * 4 + 3) * NPB);
#pragma unroll
        for (int j = 0; j < 8; j++) {
            const float4 kk = *(const float4*)(krow + j * 32 * KP_PAD + d4 * 4);
            d8[0][j] += kk.x * q0.x + kk.y * q1.x + kk.z * q2.x + kk.w * q3.x;
            d8[1][j] += kk.x * q0.y + kk.y * q1.y + kk.z * q2.y + kk.w * q3.y;
            d8[2][j] += kk.x * q0.z + kk.y * q1.z + kk.z * q2.z + kk.w * q3.z;
            d8[3][j] += kk.x * q0.w + kk.y * q1.w + kk.z * q2.w + kk.w * q3.w;
        }
    }

    // ---- softmax per node
#pragma unroll
    for (int n = 0; n < NPB; n++) {
        float mx = d8[n][0] * scale;
#pragma unroll
        for (int j = 0; j < 8; j++) { d8[n][j] *= scale; mx = fmaxf(mx, d8[n][j]); }
#pragma unroll
        for (int o = 16; o; o >>= 1) mx = fmaxf(mx, __shfl_xor_sync(0xFFFFFFFFu, mx, o));
        float sum = 0.f;
#pragma unroll
        for (int j = 0; j < 8; j++) { d8[n][j] = expf(d8[n][j] - mx); sum += d8[n][j]; }
#pragma unroll
        for (int o = 16; o; o >>= 1) sum += __shfl_xor_sync(0xFFFFFFFFu, sum, o);
        const float inv = 1.f / sum;
#pragma unroll
        for (int j = 0; j < 8; j++)
            pr_s[(w * KPROJ + j * 32 + l) * NPB + n] = d8[n][j] * inv;
    }
    __syncwarp();

    // ---- out: lane handles d = 4l..4l+3, 4 nodes
    float4 o4[NPB];
#pragma unroll
    for (int n = 0; n < NPB; n++) o4[n] = make_float4(0.f, 0.f, 0.f, 0.f);
    const float* prb = pr_s + w * KPROJ * NPB;
#pragma unroll 4
    for (int k = 0; k < KPROJ; k++) {
        const float4 kk = *(const float4*)(kp_s + k * KP_PAD + l * 4);
        const float4 pp = *(const float4*)(prb + k * NPB);
        o4[0].x += pp.x * kk.x; o4[0].y += pp.x * kk.y;
        o4[0].z += pp.x * kk.z; o4[0].w += pp.x * kk.w;
        o4[1].x += pp.y * kk.x; o4[1].y += pp.y * kk.y;
        o4[1].z += pp.y * kk.z; o4[1].w += pp.y * kk.w;
        o4[2].x += pp.z * kk.x; o4[2].y += pp.z * kk.y;
        o4[2].z += pp.z * kk.z; o4[2].w += pp.z * kk.w;
        o4[3].x += pp.w * kk.x; o4[3].y += pp.w * kk.y;
        o4[3].z += pp.w * kk.z; o4[3].w += pp.w * kk.w;
    }

#pragma unroll
    for (int n = 0; n < NPB; n++) {
        const size_t ob = (size_t)(n0 + n) * DIM + w * DH + l * 4;
        const float v[4] = {o4[n].x, o4[n].y, o4[n].z, o4[n].w};
        __nv_bfloat16 h0 = __float2bfloat16(v[0]), h1 = __float2bfloat16(v[1]);
        __nv_bfloat16 h2 = __float2bfloat16(v[2]), h3 = __float2bfloat16(v[3]);
        *(__nv_bfloat162*)&oh[ob]     = __halves2bfloat162(h0, h1);
        *(__nv_bfloat162*)&oh[ob + 2] = __halves2bfloat162(h2, h3);
        *(__nv_bfloat162*)&ol[ob] = __halves2bfloat162(
            __float2bfloat16(v[0] - __bfloat162float(h0)),
            __float2bfloat16(v[1] - __bfloat162float(h1)));
        *(__nv_bfloat162*)&ol[ob + 2] = __halves2bfloat162(
            __float2bfloat16(v[2] - __bfloat162float(h2)),
            __float2bfloat16(v[3] - __bfloat162float(h3)));
    }
}

// ---------------------------------------------------------------------------
// LayerNorm + residual (in-place safe)
// ---------------------------------------------------------------------------
__global__ void __launch_bounds__(256) ln_res_kernel(
    const float* __restrict__ src, const float* __restrict__ resid,
    const float* __restrict__ gamma, const float* __restrict__ beta,
    float* __restrict__ dst)
{
    const int row = blockIdx.x;
    const int t = threadIdx.x;
    const float4 v = *(const float4*)&src[(size_t)row * DIM + t * 4];

    float sum = v.x + v.y + v.z + v.w;
    float sq = v.x * v.x + v.y * v.y + v.z * v.z + v.w * v.w;
#pragma unroll
    for (int o = 16; o; o >>= 1) {
        sum += __shfl_xor_sync(0xFFFFFFFFu, sum, o);
        sq  += __shfl_xor_sync(0xFFFFFFFFu, sq, o);
    }
    __shared__ float ssum[8], ssq[8];
    const int w = t >> 5, l = t & 31;
    if (l == 0) { ssum[w] = sum; ssq[w] = sq; }
    __syncthreads();
    sum = 0.f; sq = 0.f;
#pragma unroll
    for (int i = 0; i < 8; i++) { sum += ssum[i]; sq += ssq[i]; }

    const float mu = sum * (1.f / DIM);
    const float var = sq * (1.f / DIM) - mu * mu;
    const float rstd = rsqrtf(var + 1e-5f);

    const float4 g = *(const float4*)&gamma[t * 4];
    const float4 b = *(const float4*)&beta[t * 4];
    const float4 rr = *(const float4*)&resid[(size_t)row * DIM + t * 4];
    float4 o;
    o.x = (v.x - mu) * rstd * g.x + b.x + rr.x;
    o.y = (v.y - mu) * rstd * g.y + b.y + rr.y;
    o.z = (v.z - mu) * rstd * g.z + b.z + rr.z;
    o.w = (v.w - mu) * rstd * g.w + b.w + rr.w;
    *(float4*)&dst[(size_t)row * DIM + t * 4] = o;
}

// ---------------------------------------------------------------------------
// kernel_launch
// ---------------------------------------------------------------------------
extern "C" void kernel_launch(void* const* d_in, const int* in_sizes, int n_in,
                              void* d_out, int out_size)
{
    const float* node       = (const float*)d_in[0];
    const float* edge       = (const float*)d_in[1];
    const float* w_query    = (const float*)d_in[2];
    const float* b_query    = (const float*)d_in[3];
    const float* w_edge     = (const float*)d_in[4];
    const float* b_edge     = (const float*)d_in[5];
    const float* w_to_q     = (const float*)d_in[6];
    const float* w_to_k     = (const float*)d_in[7];
    const float* proj_k     = (const float*)d_in[8];
    const float* w_out      = (const float*)d_in[9];
    const float* b_out      = (const float*)d_in[10];
    const float* gamma_node = (const float*)d_in[11];
    const float* beta_node  = (const float*)d_in[12];
    const float* gamma_edge = (const float*)d_in[13];
    const float* beta_edge  = (const float*)d_in[14];

    float* x_out = (float*)d_out;
    float* y_out = (float*)d_out + (size_t)N_NODES * DIM;

    __half *e16, *weT16;
    __nv_bfloat16 *nh, *nl, *wqTh, *wqTl;
    __nv_bfloat16 *wqkTh, *wqkTl, *woTh, *woTl, *xqh, *xql, *ah, *al;
    float *qkv, *kp, *xattn;
    cudaGetSymbolAddress((void**)&e16, g_e16);
    cudaGetSymbolAddress((void**)&weT16, g_weT16);
    cudaGetSymbolAddress((void**)&nh, g_nh);
    cudaGetSymbolAddress((void**)&nl, g_nl);
    cudaGetSymbolAddress((void**)&wqTh, g_wqT_h);
    cudaGetSymbolAddress((void**)&wqTl, g_wqT_l);
    cudaGetSymbolAddress((void**)&wqkTh, g_wqkT_h);
    cudaGetSymbolAddress((void**)&wqkTl, g_wqkT_l);
    cudaGetSymbolAddress((void**)&woTh, g_woT_h);
    cudaGetSymbolAddress((void**)&woTl, g_woT_l);
    cudaGetSymbolAddress((void**)&xqh, g_xqh);
    cudaGetSymbolAddress((void**)&xql, g_xql);
    cudaGetSymbolAddress((void**)&ah, g_ah);
    cudaGetSymbolAddress((void**)&al, g_al);
    cudaGetSymbolAddress((void**)&qkv, g_qkv);
    cudaGetSymbolAddress((void**)&kp, g_kproj);
    cudaGetSymbolAddress((void**)&xattn, g_xattn);

    static bool attr_set = false;
    if (!attr_set) {
        cudaFuncSetAttribute(gemm_bf16_sw,
                             cudaFuncAttributeMaxDynamicSharedMemorySize, N_SM);
        cudaFuncSetAttribute(gemm_f16_sw,
                             cudaFuncAttributeMaxDynamicSharedMemorySize, E_SM);
        cudaFuncSetAttribute(attn_v3,
                             cudaFuncAttributeMaxDynamicSharedMemorySize, ATTN_SMEM);
        attr_set = true;
    }

    // 1. fused elementwise converts (edge fp16, node bf16 split)
    fused_conv_kernel<<<CONV_BLOCKS, 256>>>(
        (const float4*)edge, (__half2*)e16,
        (const float4*)node, (__nv_bfloat162*)nh, (__nv_bfloat162*)nl);
    // 2. fused weight prep (all 5 transposes)
    fused_wprep_kernel<<<WPREP_BLOCKS, dim3(32, 8)>>>(
        w_query, w_to_q, w_to_k, w_out, w_edge,
        wqTh, wqTl, wqkTh, wqkTl, woTh, woTl, weT16);
    // 3. node GEMM #1 (xq)
    gemm_bf16_sw<<<dim3(8, 16), 256, N_SM>>>(
        nh, nl, wqTh, wqTl, b_query, nullptr, xqh, xql, DIM);
    // 4. edge GEMM (profiled slot)
    gemm_f16_sw<<<dim3(8, 256), 256, E_SM>>>(e16, weT16, b_edge, y_out, DIM);
    // 5. edge LN (in place)
    ln_res_kernel<<<N_EDGES, 256>>>(y_out, edge, gamma_edge, beta_edge, y_out);
    // 6. node GEMM #2 (qkv)
    gemm_bf16_sw<<<dim3(9, 16), 256, N_SM>>>(
        xqh, xql, wqkTh, wqkTl, nullptr, qkv, nullptr, nullptr, QKV_N);
    // 7-8. kproj + attention
    kproj_kernel<<<KPROJ, 128>>>(qkv + 1024, QKV_N, proj_k, kp);
    attn_v3<<<N_NODES / NPB, 256, ATTN_SMEM>>>(qkv, QKV_N, kp, ah, al);
    // 9. node GEMM #3 (x_attn)
    gemm_bf16_sw<<<dim3(8, 16), 256, N_SM>>>(
        ah, al, woTh, woTl, b_out, xattn, nullptr, nullptr, DIM);
    // 10. node LN
    ln_res_kernel<<<N_NODES, 256>>>(xattn, node, gamma_node, beta_node, x_out);
}